// round 1
// baseline (speedup 1.0000x reference)
#include <cuda_runtime.h>
#include <math.h>

#define BB 8
#define CIN 256
#define CC 128
#define HW 16384
#define NSPLIT 32
#define CHUNK (HW / NSPLIT)

// ---------------- scratch (no cudaMalloc allowed) ----------------
__device__ float g_wq1f[CC * CIN];
__device__ float g_wk1f[CC * CIN];
__device__ float g_wvf [CC * CIN];
__device__ float g_wq2f[CC * CC];
__device__ float g_wk2f[CC * CC];
__device__ float g_bq1[CC], g_bq2[CC], g_bk1[CC], g_bk2[CC], g_bv[CC];
__device__ float g_kh [(size_t)BB * CC * HW];
__device__ float g_key[(size_t)BB * CC * HW];
__device__ float g_val[(size_t)BB * CC * HW];
__device__ float g_qh [(size_t)BB * CC * HW];
__device__ float g_qr [(size_t)BB * CC * HW];
__device__ float g_S[BB * CC * CC];
__device__ float g_Z[BB * CC];

// ---------------- BN folding: wf[o][c] = w[o][c]*scale[o]; bf[o] = b - m*scale ----------------
__global__ void fold_k(const float* __restrict__ w, const float* __restrict__ g,
                       const float* __restrict__ be, const float* __restrict__ m,
                       const float* __restrict__ v, float* __restrict__ wf,
                       float* __restrict__ bf, int K) {
    int o = blockIdx.x;
    float s = g[o] * rsqrtf(v[o] + 1e-5f);
    if (threadIdx.x == 0) bf[o] = be[o] - m[o] * s;
    for (int c = threadIdx.x; c < K; c += blockDim.x)
        wf[o * K + c] = w[o * K + c] * s;
}

__device__ __forceinline__ float softplus_f(float x) {
    return fmaxf(x, 0.f) + log1pf(expf(-fabsf(x)));
}

// ---------------- fused 1x1-conv GEMM: Y[b,o,n] = act(sum_c W[o,c] X[b,c,n] + bias[o]) ----------------
// ACT: 0 = relu, 1 = softplus
template <int KTOT, int ACT>
__global__ void __launch_bounds__(256, 2)
conv_gemm(const float* __restrict__ W, const float* __restrict__ bias,
          const float* __restrict__ X, float* __restrict__ Y) {
    __shared__ float As[16][132];   // [k][m], padded
    __shared__ float Bs[16][128];   // [k][n]
    const int tid = threadIdx.x;
    const int b = blockIdx.y;
    const int n0 = blockIdx.x * 128;
    const float* Xb = X + (size_t)b * KTOT * HW + n0;
    const int tm = tid >> 4, tn = tid & 15;
    const int ar = tid >> 2, ac = (tid & 3) * 4;     // weight tile: 128 rows x 16 k
    const int br = tid >> 5, bc = (tid & 31) * 4;    // x tile: 16 k x 128 n

    float acc[8][8] = {};

    for (int k0 = 0; k0 < KTOT; k0 += 16) {
        float4 a0 = *(const float4*)(W + (size_t)ar * KTOT + k0 + ac);
        float4 a1 = *(const float4*)(W + (size_t)(ar + 64) * KTOT + k0 + ac);
        float4 b0 = *(const float4*)(Xb + (size_t)(k0 + br) * HW + bc);
        float4 b1 = *(const float4*)(Xb + (size_t)(k0 + br + 8) * HW + bc);
        __syncthreads();
        As[ac + 0][ar] = a0.x; As[ac + 1][ar] = a0.y;
        As[ac + 2][ar] = a0.z; As[ac + 3][ar] = a0.w;
        As[ac + 0][ar + 64] = a1.x; As[ac + 1][ar + 64] = a1.y;
        As[ac + 2][ar + 64] = a1.z; As[ac + 3][ar + 64] = a1.w;
        *(float4*)&Bs[br][bc] = b0;
        *(float4*)&Bs[br + 8][bc] = b1;
        __syncthreads();
#pragma unroll
        for (int kk = 0; kk < 16; kk++) {
            float a[8], bv[8];
            *(float4*)(a)     = *(const float4*)&As[kk][tm * 8];
            *(float4*)(a + 4) = *(const float4*)&As[kk][tm * 8 + 4];
            *(float4*)(bv)     = *(const float4*)&Bs[kk][tn * 8];
            *(float4*)(bv + 4) = *(const float4*)&Bs[kk][tn * 8 + 4];
#pragma unroll
            for (int i = 0; i < 8; i++)
#pragma unroll
                for (int j = 0; j < 8; j++)
                    acc[i][j] = fmaf(a[i], bv[j], acc[i][j]);
        }
    }

    float* Yb = Y + (size_t)b * CC * HW + n0 + tn * 8;
#pragma unroll
    for (int i = 0; i < 8; i++) {
        int o = tm * 8 + i;
        float bi = bias[o];
        float r[8];
#pragma unroll
        for (int j = 0; j < 8; j++) {
            float x = acc[i][j] + bi;
            r[j] = (ACT == 0) ? fmaxf(x, 0.f) : softplus_f(x);
        }
        *(float4*)(Yb + (size_t)o * HW)     = *(float4*)(r);
        *(float4*)(Yb + (size_t)o * HW + 4) = *(float4*)(r + 4);
    }
}

// ---------------- S[b,c,d] += sum_{n in chunk} V[b,c,n] * K[b,d,n]  (atomics over splits) ----------------
__global__ void __launch_bounds__(256, 2)
s_gemm(const float* __restrict__ V, const float* __restrict__ Kt, float* __restrict__ S) {
    __shared__ float As[16][132];
    __shared__ float Bs[16][132];
    const int tid = threadIdx.x;
    const int b = blockIdx.y;
    const int p0 = blockIdx.x * CHUNK;
    const float* Vb = V + (size_t)b * CC * HW + p0;
    const float* Kb = Kt + (size_t)b * CC * HW + p0;
    const int tm = tid >> 4, tn = tid & 15;
    const int ar = tid >> 2, ac = (tid & 3) * 4;

    float acc[8][8] = {};

    for (int k0 = 0; k0 < CHUNK; k0 += 16) {
        float4 a0 = *(const float4*)(Vb + (size_t)ar * HW + k0 + ac);
        float4 a1 = *(const float4*)(Vb + (size_t)(ar + 64) * HW + k0 + ac);
        float4 b0 = *(const float4*)(Kb + (size_t)ar * HW + k0 + ac);
        float4 b1 = *(const float4*)(Kb + (size_t)(ar + 64) * HW + k0 + ac);
        __syncthreads();
        As[ac + 0][ar] = a0.x; As[ac + 1][ar] = a0.y;
        As[ac + 2][ar] = a0.z; As[ac + 3][ar] = a0.w;
        As[ac + 0][ar + 64] = a1.x; As[ac + 1][ar + 64] = a1.y;
        As[ac + 2][ar + 64] = a1.z; As[ac + 3][ar + 64] = a1.w;
        Bs[ac + 0][ar] = b0.x; Bs[ac + 1][ar] = b0.y;
        Bs[ac + 2][ar] = b0.z; Bs[ac + 3][ar] = b0.w;
        Bs[ac + 0][ar + 64] = b1.x; Bs[ac + 1][ar + 64] = b1.y;
        Bs[ac + 2][ar + 64] = b1.z; Bs[ac + 3][ar + 64] = b1.w;
        __syncthreads();
#pragma unroll
        for (int kk = 0; kk < 16; kk++) {
            float a[8], bv[8];
            *(float4*)(a)     = *(const float4*)&As[kk][tm * 8];
            *(float4*)(a + 4) = *(const float4*)&As[kk][tm * 8 + 4];
            *(float4*)(bv)     = *(const float4*)&Bs[kk][tn * 8];
            *(float4*)(bv + 4) = *(const float4*)&Bs[kk][tn * 8 + 4];
#pragma unroll
            for (int i = 0; i < 8; i++)
#pragma unroll
                for (int j = 0; j < 8; j++)
                    acc[i][j] = fmaf(a[i], bv[j], acc[i][j]);
        }
    }

    float* Sb = S + (size_t)b * CC * CC;
#pragma unroll
    for (int i = 0; i < 8; i++)
#pragma unroll
        for (int j = 0; j < 8; j++)
            atomicAdd(&Sb[(size_t)(tm * 8 + i) * CC + tn * 8 + j], acc[i][j]);
}

// ---------------- Z[b,d] = sum_n key[b,d,n] ----------------
__global__ void z_kernel(const float* __restrict__ Kt, float* __restrict__ Z) {
    int d = blockIdx.x, b = blockIdx.y;
    const float* p = Kt + (size_t)b * CC * HW + (size_t)d * HW;
    float s = 0.f;
    for (int n = threadIdx.x; n < HW; n += 256) s += p[n];
    __shared__ float red[256];
    red[threadIdx.x] = s;
    __syncthreads();
    for (int st = 128; st > 0; st >>= 1) {
        if (threadIdx.x < st) red[threadIdx.x] += red[threadIdx.x + st];
        __syncthreads();
    }
    if (threadIdx.x == 0) Z[b * CC + d] = red[0];
}

__global__ void zero_s(float* __restrict__ S) {
    S[blockIdx.x * 256 + threadIdx.x] = 0.f;
}

// ---------------- out[b,c,n] = sum_d S[b,c,d] q[b,d,n] / max(sum_d Z[b,d] q[b,d,n], eps) ----------------
__global__ void __launch_bounds__(256, 2)
out_gemm(const float* __restrict__ S, const float* __restrict__ Z,
         const float* __restrict__ Q, float* __restrict__ O) {
    __shared__ float As[16][132];
    __shared__ float Bs[16][128];
    __shared__ float Zs[CC];
    const int tid = threadIdx.x;
    const int b = blockIdx.y;
    const int n0 = blockIdx.x * 128;
    const float* Sb = S + (size_t)b * CC * CC;
    const float* Qb = Q + (size_t)b * CC * HW + n0;
    if (tid < CC) Zs[tid] = Z[b * CC + tid];
    const int tm = tid >> 4, tn = tid & 15;
    const int ar = tid >> 2, ac = (tid & 3) * 4;
    const int br = tid >> 5, bc = (tid & 31) * 4;

    float acc[8][8] = {};
    float den[8] = {};

    for (int k0 = 0; k0 < CC; k0 += 16) {
        float4 a0 = *(const float4*)(Sb + (size_t)ar * CC + k0 + ac);
        float4 a1 = *(const float4*)(Sb + (size_t)(ar + 64) * CC + k0 + ac);
        float4 b0 = *(const float4*)(Qb + (size_t)(k0 + br) * HW + bc);
        float4 b1 = *(const float4*)(Qb + (size_t)(k0 + br + 8) * HW + bc);
        __syncthreads();
        As[ac + 0][ar] = a0.x; As[ac + 1][ar] = a0.y;
        As[ac + 2][ar] = a0.z; As[ac + 3][ar] = a0.w;
        As[ac + 0][ar + 64] = a1.x; As[ac + 1][ar + 64] = a1.y;
        As[ac + 2][ar + 64] = a1.z; As[ac + 3][ar + 64] = a1.w;
        *(float4*)&Bs[br][bc] = b0;
        *(float4*)&Bs[br + 8][bc] = b1;
        __syncthreads();
#pragma unroll
        for (int kk = 0; kk < 16; kk++) {
            float a[8], bv[8];
            *(float4*)(a)     = *(const float4*)&As[kk][tm * 8];
            *(float4*)(a + 4) = *(const float4*)&As[kk][tm * 8 + 4];
            *(float4*)(bv)     = *(const float4*)&Bs[kk][tn * 8];
            *(float4*)(bv + 4) = *(const float4*)&Bs[kk][tn * 8 + 4];
            float z = Zs[k0 + kk];
#pragma unroll
            for (int j = 0; j < 8; j++) den[j] = fmaf(z, bv[j], den[j]);
#pragma unroll
            for (int i = 0; i < 8; i++)
#pragma unroll
                for (int j = 0; j < 8; j++)
                    acc[i][j] = fmaf(a[i], bv[j], acc[i][j]);
        }
    }

    float* Ob = O + (size_t)b * CC * HW + n0 + tn * 8;
    float inv[8];
#pragma unroll
    for (int j = 0; j < 8; j++) inv[j] = 1.f / fmaxf(den[j], 1e-12f);
#pragma unroll
    for (int i = 0; i < 8; i++) {
        int o = tm * 8 + i;
        float r[8];
#pragma unroll
        for (int j = 0; j < 8; j++) r[j] = acc[i][j] * inv[j];
        *(float4*)(Ob + (size_t)o * HW)     = *(float4*)(r);
        *(float4*)(Ob + (size_t)o * HW + 4) = *(float4*)(r + 4);
    }
}

// ---------------- launch ----------------
extern "C" void kernel_launch(void* const* d_in, const int* in_sizes, int n_in,
                              void* d_out, int out_size) {
    const float* target = (const float*)d_in[0];
    const float* source = (const float*)d_in[1];
    const float* q_w1 = (const float*)d_in[2];
    const float* q_w2 = (const float*)d_in[3];
    const float* k_w1 = (const float*)d_in[4];
    const float* k_w2 = (const float*)d_in[5];
    const float* v_w  = (const float*)d_in[6];

    float *wq1f, *wk1f, *wvf, *wq2f, *wk2f;
    float *bq1, *bq2, *bk1, *bk2, *bv;
    float *kh, *key, *val, *qh, *qr, *S, *Z;
    cudaGetSymbolAddress((void**)&wq1f, g_wq1f);
    cudaGetSymbolAddress((void**)&wk1f, g_wk1f);
    cudaGetSymbolAddress((void**)&wvf,  g_wvf);
    cudaGetSymbolAddress((void**)&wq2f, g_wq2f);
    cudaGetSymbolAddress((void**)&wk2f, g_wk2f);
    cudaGetSymbolAddress((void**)&bq1, g_bq1);
    cudaGetSymbolAddress((void**)&bq2, g_bq2);
    cudaGetSymbolAddress((void**)&bk1, g_bk1);
    cudaGetSymbolAddress((void**)&bk2, g_bk2);
    cudaGetSymbolAddress((void**)&bv,  g_bv);
    cudaGetSymbolAddress((void**)&kh,  g_kh);
    cudaGetSymbolAddress((void**)&key, g_key);
    cudaGetSymbolAddress((void**)&val, g_val);
    cudaGetSymbolAddress((void**)&qh,  g_qh);
    cudaGetSymbolAddress((void**)&qr,  g_qr);
    cudaGetSymbolAddress((void**)&S,   g_S);
    cudaGetSymbolAddress((void**)&Z,   g_Z);

    // BN fold (input order: q1 @7, q2 @11, k1 @15, k2 @19, v @23)
    fold_k<<<CC, 256>>>(q_w1, (const float*)d_in[7],  (const float*)d_in[8],
                        (const float*)d_in[9],  (const float*)d_in[10], wq1f, bq1, CIN);
    fold_k<<<CC, 256>>>(q_w2, (const float*)d_in[11], (const float*)d_in[12],
                        (const float*)d_in[13], (const float*)d_in[14], wq2f, bq2, CC);
    fold_k<<<CC, 256>>>(k_w1, (const float*)d_in[15], (const float*)d_in[16],
                        (const float*)d_in[17], (const float*)d_in[18], wk1f, bk1, CIN);
    fold_k<<<CC, 256>>>(k_w2, (const float*)d_in[19], (const float*)d_in[20],
                        (const float*)d_in[21], (const float*)d_in[22], wk2f, bk2, CC);
    fold_k<<<CC, 256>>>(v_w,  (const float*)d_in[23], (const float*)d_in[24],
                        (const float*)d_in[25], (const float*)d_in[26], wvf, bv, CIN);

    dim3 gconv(HW / 128, BB);
    conv_gemm<CIN, 0><<<gconv, 256>>>(wk1f, bk1, source, kh);   // k hidden
    conv_gemm<CIN, 0><<<gconv, 256>>>(wvf,  bv,  source, val);  // value
    conv_gemm<CIN, 0><<<gconv, 256>>>(wq1f, bq1, target, qh);   // q hidden
    conv_gemm<CC, 1><<<gconv, 256>>>(wk2f, bk2, kh, key);       // key (softplus)
    conv_gemm<CC, 1><<<gconv, 256>>>(wq2f, bq2, qh, qr);        // query (softplus)

    zero_s<<<BB * CC * CC / 256, 256>>>(S);
    s_gemm<<<dim3(NSPLIT, BB), 256>>>(val, key, S);
    z_kernel<<<dim3(CC, BB), 256>>>(key, Z);
    out_gemm<<<gconv, 256>>>(S, Z, qr, (float*)d_out);
}

// round 4
// speedup vs baseline: 2.3722x; 2.3722x over previous
#include <cuda_runtime.h>
#include <math.h>
#include <stdint.h>

#define BB 8
#define CIN 256
#define CC 128
#define HW 16384
#define KB 32
#define NSPLIT 32
#define SCHUNK 512

#define APAD 36
#define BPAD 136
#define ASZ (128 * APAD)
#define BSZ (KB * BPAD)
#define SMEM_BYTES (2 * (ASZ + BSZ) * 4)

// ---------------- scratch ----------------
__device__ float g_wq1f[CC * CIN];
__device__ float g_wk1f[CC * CIN];
__device__ float g_wvf [CC * CIN];
__device__ float g_wq2f[CC * CC];
__device__ float g_wk2f[CC * CC];
__device__ float g_bq1[CC], g_bq2[CC], g_bk1[CC], g_bk2[CC], g_bv[CC];
__device__ float g_kh [(size_t)BB * CC * HW];
__device__ float g_key[(size_t)BB * CC * HW];
__device__ float g_val[(size_t)BB * CC * HW];
__device__ float g_qh [(size_t)BB * CC * HW];
__device__ float g_qr [(size_t)BB * CC * HW];
__device__ float g_S[BB * CC * CC];
__device__ float g_Z[BB * CC];
__device__ float g_den[(size_t)BB * HW];

// ---------------- helpers ----------------
__device__ __forceinline__ float to_tf32(float x) {
    uint32_t u;
    asm("cvt.rna.tf32.f32 %0, %1;" : "=r"(u) : "f"(x));
    return __uint_as_float(u);
}

__device__ __forceinline__ void mma8(float* c, uint32_t a0, uint32_t a1,
                                     uint32_t a2, uint32_t a3,
                                     uint32_t b0, uint32_t b1) {
    asm volatile(
        "mma.sync.aligned.m16n8k8.row.col.f32.tf32.tf32.f32 "
        "{%0,%1,%2,%3}, {%4,%5,%6,%7}, {%8,%9}, {%0,%1,%2,%3};"
        : "+f"(c[0]), "+f"(c[1]), "+f"(c[2]), "+f"(c[3])
        : "r"(a0), "r"(a1), "r"(a2), "r"(a3), "r"(b0), "r"(b1));
}

__device__ __forceinline__ float softplus_f(float x) {
    return fmaxf(x, 0.f) + log1pf(expf(-fabsf(x)));
}

// ---------------- BN fold (weights rounded to tf32) ----------------
__global__ void fold_k(const float* __restrict__ w, const float* __restrict__ g,
                       const float* __restrict__ be, const float* __restrict__ m,
                       const float* __restrict__ v, float* __restrict__ wf,
                       float* __restrict__ bf, int K) {
    int o = blockIdx.x;
    float s = g[o] * rsqrtf(v[o] + 1e-5f);
    if (threadIdx.x == 0) bf[o] = be[o] - m[o] * s;
    for (int c = threadIdx.x; c < K; c += blockDim.x)
        wf[o * K + c] = to_tf32(w[o * K + c] * s);
}

// ============================================================================
// Y[b,m,n] = act( sum_k A[m,k] X[b,k,n] + bias[m] )    (tile 128x128, tf32 mma)
// ACT: 0 relu (+tf32 round), 1 softplus (+tf32 round), 2 divide-by-den (raw)
// ============================================================================
template <int KTOT, int ACT>
__global__ void __launch_bounds__(256)
gemm_tc(const float* __restrict__ W, const float* __restrict__ bias,
        const float* __restrict__ X, long a_bstride,
        const float* __restrict__ den, float* __restrict__ Y) {
    extern __shared__ float smd[];
    float* As = smd;
    float* Bs = smd + 2 * ASZ;
    const int tid = threadIdx.x;
    const int b = blockIdx.y;
    const int n0 = blockIdx.x * 128;
    const int warp = tid >> 5, lane = tid & 31;
    const int wm = warp >> 1, wn = warp & 1;
    const int qid = lane >> 2, tq = lane & 3;
    const float* Ab = W + (size_t)b * a_bstride;
    const float* Xb = X + (size_t)b * KTOT * HW + n0;
    constexpr int NKB = KTOT / KB;

    float acc[2][8][4];
#pragma unroll
    for (int i = 0; i < 2; i++)
#pragma unroll
        for (int j = 0; j < 8; j++)
#pragma unroll
            for (int l = 0; l < 4; l++) acc[i][j][l] = 0.f;

    const int am = tid >> 3, ak = (tid & 7) * 4;   // A: 4 rows apart per iter
    const int bk = tid >> 5, bn = (tid & 31) * 4;  // B: 8 rows per iter

    // preload tile 0
    {
        float* Ad = As; float* Bd = Bs;
#pragma unroll
        for (int i = 0; i < 4; i++) {
            int m = am + i * 32;
            float4 v = *(const float4*)(Ab + (size_t)m * KTOT + ak);
            float4 w4 = { to_tf32(v.x), to_tf32(v.y), to_tf32(v.z), to_tf32(v.w) };
            *(float4*)(Ad + m * APAD + ak) = w4;
        }
#pragma unroll
        for (int i = 0; i < 4; i++) {
            int k = bk + i * 8;
            float4 v = *(const float4*)(Xb + (size_t)k * HW + bn);
            float4 w4 = { to_tf32(v.x), to_tf32(v.y), to_tf32(v.z), to_tf32(v.w) };
            *(float4*)(Bd + k * BPAD + bn) = w4;
        }
    }
    __syncthreads();

    for (int kb = 0; kb < NKB; kb++) {
        float4 ra[4], rb[4];
        if (kb + 1 < NKB) {
            const int k0 = (kb + 1) * KB;
#pragma unroll
            for (int i = 0; i < 4; i++)
                ra[i] = *(const float4*)(Ab + (size_t)(am + i * 32) * KTOT + k0 + ak);
#pragma unroll
            for (int i = 0; i < 4; i++)
                rb[i] = *(const float4*)(Xb + (size_t)(k0 + bk + i * 8) * HW + bn);
        }

        // compute current buffer
        {
            float* Ad = As + (kb & 1) * ASZ;
            float* Bd = Bs + (kb & 1) * BSZ;
#pragma unroll
            for (int kk = 0; kk < 4; kk++) {
                uint32_t a[2][4], bf[8][2];
#pragma unroll
                for (int mw = 0; mw < 2; mw++) {
                    const float* ap = Ad + (wm * 32 + mw * 16 + qid) * APAD + kk * 8 + tq;
                    a[mw][0] = __float_as_uint(ap[0]);
                    a[mw][1] = __float_as_uint(ap[8 * APAD]);
                    a[mw][2] = __float_as_uint(ap[4]);
                    a[mw][3] = __float_as_uint(ap[8 * APAD + 4]);
                }
#pragma unroll
                for (int nw = 0; nw < 8; nw++) {
                    const float* bp = Bd + (kk * 8 + tq) * BPAD + wn * 64 + nw * 8 + qid;
                    bf[nw][0] = __float_as_uint(bp[0]);
                    bf[nw][1] = __float_as_uint(bp[4 * BPAD]);
                }
#pragma unroll
                for (int mw = 0; mw < 2; mw++)
#pragma unroll
                    for (int nw = 0; nw < 8; nw++)
                        mma8(acc[mw][nw], a[mw][0], a[mw][1], a[mw][2], a[mw][3],
                             bf[nw][0], bf[nw][1]);
            }
        }

        if (kb + 1 < NKB) {
            float* Ad = As + ((kb + 1) & 1) * ASZ;
            float* Bd = Bs + ((kb + 1) & 1) * BSZ;
#pragma unroll
            for (int i = 0; i < 4; i++) {
                float4 w4 = { to_tf32(ra[i].x), to_tf32(ra[i].y), to_tf32(ra[i].z), to_tf32(ra[i].w) };
                *(float4*)(Ad + (am + i * 32) * APAD + ak) = w4;
            }
#pragma unroll
            for (int i = 0; i < 4; i++) {
                float4 w4 = { to_tf32(rb[i].x), to_tf32(rb[i].y), to_tf32(rb[i].z), to_tf32(rb[i].w) };
                *(float4*)(Bd + (bk + i * 8) * BPAD + bn) = w4;
            }
        }
        __syncthreads();
    }

    // epilogue
    float inv[8][2];
    if (ACT == 2) {
#pragma unroll
        for (int nw = 0; nw < 8; nw++) {
            const float* dp = den + (size_t)b * HW + n0 + wn * 64 + nw * 8 + tq * 2;
            float2 d2 = *(const float2*)dp;
            inv[nw][0] = 1.f / fmaxf(d2.x, 1e-12f);
            inv[nw][1] = 1.f / fmaxf(d2.y, 1e-12f);
        }
    }
    float* Yb = Y + (size_t)b * CC * HW + n0;
#pragma unroll
    for (int mw = 0; mw < 2; mw++) {
        const int r0 = wm * 32 + mw * 16 + qid;
        float bv0 = 0.f, bv1 = 0.f;
        if (ACT != 2) { bv0 = bias[r0]; bv1 = bias[r0 + 8]; }
#pragma unroll
        for (int nw = 0; nw < 8; nw++) {
            const int col = wn * 64 + nw * 8 + tq * 2;
            float o00 = acc[mw][nw][0] + bv0, o01 = acc[mw][nw][1] + bv0;
            float o10 = acc[mw][nw][2] + bv1, o11 = acc[mw][nw][3] + bv1;
            if (ACT == 0) {
                o00 = to_tf32(fmaxf(o00, 0.f)); o01 = to_tf32(fmaxf(o01, 0.f));
                o10 = to_tf32(fmaxf(o10, 0.f)); o11 = to_tf32(fmaxf(o11, 0.f));
            } else if (ACT == 1) {
                o00 = to_tf32(softplus_f(o00)); o01 = to_tf32(softplus_f(o01));
                o10 = to_tf32(softplus_f(o10)); o11 = to_tf32(softplus_f(o11));
            } else {
                o00 *= inv[nw][0]; o01 *= inv[nw][1];
                o10 *= inv[nw][0]; o11 *= inv[nw][1];
            }
            float2 p0 = { o00, o01 }, p1 = { o10, o11 };
            *(float2*)(Yb + (size_t)r0 * HW + col) = p0;
            *(float2*)(Yb + (size_t)(r0 + 8) * HW + col) = p1;
        }
    }
}

// ============================================================================
// S[b,c,d] += sum_{n in chunk} V[b,c,n] K[b,d,n]   (+ fused Z[b,d] = sum_n K)
// ============================================================================
__global__ void __launch_bounds__(256)
s_mma(const float* __restrict__ V, const float* __restrict__ Kt,
      float* __restrict__ S, float* __restrict__ Z) {
    extern __shared__ float smd[];
    float* As = smd;
    float* Bs = smd + 2 * ASZ;
    const int tid = threadIdx.x;
    const int b = blockIdx.y;
    const int n0 = blockIdx.x * SCHUNK;
    const int warp = tid >> 5, lane = tid & 31;
    const int wm = warp >> 1, wn = warp & 1;
    const int qid = lane >> 2, tq = lane & 3;
    const float* Vb = V + (size_t)b * CC * HW + n0;
    const float* Kb = Kt + (size_t)b * CC * HW + n0;
    constexpr int NKB = SCHUNK / KB;

    float acc[2][8][4];
#pragma unroll
    for (int i = 0; i < 2; i++)
#pragma unroll
        for (int j = 0; j < 8; j++)
#pragma unroll
            for (int l = 0; l < 4; l++) acc[i][j][l] = 0.f;

    float zp[4] = {};
    const int am = tid >> 3, ak = (tid & 7) * 4;   // rows am+32i
    // B (Kt): same mapping, transpose-store
    const int bd = tid >> 3, bq = (tid & 7) * 4;

    // preload tile 0
    {
#pragma unroll
        for (int i = 0; i < 4; i++) {
            int m = am + i * 32;
            float4 v = *(const float4*)(Vb + (size_t)m * HW + ak);
            float4 w4 = { to_tf32(v.x), to_tf32(v.y), to_tf32(v.z), to_tf32(v.w) };
            *(float4*)(As + m * APAD + ak) = w4;
        }
#pragma unroll
        for (int i = 0; i < 4; i++) {
            int d = bd + i * 32;
            float4 v = *(const float4*)(Kb + (size_t)d * HW + bq);
            zp[i] += v.x + v.y + v.z + v.w;
            Bs[(bq + 0) * BPAD + d] = to_tf32(v.x);
            Bs[(bq + 1) * BPAD + d] = to_tf32(v.y);
            Bs[(bq + 2) * BPAD + d] = to_tf32(v.z);
            Bs[(bq + 3) * BPAD + d] = to_tf32(v.w);
        }
    }
    __syncthreads();

    for (int kb = 0; kb < NKB; kb++) {
        float4 ra[4], rb[4];
        if (kb + 1 < NKB) {
            const int k0 = (kb + 1) * KB;
#pragma unroll
            for (int i = 0; i < 4; i++)
                ra[i] = *(const float4*)(Vb + (size_t)(am + i * 32) * HW + k0 + ak);
#pragma unroll
            for (int i = 0; i < 4; i++) {
                rb[i] = *(const float4*)(Kb + (size_t)(bd + i * 32) * HW + k0 + bq);
                zp[i] += rb[i].x + rb[i].y + rb[i].z + rb[i].w;
            }
        }

        {
            float* Ad = As + (kb & 1) * ASZ;
            float* Bd = Bs + (kb & 1) * BSZ;
#pragma unroll
            for (int kk = 0; kk < 4; kk++) {
                uint32_t a[2][4], bf[8][2];
#pragma unroll
                for (int mw = 0; mw < 2; mw++) {
                    const float* ap = Ad + (wm * 32 + mw * 16 + qid) * APAD + kk * 8 + tq;
                    a[mw][0] = __float_as_uint(ap[0]);
                    a[mw][1] = __float_as_uint(ap[8 * APAD]);
                    a[mw][2] = __float_as_uint(ap[4]);
                    a[mw][3] = __float_as_uint(ap[8 * APAD + 4]);
                }
#pragma unroll
                for (int nw = 0; nw < 8; nw++) {
                    const float* bp = Bd + (kk * 8 + tq) * BPAD + wn * 64 + nw * 8 + qid;
                    bf[nw][0] = __float_as_uint(bp[0]);
                    bf[nw][1] = __float_as_uint(bp[4 * BPAD]);
                }
#pragma unroll
                for (int mw = 0; mw < 2; mw++)
#pragma unroll
                    for (int nw = 0; nw < 8; nw++)
                        mma8(acc[mw][nw], a[mw][0], a[mw][1], a[mw][2], a[mw][3],
                             bf[nw][0], bf[nw][1]);
            }
        }

        if (kb + 1 < NKB) {
            float* Ad = As + ((kb + 1) & 1) * ASZ;
            float* Bd = Bs + ((kb + 1) & 1) * BSZ;
#pragma unroll
            for (int i = 0; i < 4; i++) {
                float4 w4 = { to_tf32(ra[i].x), to_tf32(ra[i].y), to_tf32(ra[i].z), to_tf32(ra[i].w) };
                *(float4*)(Ad + (am + i * 32) * APAD + ak) = w4;
            }
#pragma unroll
            for (int i = 0; i < 4; i++) {
                int d = bd + i * 32;
                Bd[(bq + 0) * BPAD + d] = to_tf32(rb[i].x);
                Bd[(bq + 1) * BPAD + d] = to_tf32(rb[i].y);
                Bd[(bq + 2) * BPAD + d] = to_tf32(rb[i].z);
                Bd[(bq + 3) * BPAD + d] = to_tf32(rb[i].w);
            }
        }
        __syncthreads();
    }

    // Z reduce: zp[i] is partial for d = (tid>>3) + 32i over nq = tid&7
#pragma unroll
    for (int i = 0; i < 4; i++) {
#pragma unroll
        for (int o = 1; o < 8; o <<= 1)
            zp[i] += __shfl_xor_sync(0xffffffff, zp[i], o);
        if ((lane & 7) == 0)
            atomicAdd(&Z[b * CC + (tid >> 3) + 32 * i], zp[i]);
    }

    // S accumulate via atomics
    float* Sb = S + (size_t)b * CC * CC;
#pragma unroll
    for (int mw = 0; mw < 2; mw++) {
        const int r0 = wm * 32 + mw * 16 + qid;
#pragma unroll
        for (int nw = 0; nw < 8; nw++) {
            const int col = wn * 64 + nw * 8 + tq * 2;
            atomicAdd(&Sb[(size_t)r0 * CC + col],       acc[mw][nw][0]);
            atomicAdd(&Sb[(size_t)r0 * CC + col + 1],   acc[mw][nw][1]);
            atomicAdd(&Sb[(size_t)(r0 + 8) * CC + col],     acc[mw][nw][2]);
            atomicAdd(&Sb[(size_t)(r0 + 8) * CC + col + 1], acc[mw][nw][3]);
        }
    }
}

// ---------------- den[b,n] = sum_d Z[b,d] * Q[b,d,n] ----------------
__global__ void den_k(const float* __restrict__ Z, const float* __restrict__ Q,
                      float* __restrict__ D) {
    __shared__ float Zs[CC];
    const int tid = threadIdx.x;
    const int b = blockIdx.y;
    const int n0 = blockIdx.x * 1024;
    if (tid < CC) Zs[tid] = Z[b * CC + tid];
    __syncthreads();
    const float* Qb = Q + (size_t)b * CC * HW + n0 + tid * 4;
    float4 acc = make_float4(0.f, 0.f, 0.f, 0.f);
#pragma unroll 8
    for (int d = 0; d < CC; d++) {
        float4 q = *(const float4*)(Qb + (size_t)d * HW);
        float z = Zs[d];
        acc.x = fmaf(z, q.x, acc.x); acc.y = fmaf(z, q.y, acc.y);
        acc.z = fmaf(z, q.z, acc.z); acc.w = fmaf(z, q.w, acc.w);
    }
    *(float4*)(D + (size_t)b * HW + n0 + tid * 4) = acc;
}

// ---------------- launch ----------------
extern "C" void kernel_launch(void* const* d_in, const int* in_sizes, int n_in,
                              void* d_out, int out_size) {
    const float* target = (const float*)d_in[0];
    const float* source = (const float*)d_in[1];
    const float* q_w1 = (const float*)d_in[2];
    const float* q_w2 = (const float*)d_in[3];
    const float* k_w1 = (const float*)d_in[4];
    const float* k_w2 = (const float*)d_in[5];
    const float* v_w  = (const float*)d_in[6];

    float *wq1f, *wk1f, *wvf, *wq2f, *wk2f, *bq1, *bq2, *bk1, *bk2, *bv;
    float *kh, *key, *val, *qh, *qr, *S, *Z, *den;
    cudaGetSymbolAddress((void**)&wq1f, g_wq1f);
    cudaGetSymbolAddress((void**)&wk1f, g_wk1f);
    cudaGetSymbolAddress((void**)&wvf,  g_wvf);
    cudaGetSymbolAddress((void**)&wq2f, g_wq2f);
    cudaGetSymbolAddress((void**)&wk2f, g_wk2f);
    cudaGetSymbolAddress((void**)&bq1, g_bq1);
    cudaGetSymbolAddress((void**)&bq2, g_bq2);
    cudaGetSymbolAddress((void**)&bk1, g_bk1);
    cudaGetSymbolAddress((void**)&bk2, g_bk2);
    cudaGetSymbolAddress((void**)&bv,  g_bv);
    cudaGetSymbolAddress((void**)&kh,  g_kh);
    cudaGetSymbolAddress((void**)&key, g_key);
    cudaGetSymbolAddress((void**)&val, g_val);
    cudaGetSymbolAddress((void**)&qh,  g_qh);
    cudaGetSymbolAddress((void**)&qr,  g_qr);
    cudaGetSymbolAddress((void**)&S,   g_S);
    cudaGetSymbolAddress((void**)&Z,   g_Z);
    cudaGetSymbolAddress((void**)&den, g_den);

    cudaFuncSetAttribute(gemm_tc<CIN, 0>, cudaFuncAttributeMaxDynamicSharedMemorySize, SMEM_BYTES);
    cudaFuncSetAttribute(gemm_tc<CC, 1>,  cudaFuncAttributeMaxDynamicSharedMemorySize, SMEM_BYTES);
    cudaFuncSetAttribute(gemm_tc<CC, 2>,  cudaFuncAttributeMaxDynamicSharedMemorySize, SMEM_BYTES);
    cudaFuncSetAttribute(s_mma, cudaFuncAttributeMaxDynamicSharedMemorySize, SMEM_BYTES);

    fold_k<<<CC, 256>>>(q_w1, (const float*)d_in[7],  (const float*)d_in[8],
                        (const float*)d_in[9],  (const float*)d_in[10], wq1f, bq1, CIN);
    fold_k<<<CC, 256>>>(q_w2, (const float*)d_in[11], (const float*)d_in[12],
                        (const float*)d_in[13], (const float*)d_in[14], wq2f, bq2, CC);
    fold_k<<<CC, 256>>>(k_w1, (const float*)d_in[15], (const float*)d_in[16],
                        (const float*)d_in[17], (const float*)d_in[18], wk1f, bk1, CIN);
    fold_k<<<CC, 256>>>(k_w2, (const float*)d_in[19], (const float*)d_in[20],
                        (const float*)d_in[21], (const float*)d_in[22], wk2f, bk2, CC);
    fold_k<<<CC, 256>>>(v_w,  (const float*)d_in[23], (const float*)d_in[24],
                        (const float*)d_in[25], (const float*)d_in[26], wvf, bv, CIN);

    cudaMemsetAsync(S, 0, BB * CC * CC * sizeof(float));
    cudaMemsetAsync(Z, 0, BB * CC * sizeof(float));

    dim3 gconv(HW / 128, BB);
    gemm_tc<CIN, 0><<<gconv, 256, SMEM_BYTES>>>(wk1f, bk1, source, 0, nullptr, kh);
    gemm_tc<CIN, 0><<<gconv, 256, SMEM_BYTES>>>(wvf,  bv,  source, 0, nullptr, val);
    gemm_tc<CIN, 0><<<gconv, 256, SMEM_BYTES>>>(wq1f, bq1, target, 0, nullptr, qh);
    gemm_tc<CC, 1><<<gconv, 256, SMEM_BYTES>>>(wk2f, bk2, kh, 0, nullptr, key);
    gemm_tc<CC, 1><<<gconv, 256, SMEM_BYTES>>>(wq2f, bq2, qh, 0, nullptr, qr);

    s_mma<<<dim3(NSPLIT, BB), 256, SMEM_BYTES>>>(val, key, S, Z);
    den_k<<<dim3(HW / 1024, BB), 256>>>(Z, qr, den);
    gemm_tc<CC, 2><<<gconv, 256, SMEM_BYTES>>>(S, nullptr, qr, (long)(CC * CC), den, (float*)d_out);
}

// round 5
// speedup vs baseline: 2.6310x; 1.1091x over previous
#include <cuda_runtime.h>
#include <cuda_bf16.h>
#include <math.h>
#include <stdint.h>

#define BB 8
#define CIN 256
#define CC 128
#define HW 16384
#define KB 32
#define NSPLIT 32
#define SCHUNK 512

#define APAD 36
#define BPAD 136
#define ASZ (128 * APAD)
#define BSZ (KB * BPAD)
#define SMEM_BYTES ((2 * (ASZ + BSZ) + 256) * 4)

// ---------------- scratch ----------------
__device__ float g_wkvf[2 * CC * CIN];   // rows 0-127: k_w1 folded, 128-255: v_w folded
__device__ float g_bkv [2 * CC];
__device__ float g_wq1f[CC * CIN];
__device__ float g_wq2f[CC * CC];
__device__ float g_wk2f[CC * CC];
__device__ float g_bq1[CC], g_bq2[CC], g_bk2[CC];
__device__ __nv_bfloat16 g_kv [(size_t)BB * 2 * CC * HW];  // [b][0:128]=k_h, [128:256]=value
__device__ __nv_bfloat16 g_qh [(size_t)BB * CC * HW];
__device__ __nv_bfloat16 g_qr [(size_t)BB * CC * HW];
__device__ __nv_bfloat16 g_key[(size_t)BB * CC * HW];
__device__ float g_S[BB * CC * CC];
__device__ float g_Z[BB * CC];

// ---------------- helpers ----------------
__device__ __forceinline__ float to_tf32(float x) {
    uint32_t u;
    asm("cvt.rna.tf32.f32 %0, %1;" : "=r"(u) : "f"(x));
    return __uint_as_float(u);
}
__device__ __forceinline__ float4 rnd4(float4 v) {
    return make_float4(to_tf32(v.x), to_tf32(v.y), to_tf32(v.z), to_tf32(v.w));
}
__device__ __forceinline__ float4 ld4(const float* p) { return *(const float4*)p; }
__device__ __forceinline__ float4 ld4(const __nv_bfloat16* p) {
    uint2 u = *(const uint2*)p;
    __nv_bfloat162 lo = *reinterpret_cast<__nv_bfloat162*>(&u.x);
    __nv_bfloat162 hi = *reinterpret_cast<__nv_bfloat162*>(&u.y);
    float2 f0 = __bfloat1622float2(lo), f1 = __bfloat1622float2(hi);
    return make_float4(f0.x, f0.y, f1.x, f1.y);
}

__device__ __forceinline__ void mma8(float* c, uint32_t a0, uint32_t a1,
                                     uint32_t a2, uint32_t a3,
                                     uint32_t b0, uint32_t b1) {
    asm volatile(
        "mma.sync.aligned.m16n8k8.row.col.f32.tf32.tf32.f32 "
        "{%0,%1,%2,%3}, {%4,%5,%6,%7}, {%8,%9}, {%0,%1,%2,%3};"
        : "+f"(c[0]), "+f"(c[1]), "+f"(c[2]), "+f"(c[3])
        : "r"(a0), "r"(a1), "r"(a2), "r"(a3), "r"(b0), "r"(b1));
}

__device__ __forceinline__ float softplus_f(float x) {
    return fmaxf(x, 0.f) + log1pf(expf(-fabsf(x)));
}

// ---------------- merged BN fold ----------------
struct PrepEnt { const float *w, *g, *b, *m, *v; float *wf, *bf; int K; };
struct PrepAll { PrepEnt e[5]; };

__global__ void fold5(PrepAll a) {
    PrepEnt p = a.e[blockIdx.y];
    int o = blockIdx.x;
    float s = p.g[o] * rsqrtf(p.v[o] + 1e-5f);
    if (threadIdx.x == 0) p.bf[o] = p.b[o] - p.m[o] * s;
    for (int c = threadIdx.x; c < p.K; c += blockDim.x)
        p.wf[o * p.K + c] = to_tf32(p.w[o * p.K + c] * s);
}

// ============================================================================
// Y[b, mt*128+m, n] = act( sum_k A[m,k] X[b,k,n] + bias[m] )
// ACT: 0 relu -> bf16, 1 softplus -> bf16, 2 out: (acc / max(den,eps)) -> f32
//   ACT==2 fuses den[n] = sum_k Z[k] * X[k,n] on the B-load path.
// ============================================================================
template <int KTOT, int ACT, int MTILES, typename TX, typename TY>
__global__ void __launch_bounds__(256)
gemm_tc(const float* __restrict__ W, const float* __restrict__ bias,
        const TX* __restrict__ X, long x_bstride, long a_bstride,
        const float* __restrict__ Zvec, TY* __restrict__ Y, long y_bstride) {
    extern __shared__ float smd[];
    float* As = smd;
    float* Bs = smd + 2 * ASZ;
    float* den_s = smd + 2 * (ASZ + BSZ);
    float* Zs = den_s + 128;
    const int tid = threadIdx.x;
    const int b = blockIdx.y;
    const int mt = (MTILES == 2) ? (blockIdx.x & 1) : 0;
    const int n0 = ((MTILES == 2) ? (blockIdx.x >> 1) : blockIdx.x) * 128;
    const int warp = tid >> 5, lane = tid & 31;
    const int wm = warp >> 1, wn = warp & 1;
    const int qid = lane >> 2, tq = lane & 3;
    const float* Ab = W + (size_t)b * a_bstride + (size_t)mt * 128 * KTOT;
    const TX* Xb = X + (size_t)b * x_bstride + n0;
    constexpr int NKB = KTOT / KB;

    float acc[2][8][4];
#pragma unroll
    for (int i = 0; i < 2; i++)
#pragma unroll
        for (int j = 0; j < 8; j++)
#pragma unroll
            for (int l = 0; l < 4; l++) acc[i][j][l] = 0.f;

    const int am = tid >> 3, ak = (tid & 7) * 4;
    const int bk = tid >> 5, bn = (tid & 31) * 4;
    float dreg[4] = {0.f, 0.f, 0.f, 0.f};

    if (ACT == 2) {
        if (tid < 128) { Zs[tid] = Zvec[b * CC + tid]; den_s[tid] = 0.f; }
        __syncthreads();
    }

    // preload tile 0
    {
#pragma unroll
        for (int i = 0; i < 4; i++) {
            int m = am + i * 32;
            float4 v = rnd4(ld4(Ab + (size_t)m * KTOT + ak));
            *(float4*)(As + m * APAD + ak) = v;
        }
#pragma unroll
        for (int i = 0; i < 4; i++) {
            int k = bk + i * 8;
            float4 v = ld4(Xb + (size_t)k * HW + bn);
            if (sizeof(TX) == 4) v = rnd4(v);
            if (ACT == 2) {
                float z = Zs[k];
                dreg[0] = fmaf(z, v.x, dreg[0]); dreg[1] = fmaf(z, v.y, dreg[1]);
                dreg[2] = fmaf(z, v.z, dreg[2]); dreg[3] = fmaf(z, v.w, dreg[3]);
            }
            *(float4*)(Bs + k * BPAD + bn) = v;
        }
    }
    __syncthreads();

    for (int kb = 0; kb < NKB; kb++) {
        float4 ra[4], rb[4];
        if (kb + 1 < NKB) {
            const int k0 = (kb + 1) * KB;
#pragma unroll
            for (int i = 0; i < 4; i++)
                ra[i] = ld4(Ab + (size_t)(am + i * 32) * KTOT + k0 + ak);
#pragma unroll
            for (int i = 0; i < 4; i++) {
                rb[i] = ld4(Xb + (size_t)(k0 + bk + i * 8) * HW + bn);
                if (ACT == 2) {
                    float z = Zs[k0 + bk + i * 8];
                    dreg[0] = fmaf(z, rb[i].x, dreg[0]); dreg[1] = fmaf(z, rb[i].y, dreg[1]);
                    dreg[2] = fmaf(z, rb[i].z, dreg[2]); dreg[3] = fmaf(z, rb[i].w, dreg[3]);
                }
            }
        }

        {
            float* Ad = As + (kb & 1) * ASZ;
            float* Bd = Bs + (kb & 1) * BSZ;
#pragma unroll
            for (int kk = 0; kk < 4; kk++) {
                uint32_t a[2][4], bf[8][2];
#pragma unroll
                for (int mw = 0; mw < 2; mw++) {
                    const float* ap = Ad + (wm * 32 + mw * 16 + qid) * APAD + kk * 8 + tq;
                    a[mw][0] = __float_as_uint(ap[0]);
                    a[mw][1] = __float_as_uint(ap[8 * APAD]);
                    a[mw][2] = __float_as_uint(ap[4]);
                    a[mw][3] = __float_as_uint(ap[8 * APAD + 4]);
                }
#pragma unroll
                for (int nw = 0; nw < 8; nw++) {
                    const float* bp = Bd + (kk * 8 + tq) * BPAD + wn * 64 + nw * 8 + qid;
                    bf[nw][0] = __float_as_uint(bp[0]);
                    bf[nw][1] = __float_as_uint(bp[4 * BPAD]);
                }
#pragma unroll
                for (int mw = 0; mw < 2; mw++)
#pragma unroll
                    for (int nw = 0; nw < 8; nw++)
                        mma8(acc[mw][nw], a[mw][0], a[mw][1], a[mw][2], a[mw][3],
                             bf[nw][0], bf[nw][1]);
            }
        }

        if (kb + 1 < NKB) {
            float* Ad = As + ((kb + 1) & 1) * ASZ;
            float* Bd = Bs + ((kb + 1) & 1) * BSZ;
#pragma unroll
            for (int i = 0; i < 4; i++)
                *(float4*)(Ad + (am + i * 32) * APAD + ak) = rnd4(ra[i]);
#pragma unroll
            for (int i = 0; i < 4; i++) {
                float4 v = rb[i];
                if (sizeof(TX) == 4) v = rnd4(v);
                *(float4*)(Bd + (bk + i * 8) * BPAD + bn) = v;
            }
        }
        __syncthreads();
    }

    if (ACT == 2) {
#pragma unroll
        for (int j = 0; j < 4; j++) atomicAdd(&den_s[bn + j], dreg[j]);
        __syncthreads();
    }

    // epilogue
    TY* Yb = Y + (size_t)b * y_bstride + (size_t)mt * 128 * HW + n0;
    const float* bp = (ACT != 2) ? bias + mt * 128 : nullptr;
#pragma unroll
    for (int mw = 0; mw < 2; mw++) {
        const int r0 = wm * 32 + mw * 16 + qid;
        float bv0 = 0.f, bv1 = 0.f;
        if (ACT != 2) { bv0 = bp[r0]; bv1 = bp[r0 + 8]; }
#pragma unroll
        for (int nw = 0; nw < 8; nw++) {
            const int col = wn * 64 + nw * 8 + tq * 2;
            float o00 = acc[mw][nw][0] + bv0, o01 = acc[mw][nw][1] + bv0;
            float o10 = acc[mw][nw][2] + bv1, o11 = acc[mw][nw][3] + bv1;
            if (ACT == 0) {
                o00 = fmaxf(o00, 0.f); o01 = fmaxf(o01, 0.f);
                o10 = fmaxf(o10, 0.f); o11 = fmaxf(o11, 0.f);
            } else if (ACT == 1) {
                o00 = softplus_f(o00); o01 = softplus_f(o01);
                o10 = softplus_f(o10); o11 = softplus_f(o11);
            } else {
                float i0 = 1.f / fmaxf(den_s[col], 1e-12f);
                float i1 = 1.f / fmaxf(den_s[col + 1], 1e-12f);
                o00 *= i0; o01 *= i1; o10 *= i0; o11 *= i1;
            }
            if (ACT == 2) {
                float2 p0 = { o00, o01 }, p1 = { o10, o11 };
                *(float2*)((float*)Yb + (size_t)r0 * HW + col) = p0;
                *(float2*)((float*)Yb + (size_t)(r0 + 8) * HW + col) = p1;
            } else {
                __nv_bfloat162 p0 = __floats2bfloat162_rn(o00, o01);
                __nv_bfloat162 p1 = __floats2bfloat162_rn(o10, o11);
                *(__nv_bfloat162*)((__nv_bfloat16*)Yb + (size_t)r0 * HW + col) = p0;
                *(__nv_bfloat162*)((__nv_bfloat16*)Yb + (size_t)(r0 + 8) * HW + col) = p1;
            }
        }
    }
}

// ============================================================================
// S[b,c,d] += sum_{n chunk} V[b,c,n] K[b,d,n]   (+ fused Z[b,d] = sum_n K)
// ============================================================================
__global__ void __launch_bounds__(256)
s_mma(const __nv_bfloat16* __restrict__ V, long v_bstride,
      const __nv_bfloat16* __restrict__ Kt,
      float* __restrict__ S, float* __restrict__ Z) {
    extern __shared__ float smd[];
    float* As = smd;
    float* Bs = smd + 2 * ASZ;
    const int tid = threadIdx.x;
    const int b = blockIdx.y;
    const int n0 = blockIdx.x * SCHUNK;
    const int warp = tid >> 5, lane = tid & 31;
    const int wm = warp >> 1, wn = warp & 1;
    const int qid = lane >> 2, tq = lane & 3;
    const __nv_bfloat16* Vb = V + (size_t)b * v_bstride + n0;
    const __nv_bfloat16* Kb = Kt + (size_t)b * CC * HW + n0;
    constexpr int NKB = SCHUNK / KB;

    float acc[2][8][4];
#pragma unroll
    for (int i = 0; i < 2; i++)
#pragma unroll
        for (int j = 0; j < 8; j++)
#pragma unroll
            for (int l = 0; l < 4; l++) acc[i][j][l] = 0.f;

    float zp[4] = {};
    const int am = tid >> 3, ak = (tid & 7) * 4;
    const int bd = tid >> 3, bq = (tid & 7) * 4;

    {
#pragma unroll
        for (int i = 0; i < 4; i++) {
            int m = am + i * 32;
            *(float4*)(As + m * APAD + ak) = ld4(Vb + (size_t)m * HW + ak);
        }
#pragma unroll
        for (int i = 0; i < 4; i++) {
            int d = bd + i * 32;
            float4 v = ld4(Kb + (size_t)d * HW + bq);
            zp[i] += v.x + v.y + v.z + v.w;
            Bs[(bq + 0) * BPAD + d] = v.x;
            Bs[(bq + 1) * BPAD + d] = v.y;
            Bs[(bq + 2) * BPAD + d] = v.z;
            Bs[(bq + 3) * BPAD + d] = v.w;
        }
    }
    __syncthreads();

    for (int kb = 0; kb < NKB; kb++) {
        float4 ra[4], rb[4];
        if (kb + 1 < NKB) {
            const int k0 = (kb + 1) * KB;
#pragma unroll
            for (int i = 0; i < 4; i++)
                ra[i] = ld4(Vb + (size_t)(am + i * 32) * HW + k0 + ak);
#pragma unroll
            for (int i = 0; i < 4; i++) {
                rb[i] = ld4(Kb + (size_t)(bd + i * 32) * HW + k0 + bq);
                zp[i] += rb[i].x + rb[i].y + rb[i].z + rb[i].w;
            }
        }

        {
            float* Ad = As + (kb & 1) * ASZ;
            float* Bd = Bs + (kb & 1) * BSZ;
#pragma unroll
            for (int kk = 0; kk < 4; kk++) {
                uint32_t a[2][4], bf[8][2];
#pragma unroll
                for (int mw = 0; mw < 2; mw++) {
                    const float* ap = Ad + (wm * 32 + mw * 16 + qid) * APAD + kk * 8 + tq;
                    a[mw][0] = __float_as_uint(ap[0]);
                    a[mw][1] = __float_as_uint(ap[8 * APAD]);
                    a[mw][2] = __float_as_uint(ap[4]);
                    a[mw][3] = __float_as_uint(ap[8 * APAD + 4]);
                }
#pragma unroll
                for (int nw = 0; nw < 8; nw++) {
                    const float* bp = Bd + (kk * 8 + tq) * BPAD + wn * 64 + nw * 8 + qid;
                    bf[nw][0] = __float_as_uint(bp[0]);
                    bf[nw][1] = __float_as_uint(bp[4 * BPAD]);
                }
#pragma unroll
                for (int mw = 0; mw < 2; mw++)
#pragma unroll
                    for (int nw = 0; nw < 8; nw++)
                        mma8(acc[mw][nw], a[mw][0], a[mw][1], a[mw][2], a[mw][3],
                             bf[nw][0], bf[nw][1]);
            }
        }

        if (kb + 1 < NKB) {
            float* Ad = As + ((kb + 1) & 1) * ASZ;
            float* Bd = Bs + ((kb + 1) & 1) * BSZ;
#pragma unroll
            for (int i = 0; i < 4; i++)
                *(float4*)(Ad + (am + i * 32) * APAD + ak) = ra[i];
#pragma unroll
            for (int i = 0; i < 4; i++) {
                int d = bd + i * 32;
                Bd[(bq + 0) * BPAD + d] = rb[i].x;
                Bd[(bq + 1) * BPAD + d] = rb[i].y;
                Bd[(bq + 2) * BPAD + d] = rb[i].z;
                Bd[(bq + 3) * BPAD + d] = rb[i].w;
            }
        }
        __syncthreads();
    }

#pragma unroll
    for (int i = 0; i < 4; i++) {
#pragma unroll
        for (int o = 1; o < 8; o <<= 1)
            zp[i] += __shfl_xor_sync(0xffffffff, zp[i], o);
        if ((lane & 7) == 0)
            atomicAdd(&Z[b * CC + (tid >> 3) + 32 * i], zp[i]);
    }

    float* Sb = S + (size_t)b * CC * CC;
#pragma unroll
    for (int mw = 0; mw < 2; mw++) {
        const int r0 = wm * 32 + mw * 16 + qid;
#pragma unroll
        for (int nw = 0; nw < 8; nw++) {
            const int col = wn * 64 + nw * 8 + tq * 2;
            atomicAdd(&Sb[(size_t)r0 * CC + col],       acc[mw][nw][0]);
            atomicAdd(&Sb[(size_t)r0 * CC + col + 1],   acc[mw][nw][1]);
            atomicAdd(&Sb[(size_t)(r0 + 8) * CC + col],     acc[mw][nw][2]);
            atomicAdd(&Sb[(size_t)(r0 + 8) * CC + col + 1], acc[mw][nw][3]);
        }
    }
}

// ---------------- launch ----------------
extern "C" void kernel_launch(void* const* d_in, const int* in_sizes, int n_in,
                              void* d_out, int out_size) {
    const float* target = (const float*)d_in[0];
    const float* source = (const float*)d_in[1];
    const float* q_w1 = (const float*)d_in[2];
    const float* q_w2 = (const float*)d_in[3];
    const float* k_w1 = (const float*)d_in[4];
    const float* k_w2 = (const float*)d_in[5];
    const float* v_w  = (const float*)d_in[6];

    float *wkvf, *bkv, *wq1f, *wq2f, *wk2f, *bq1, *bq2, *bk2, *S, *Z;
    __nv_bfloat16 *kv, *qh, *qr, *key;
    cudaGetSymbolAddress((void**)&wkvf, g_wkvf);
    cudaGetSymbolAddress((void**)&bkv,  g_bkv);
    cudaGetSymbolAddress((void**)&wq1f, g_wq1f);
    cudaGetSymbolAddress((void**)&wq2f, g_wq2f);
    cudaGetSymbolAddress((void**)&wk2f, g_wk2f);
    cudaGetSymbolAddress((void**)&bq1, g_bq1);
    cudaGetSymbolAddress((void**)&bq2, g_bq2);
    cudaGetSymbolAddress((void**)&bk2, g_bk2);
    cudaGetSymbolAddress((void**)&kv,  g_kv);
    cudaGetSymbolAddress((void**)&qh,  g_qh);
    cudaGetSymbolAddress((void**)&qr,  g_qr);
    cudaGetSymbolAddress((void**)&key, g_key);
    cudaGetSymbolAddress((void**)&S,   g_S);
    cudaGetSymbolAddress((void**)&Z,   g_Z);

    cudaFuncSetAttribute(gemm_tc<CIN, 0, 2, float, __nv_bfloat16>, cudaFuncAttributeMaxDynamicSharedMemorySize, SMEM_BYTES);
    cudaFuncSetAttribute(gemm_tc<CIN, 0, 1, float, __nv_bfloat16>, cudaFuncAttributeMaxDynamicSharedMemorySize, SMEM_BYTES);
    cudaFuncSetAttribute(gemm_tc<CC, 1, 1, __nv_bfloat16, __nv_bfloat16>, cudaFuncAttributeMaxDynamicSharedMemorySize, SMEM_BYTES);
    cudaFuncSetAttribute(gemm_tc<CC, 2, 1, __nv_bfloat16, float>, cudaFuncAttributeMaxDynamicSharedMemorySize, SMEM_BYTES);
    cudaFuncSetAttribute(s_mma, cudaFuncAttributeMaxDynamicSharedMemorySize, SMEM_BYTES);

    // merged BN fold: k1 -> wkv rows 0-127, v -> wkv rows 128-255
    PrepAll pa;
    pa.e[0] = { k_w1, (const float*)d_in[15], (const float*)d_in[16], (const float*)d_in[17], (const float*)d_in[18], wkvf, bkv, CIN };
    pa.e[1] = { v_w,  (const float*)d_in[23], (const float*)d_in[24], (const float*)d_in[25], (const float*)d_in[26], wkvf + CC * CIN, bkv + CC, CIN };
    pa.e[2] = { q_w1, (const float*)d_in[7],  (const float*)d_in[8],  (const float*)d_in[9],  (const float*)d_in[10], wq1f, bq1, CIN };
    pa.e[3] = { q_w2, (const float*)d_in[11], (const float*)d_in[12], (const float*)d_in[13], (const float*)d_in[14], wq2f, bq2, CC };
    pa.e[4] = { k_w2, (const float*)d_in[19], (const float*)d_in[20], (const float*)d_in[21], (const float*)d_in[22], wk2f, bk2, CC };
    fold5<<<dim3(CC, 5), 256>>>(pa);

    cudaMemsetAsync(S, 0, BB * CC * CC * sizeof(float));
    cudaMemsetAsync(Z, 0, BB * CC * sizeof(float));

    // conv1 dual: source -> [k_h ; value] bf16 (mtile interleaved for L2 reuse)
    gemm_tc<CIN, 0, 2, float, __nv_bfloat16><<<dim3(HW / 128 * 2, BB), 256, SMEM_BYTES>>>(
        wkvf, bkv, source, (long)CIN * HW, 0, nullptr, kv, (long)2 * CC * HW);
    // conv1 q: target -> qh bf16
    gemm_tc<CIN, 0, 1, float, __nv_bfloat16><<<dim3(HW / 128, BB), 256, SMEM_BYTES>>>(
        wq1f, bq1, target, (long)CIN * HW, 0, nullptr, qh, (long)CC * HW);
    // conv2: key (from kv rows 0-127), query
    gemm_tc<CC, 1, 1, __nv_bfloat16, __nv_bfloat16><<<dim3(HW / 128, BB), 256, SMEM_BYTES>>>(
        wk2f, bk2, kv, (long)2 * CC * HW, 0, nullptr, key, (long)CC * HW);
    gemm_tc<CC, 1, 1, __nv_bfloat16, __nv_bfloat16><<<dim3(HW / 128, BB), 256, SMEM_BYTES>>>(
        wq2f, bq2, qh, (long)CC * HW, 0, nullptr, qr, (long)CC * HW);
    // S = V K^T + fused Z   (value = kv rows 128-255)
    s_mma<<<dim3(NSPLIT, BB), 256, SMEM_BYTES>>>(kv + (size_t)CC * HW, (long)2 * CC * HW, key, S, Z);
    // out = (S q) / max(Z.q, eps)  with den fused
    gemm_tc<CC, 2, 1, __nv_bfloat16, float><<<dim3(HW / 128, BB), 256, SMEM_BYTES>>>(
        S, nullptr, qr, (long)CC * HW, (long)CC * CC, Z, (float*)d_out, (long)CC * HW);
}

// round 6
// speedup vs baseline: 3.3686x; 1.2804x over previous
#include <cuda_runtime.h>
#include <cuda_bf16.h>
#include <math.h>
#include <stdint.h>

#define BB 8
#define CIN 256
#define CC 128
#define HW 16384
#define NSPLIT 32
#define SCHUNK 512

// ---- bf16 hgemm tiles ----
#define KPAD 40
#define NPAD 136
#define HA_STG (128 * KPAD)
#define HB_STG (32 * NPAD)
#define HSM_BYTES ((2 * HA_STG + 2 * HB_STG) * 2)
#define SSM_BYTES (4 * HA_STG * 2)

// ---- tf32 out-gemm tiles (legacy path) ----
#define KB 32
#define APAD 36
#define BPAD 136
#define ASZ (128 * APAD)
#define BSZ (KB * BPAD)
#define TSM_BYTES ((2 * (ASZ + BSZ) + 256) * 4)

// ---------------- scratch ----------------
__device__ float g_wkvf[2 * CC * CIN];
__device__ float g_bkv [2 * CC];
__device__ float g_wq1f[CC * CIN];
__device__ float g_wq2f[CC * CC];
__device__ float g_wk2f[CC * CC];
__device__ float g_bq1[CC], g_bq2[CC], g_bk2[CC];
__device__ __nv_bfloat16 g_kv [(size_t)BB * 2 * CC * HW];
__device__ __nv_bfloat16 g_qh [(size_t)BB * CC * HW];
__device__ __nv_bfloat16 g_qr [(size_t)BB * CC * HW];
__device__ __nv_bfloat16 g_key[(size_t)BB * CC * HW];
__device__ float g_S[BB * CC * CC];
__device__ float g_Z[BB * CC];

// ---------------- helpers ----------------
__device__ __forceinline__ float to_tf32(float x) {
    uint32_t u;
    asm("cvt.rna.tf32.f32 %0, %1;" : "=r"(u) : "f"(x));
    return __uint_as_float(u);
}
__device__ __forceinline__ float4 rnd4(float4 v) {
    return make_float4(to_tf32(v.x), to_tf32(v.y), to_tf32(v.z), to_tf32(v.w));
}
__device__ __forceinline__ float4 ld4(const float* p) { return *(const float4*)p; }
__device__ __forceinline__ float4 ld4(const __nv_bfloat16* p) {
    uint2 u = *(const uint2*)p;
    __nv_bfloat162 lo = *reinterpret_cast<__nv_bfloat162*>(&u.x);
    __nv_bfloat162 hi = *reinterpret_cast<__nv_bfloat162*>(&u.y);
    float2 f0 = __bfloat1622float2(lo), f1 = __bfloat1622float2(hi);
    return make_float4(f0.x, f0.y, f1.x, f1.y);
}
__device__ __forceinline__ void st4h(__nv_bfloat16* p, float4 v) {
    __nv_bfloat162 lo = __floats2bfloat162_rn(v.x, v.y);
    __nv_bfloat162 hi = __floats2bfloat162_rn(v.z, v.w);
    uint2 u = { *(uint32_t*)&lo, *(uint32_t*)&hi };
    *(uint2*)p = u;
}
__device__ __forceinline__ void ldsm4(uint32_t* r, uint32_t a) {
    asm volatile("ldmatrix.sync.aligned.m8n8.x4.shared.b16 {%0,%1,%2,%3}, [%4];"
                 : "=r"(r[0]), "=r"(r[1]), "=r"(r[2]), "=r"(r[3]) : "r"(a));
}
__device__ __forceinline__ void ldsm4t(uint32_t* r, uint32_t a) {
    asm volatile("ldmatrix.sync.aligned.m8n8.x4.trans.shared.b16 {%0,%1,%2,%3}, [%4];"
                 : "=r"(r[0]), "=r"(r[1]), "=r"(r[2]), "=r"(r[3]) : "r"(a));
}
__device__ __forceinline__ void mma16(float* c, const uint32_t* a, const uint32_t* b) {
    asm volatile("mma.sync.aligned.m16n8k16.row.col.f32.bf16.bf16.f32 "
                 "{%0,%1,%2,%3}, {%4,%5,%6,%7}, {%8,%9}, {%0,%1,%2,%3};"
                 : "+f"(c[0]), "+f"(c[1]), "+f"(c[2]), "+f"(c[3])
                 : "r"(a[0]), "r"(a[1]), "r"(a[2]), "r"(a[3]), "r"(b[0]), "r"(b[1]));
}
__device__ __forceinline__ void mma8(float* c, uint32_t a0, uint32_t a1,
                                     uint32_t a2, uint32_t a3,
                                     uint32_t b0, uint32_t b1) {
    asm volatile(
        "mma.sync.aligned.m16n8k8.row.col.f32.tf32.tf32.f32 "
        "{%0,%1,%2,%3}, {%4,%5,%6,%7}, {%8,%9}, {%0,%1,%2,%3};"
        : "+f"(c[0]), "+f"(c[1]), "+f"(c[2]), "+f"(c[3])
        : "r"(a0), "r"(a1), "r"(a2), "r"(a3), "r"(b0), "r"(b1));
}
__device__ __forceinline__ float softplus_f(float x) {
    return fmaxf(x, 0.f) + log1pf(expf(-fabsf(x)));
}

// ---------------- merged BN fold ----------------
struct PrepEnt { const float *w, *g, *b, *m, *v; float *wf, *bf; int K; };
struct PrepAll { PrepEnt e[5]; };

__global__ void fold5(PrepAll a) {
    PrepEnt p = a.e[blockIdx.y];
    int o = blockIdx.x;
    float s = p.g[o] * rsqrtf(p.v[o] + 1e-5f);
    if (threadIdx.x == 0) p.bf[o] = p.b[o] - p.m[o] * s;
    for (int c = threadIdx.x; c < p.K; c += blockDim.x)
        p.wf[o * p.K + c] = p.w[o * p.K + c] * s;
}

// ---------------- smem fills for hgemm ----------------
__device__ __forceinline__ void fillA_h(__nv_bfloat16* Ad, const float* Ab,
                                        int KTOT, int k0, int tid) {
#pragma unroll
    for (int i = 0; i < 4; i++) {
        int m = (tid >> 3) + 32 * i, kf = (tid & 7) * 4;
        float4 v = *(const float4*)(Ab + (size_t)m * KTOT + k0 + kf);
        st4h(Ad + m * KPAD + kf, v);
    }
}
__device__ __forceinline__ void fillB_h(__nv_bfloat16* Bd, const float* Xb,
                                        int k0, int tid) {
#pragma unroll
    for (int i = 0; i < 4; i++) {
        int k = (tid >> 5) + 8 * i, nf = (tid & 31) * 4;
        float4 v = *(const float4*)(Xb + (size_t)(k0 + k) * HW + nf);
        st4h(Bd + k * NPAD + nf, v);
    }
}
__device__ __forceinline__ void fillB_h(__nv_bfloat16* Bd, const __nv_bfloat16* Xb,
                                        int k0, int tid) {
#pragma unroll
    for (int i = 0; i < 2; i++) {
        int k = (tid >> 4) + 16 * i, nf = (tid & 15) * 8;
        *(uint4*)(Bd + k * NPAD + nf) = *(const uint4*)(Xb + (size_t)(k0 + k) * HW + nf);
    }
}

// ============================================================================
// bf16 GEMM: Y[b, mt*128+m, n] = act( sum_k A[m,k] X[b,k,n] + bias[m] ) -> bf16
// ACT: 0 relu, 1 softplus.  m16n8k16 bf16 MMA + ldmatrix.
// ============================================================================
template <int KTOT, int ACT, int MTILES, typename TX>
__global__ void __launch_bounds__(256, 2)
hgemm(const float* __restrict__ W, const float* __restrict__ bias,
      const TX* __restrict__ X, long x_bstride,
      __nv_bfloat16* __restrict__ Y, long y_bstride) {
    extern __shared__ __nv_bfloat16 hsm[];
    __nv_bfloat16* As = hsm;
    __nv_bfloat16* Bs = hsm + 2 * HA_STG;
    const int tid = threadIdx.x;
    const int b = blockIdx.y;
    const int mt = (MTILES == 2) ? (blockIdx.x & 1) : 0;
    const int n0 = ((MTILES == 2) ? (blockIdx.x >> 1) : blockIdx.x) * 128;
    const int warp = tid >> 5, lane = tid & 31;
    const int wm = warp >> 1, wn = warp & 1;
    const int qid = lane >> 2, tq = lane & 3;
    const float* Ab = W + (size_t)mt * 128 * KTOT;
    const TX* Xb = X + (size_t)b * x_bstride + n0;
    constexpr int NKB = KTOT / 32;

    float acc[2][8][4];
#pragma unroll
    for (int i = 0; i < 2; i++)
#pragma unroll
        for (int j = 0; j < 8; j++)
#pragma unroll
            for (int l = 0; l < 4; l++) acc[i][j][l] = 0.f;

    const uint32_t sbase = (uint32_t)__cvta_generic_to_shared(hsm);
    const uint32_t aLane = ((lane & 15) * KPAD + (lane >> 4) * 8) * 2;
    const uint32_t bLane = ((lane & 15) * NPAD + (lane >> 4) * 8) * 2;

    fillA_h(As, Ab, KTOT, 0, tid);
    fillB_h(Bs, Xb, 0, tid);
    __syncthreads();

    for (int kb = 0; kb < NKB; kb++) {
        if (kb + 1 < NKB) {
            fillA_h(As + ((kb + 1) & 1) * HA_STG, Ab, KTOT, (kb + 1) * 32, tid);
            fillB_h(Bs + ((kb + 1) & 1) * HB_STG, Xb, (kb + 1) * 32, tid);
        }
        const uint32_t sA = sbase + ((kb & 1) * HA_STG) * 2;
        const uint32_t sB = sbase + (2 * HA_STG + (kb & 1) * HB_STG) * 2;
#pragma unroll
        for (int kk = 0; kk < 2; kk++) {
            uint32_t a[2][4], bq[8][2];
#pragma unroll
            for (int mw = 0; mw < 2; mw++)
                ldsm4(a[mw], sA + ((wm * 32 + mw * 16) * KPAD) * 2 + kk * 32 + aLane);
#pragma unroll
            for (int ng = 0; ng < 4; ng++) {
                uint32_t r[4];
                ldsm4t(r, sB + (kk * 16 * NPAD + wn * 64 + ng * 16) * 2 + bLane);
                bq[2 * ng][0] = r[0]; bq[2 * ng][1] = r[1];
                bq[2 * ng + 1][0] = r[2]; bq[2 * ng + 1][1] = r[3];
            }
#pragma unroll
            for (int mw = 0; mw < 2; mw++)
#pragma unroll
                for (int nw = 0; nw < 8; nw++)
                    mma16(acc[mw][nw], a[mw], bq[nw]);
        }
        __syncthreads();
    }

    __nv_bfloat16* Yb = Y + (size_t)b * y_bstride + (size_t)mt * 128 * HW + n0;
    const float* bp = bias + mt * 128;
#pragma unroll
    for (int mw = 0; mw < 2; mw++) {
        const int r0 = wm * 32 + mw * 16 + qid;
        float bv0 = bp[r0], bv1 = bp[r0 + 8];
#pragma unroll
        for (int nw = 0; nw < 8; nw++) {
            const int col = wn * 64 + nw * 8 + tq * 2;
            float o00 = acc[mw][nw][0] + bv0, o01 = acc[mw][nw][1] + bv0;
            float o10 = acc[mw][nw][2] + bv1, o11 = acc[mw][nw][3] + bv1;
            if (ACT == 0) {
                o00 = fmaxf(o00, 0.f); o01 = fmaxf(o01, 0.f);
                o10 = fmaxf(o10, 0.f); o11 = fmaxf(o11, 0.f);
            } else {
                o00 = softplus_f(o00); o01 = softplus_f(o01);
                o10 = softplus_f(o10); o11 = softplus_f(o11);
            }
            __nv_bfloat162 p0 = __floats2bfloat162_rn(o00, o01);
            __nv_bfloat162 p1 = __floats2bfloat162_rn(o10, o11);
            *(__nv_bfloat162*)(Yb + (size_t)r0 * HW + col) = p0;
            *(__nv_bfloat162*)(Yb + (size_t)(r0 + 8) * HW + col) = p1;
        }
    }
}

// ============================================================================
// S[b,c,d] += sum_n V[b,c,n] K[b,d,n]  (bf16 MMA; both tiles k-contig)
// + fused Z[b,d] = sum_n K[b,d,n]
// ============================================================================
__global__ void __launch_bounds__(256, 2)
s_bf(const __nv_bfloat16* __restrict__ V, long v_bstride,
     const __nv_bfloat16* __restrict__ Kt,
     float* __restrict__ S, float* __restrict__ Z) {
    extern __shared__ __nv_bfloat16 hsm[];
    __nv_bfloat16* As = hsm;                 // V: 2 stages [128][KPAD]
    __nv_bfloat16* Bs = hsm + 2 * HA_STG;    // K: 2 stages [128][KPAD]
    const int tid = threadIdx.x;
    const int b = blockIdx.y;
    const int n0 = blockIdx.x * SCHUNK;
    const int warp = tid >> 5, lane = tid & 31;
    const int wm = warp >> 1, wn = warp & 1;
    const int qid = lane >> 2, tq = lane & 3;
    const __nv_bfloat16* Vb = V + (size_t)b * v_bstride + n0;
    const __nv_bfloat16* Kb = Kt + (size_t)b * CC * HW + n0;
    constexpr int NKB = SCHUNK / 32;

    float acc[2][8][4];
#pragma unroll
    for (int i = 0; i < 2; i++)
#pragma unroll
        for (int j = 0; j < 8; j++)
#pragma unroll
            for (int l = 0; l < 4; l++) acc[i][j][l] = 0.f;

    float zp[2] = {0.f, 0.f};
    const uint32_t sbase = (uint32_t)__cvta_generic_to_shared(hsm);
    const uint32_t lLane = ((lane & 15) * KPAD + (lane >> 4) * 8) * 2;

    auto fill = [&](int stage, int k0) {
        __nv_bfloat16* Ad = As + stage * HA_STG;
        __nv_bfloat16* Bd = Bs + stage * HA_STG;
#pragma unroll
        for (int t = 0; t < 2; t++) {
            int f = tid + 256 * t;
            int row = f >> 2, kf = (f & 3) * 8;
            *(uint4*)(Ad + row * KPAD + kf) = *(const uint4*)(Vb + (size_t)row * HW + k0 + kf);
            uint4 kv4 = *(const uint4*)(Kb + (size_t)row * HW + k0 + kf);
            *(uint4*)(Bd + row * KPAD + kf) = kv4;
            const __nv_bfloat162* h = (const __nv_bfloat162*)&kv4;
#pragma unroll
            for (int j = 0; j < 4; j++) {
                float2 f2 = __bfloat1622float2(h[j]);
                zp[t] += f2.x + f2.y;
            }
        }
    };

    fill(0, 0);
    __syncthreads();

    for (int kb = 0; kb < NKB; kb++) {
        if (kb + 1 < NKB) fill((kb + 1) & 1, (kb + 1) * 32);
        const uint32_t sA = sbase + ((kb & 1) * HA_STG) * 2;
        const uint32_t sB = sbase + (2 * HA_STG + (kb & 1) * HA_STG) * 2;
#pragma unroll
        for (int kk = 0; kk < 2; kk++) {
            uint32_t a[2][4], bq[8][2];
#pragma unroll
            for (int mw = 0; mw < 2; mw++)
                ldsm4(a[mw], sA + ((wm * 32 + mw * 16) * KPAD) * 2 + kk * 32 + lLane);
#pragma unroll
            for (int ng = 0; ng < 4; ng++) {
                uint32_t r[4];
                ldsm4(r, sB + ((wn * 64 + ng * 16) * KPAD) * 2 + kk * 32 + lLane);
                bq[2 * ng][0] = r[0]; bq[2 * ng][1] = r[2];
                bq[2 * ng + 1][0] = r[1]; bq[2 * ng + 1][1] = r[3];
            }
#pragma unroll
            for (int mw = 0; mw < 2; mw++)
#pragma unroll
                for (int nw = 0; nw < 8; nw++)
                    mma16(acc[mw][nw], a[mw], bq[nw]);
        }
        __syncthreads();
    }

    // Z reduce: zp[t] belongs to row (tid>>2) + 64t, partial over (tid&3)
#pragma unroll
    for (int o = 1; o < 4; o <<= 1) {
        zp[0] += __shfl_xor_sync(0xffffffff, zp[0], o);
        zp[1] += __shfl_xor_sync(0xffffffff, zp[1], o);
    }
    if ((lane & 3) == 0) {
        atomicAdd(&Z[b * CC + (tid >> 2)], zp[0]);
        atomicAdd(&Z[b * CC + 64 + (tid >> 2)], zp[1]);
    }

    float* Sb = S + (size_t)b * CC * CC;
#pragma unroll
    for (int mw = 0; mw < 2; mw++) {
        const int r0 = wm * 32 + mw * 16 + qid;
#pragma unroll
        for (int nw = 0; nw < 8; nw++) {
            const int col = wn * 64 + nw * 8 + tq * 2;
            atomicAdd(&Sb[(size_t)r0 * CC + col],           acc[mw][nw][0]);
            atomicAdd(&Sb[(size_t)r0 * CC + col + 1],       acc[mw][nw][1]);
            atomicAdd(&Sb[(size_t)(r0 + 8) * CC + col],     acc[mw][nw][2]);
            atomicAdd(&Sb[(size_t)(r0 + 8) * CC + col + 1], acc[mw][nw][3]);
        }
    }
}

// ============================================================================
// out GEMM (tf32, den fused): out[b,c,n] = (sum_d S q) / max(sum_d Z q, eps)
// ============================================================================
__global__ void __launch_bounds__(256)
out_tc(const float* __restrict__ Sg, const __nv_bfloat16* __restrict__ Q,
       const float* __restrict__ Zvec, float* __restrict__ Y) {
    extern __shared__ float smd[];
    float* As = smd;
    float* Bs = smd + 2 * ASZ;
    float* den_s = smd + 2 * (ASZ + BSZ);
    float* Zs = den_s + 128;
    const int tid = threadIdx.x;
    const int b = blockIdx.y;
    const int n0 = blockIdx.x * 128;
    const int warp = tid >> 5, lane = tid & 31;
    const int wm = warp >> 1, wn = warp & 1;
    const int qid = lane >> 2, tq = lane & 3;
    const float* Ab = Sg + (size_t)b * CC * CC;
    const __nv_bfloat16* Xb = Q + (size_t)b * CC * HW + n0;
    constexpr int NKB = CC / KB;

    float acc[2][8][4];
#pragma unroll
    for (int i = 0; i < 2; i++)
#pragma unroll
        for (int j = 0; j < 8; j++)
#pragma unroll
            for (int l = 0; l < 4; l++) acc[i][j][l] = 0.f;

    const int am = tid >> 3, ak = (tid & 7) * 4;
    const int bk = tid >> 5, bn = (tid & 31) * 4;
    float dreg[4] = {0.f, 0.f, 0.f, 0.f};

    if (tid < 128) { Zs[tid] = Zvec[b * CC + tid]; den_s[tid] = 0.f; }
    __syncthreads();

    {
#pragma unroll
        for (int i = 0; i < 4; i++) {
            int m = am + i * 32;
            *(float4*)(As + m * APAD + ak) = rnd4(ld4(Ab + (size_t)m * CC + ak));
        }
#pragma unroll
        for (int i = 0; i < 4; i++) {
            int k = bk + i * 8;
            float4 v = ld4(Xb + (size_t)k * HW + bn);
            float z = Zs[k];
            dreg[0] = fmaf(z, v.x, dreg[0]); dreg[1] = fmaf(z, v.y, dreg[1]);
            dreg[2] = fmaf(z, v.z, dreg[2]); dreg[3] = fmaf(z, v.w, dreg[3]);
            *(float4*)(Bs + k * BPAD + bn) = v;
        }
    }
    __syncthreads();

    for (int kb = 0; kb < NKB; kb++) {
        float4 ra[4], rb[4];
        if (kb + 1 < NKB) {
            const int k0 = (kb + 1) * KB;
#pragma unroll
            for (int i = 0; i < 4; i++)
                ra[i] = ld4(Ab + (size_t)(am + i * 32) * CC + k0 + ak);
#pragma unroll
            for (int i = 0; i < 4; i++) {
                rb[i] = ld4(Xb + (size_t)(k0 + bk + i * 8) * HW + bn);
                float z = Zs[k0 + bk + i * 8];
                dreg[0] = fmaf(z, rb[i].x, dreg[0]); dreg[1] = fmaf(z, rb[i].y, dreg[1]);
                dreg[2] = fmaf(z, rb[i].z, dreg[2]); dreg[3] = fmaf(z, rb[i].w, dreg[3]);
            }
        }
        {
            float* Ad = As + (kb & 1) * ASZ;
            float* Bd = Bs + (kb & 1) * BSZ;
#pragma unroll
            for (int kk = 0; kk < 4; kk++) {
                uint32_t a[2][4], bf[8][2];
#pragma unroll
                for (int mw = 0; mw < 2; mw++) {
                    const float* ap = Ad + (wm * 32 + mw * 16 + qid) * APAD + kk * 8 + tq;
                    a[mw][0] = __float_as_uint(ap[0]);
                    a[mw][1] = __float_as_uint(ap[8 * APAD]);
                    a[mw][2] = __float_as_uint(ap[4]);
                    a[mw][3] = __float_as_uint(ap[8 * APAD + 4]);
                }
#pragma unroll
                for (int nw = 0; nw < 8; nw++) {
                    const float* bp = Bd + (kk * 8 + tq) * BPAD + wn * 64 + nw * 8 + qid;
                    bf[nw][0] = __float_as_uint(bp[0]);
                    bf[nw][1] = __float_as_uint(bp[4 * BPAD]);
                }
#pragma unroll
                for (int mw = 0; mw < 2; mw++)
#pragma unroll
                    for (int nw = 0; nw < 8; nw++)
                        mma8(acc[mw][nw], a[mw][0], a[mw][1], a[mw][2], a[mw][3],
                             bf[nw][0], bf[nw][1]);
            }
        }
        if (kb + 1 < NKB) {
            float* Ad = As + ((kb + 1) & 1) * ASZ;
            float* Bd = Bs + ((kb + 1) & 1) * BSZ;
#pragma unroll
            for (int i = 0; i < 4; i++)
                *(float4*)(Ad + (am + i * 32) * APAD + ak) = rnd4(ra[i]);
#pragma unroll
            for (int i = 0; i < 4; i++)
                *(float4*)(Bd + (bk + i * 8) * BPAD + bn) = rb[i];
        }
        __syncthreads();
    }

#pragma unroll
    for (int j = 0; j < 4; j++) atomicAdd(&den_s[bn + j], dreg[j]);
    __syncthreads();

    float* Yb = Y + (size_t)b * CC * HW + n0;
#pragma unroll
    for (int mw = 0; mw < 2; mw++) {
        const int r0 = wm * 32 + mw * 16 + qid;
#pragma unroll
        for (int nw = 0; nw < 8; nw++) {
            const int col = wn * 64 + nw * 8 + tq * 2;
            float i0 = 1.f / fmaxf(den_s[col], 1e-12f);
            float i1 = 1.f / fmaxf(den_s[col + 1], 1e-12f);
            float2 p0 = { acc[mw][nw][0] * i0, acc[mw][nw][1] * i1 };
            float2 p1 = { acc[mw][nw][2] * i0, acc[mw][nw][3] * i1 };
            *(float2*)(Yb + (size_t)r0 * HW + col) = p0;
            *(float2*)(Yb + (size_t)(r0 + 8) * HW + col) = p1;
        }
    }
}

// ---------------- launch ----------------
extern "C" void kernel_launch(void* const* d_in, const int* in_sizes, int n_in,
                              void* d_out, int out_size) {
    const float* target = (const float*)d_in[0];
    const float* source = (const float*)d_in[1];
    const float* q_w1 = (const float*)d_in[2];
    const float* q_w2 = (const float*)d_in[3];
    const float* k_w1 = (const float*)d_in[4];
    const float* k_w2 = (const float*)d_in[5];
    const float* v_w  = (const float*)d_in[6];

    float *wkvf, *bkv, *wq1f, *wq2f, *wk2f, *bq1, *bq2, *bk2, *S, *Z;
    __nv_bfloat16 *kv, *qh, *qr, *key;
    cudaGetSymbolAddress((void**)&wkvf, g_wkvf);
    cudaGetSymbolAddress((void**)&bkv,  g_bkv);
    cudaGetSymbolAddress((void**)&wq1f, g_wq1f);
    cudaGetSymbolAddress((void**)&wq2f, g_wq2f);
    cudaGetSymbolAddress((void**)&wk2f, g_wk2f);
    cudaGetSymbolAddress((void**)&bq1, g_bq1);
    cudaGetSymbolAddress((void**)&bq2, g_bq2);
    cudaGetSymbolAddress((void**)&bk2, g_bk2);
    cudaGetSymbolAddress((void**)&kv,  g_kv);
    cudaGetSymbolAddress((void**)&qh,  g_qh);
    cudaGetSymbolAddress((void**)&qr,  g_qr);
    cudaGetSymbolAddress((void**)&key, g_key);
    cudaGetSymbolAddress((void**)&S,   g_S);
    cudaGetSymbolAddress((void**)&Z,   g_Z);

    cudaFuncSetAttribute(hgemm<CIN, 0, 2, float>, cudaFuncAttributeMaxDynamicSharedMemorySize, HSM_BYTES);
    cudaFuncSetAttribute(hgemm<CIN, 0, 1, float>, cudaFuncAttributeMaxDynamicSharedMemorySize, HSM_BYTES);
    cudaFuncSetAttribute(hgemm<CC, 1, 1, __nv_bfloat16>, cudaFuncAttributeMaxDynamicSharedMemorySize, HSM_BYTES);
    cudaFuncSetAttribute(s_bf, cudaFuncAttributeMaxDynamicSharedMemorySize, SSM_BYTES);
    cudaFuncSetAttribute(out_tc, cudaFuncAttributeMaxDynamicSharedMemorySize, TSM_BYTES);

    PrepAll pa;
    pa.e[0] = { k_w1, (const float*)d_in[15], (const float*)d_in[16], (const float*)d_in[17], (const float*)d_in[18], wkvf, bkv, CIN };
    pa.e[1] = { v_w,  (const float*)d_in[23], (const float*)d_in[24], (const float*)d_in[25], (const float*)d_in[26], wkvf + CC * CIN, bkv + CC, CIN };
    pa.e[2] = { q_w1, (const float*)d_in[7],  (const float*)d_in[8],  (const float*)d_in[9],  (const float*)d_in[10], wq1f, bq1, CIN };
    pa.e[3] = { q_w2, (const float*)d_in[11], (const float*)d_in[12], (const float*)d_in[13], (const float*)d_in[14], wq2f, bq2, CC };
    pa.e[4] = { k_w2, (const float*)d_in[19], (const float*)d_in[20], (const float*)d_in[21], (const float*)d_in[22], wk2f, bk2, CC };
    fold5<<<dim3(CC, 5), 256>>>(pa);

    cudaMemsetAsync(S, 0, BB * CC * CC * sizeof(float));
    cudaMemsetAsync(Z, 0, BB * CC * sizeof(float));

    // conv1 dual: source -> [k_h ; value] bf16
    hgemm<CIN, 0, 2, float><<<dim3(HW / 128 * 2, BB), 256, HSM_BYTES>>>(
        wkvf, bkv, source, (long)CIN * HW, kv, (long)2 * CC * HW);
    // conv1 q: target -> qh
    hgemm<CIN, 0, 1, float><<<dim3(HW / 128, BB), 256, HSM_BYTES>>>(
        wq1f, bq1, target, (long)CIN * HW, qh, (long)CC * HW);
    // conv2: key / query (softplus)
    hgemm<CC, 1, 1, __nv_bfloat16><<<dim3(HW / 128, BB), 256, HSM_BYTES>>>(
        wk2f, bk2, kv, (long)2 * CC * HW, key, (long)CC * HW);
    hgemm<CC, 1, 1, __nv_bfloat16><<<dim3(HW / 128, BB), 256, HSM_BYTES>>>(
        wq2f, bq2, qh, (long)CC * HW, qr, (long)CC * HW);
    // S = V K^T + fused Z
    s_bf<<<dim3(NSPLIT, BB), 256, SSM_BYTES>>>(kv + (size_t)CC * HW, (long)2 * CC * HW, key, S, Z);
    // out
    out_tc<<<dim3(HW / 128, BB), 256, TSM_BYTES>>>(S, qr, Z, (float*)d_out);
}

// round 9
// speedup vs baseline: 3.6983x; 1.0979x over previous
#include <cuda_runtime.h>
#include <cuda_bf16.h>
#include <math.h>
#include <stdint.h>

#define BB 8
#define CIN 256
#define CC 128
#define HW 16384
#define NSPLIT 32
#define SCHUNK 512

#define KPAD 40
#define NPAD 136
#define A2PAD 136
#define HA_STG (128 * KPAD)      // 5120 elems
#define HB_STG (32 * NPAD)       // 4352 elems

// chain kernel smem layout (bf16 elems):
// phase1: [AS 2*5120][BS 2*4352] at offset 0   (18944 elems)
// phase2: A2 (128*A2PAD = 17408) ALIASES offset 0 after phase1 completes
// B2 (128*NPAD = 17408) lives separately after the phase1 region.
#define AS_OFF 0
#define BS_OFF (AS_OFF + 2 * HA_STG)          // 10240
#define P1_ELEMS (BS_OFF + 2 * HB_STG)        // 18944
#define A2_OFF 0
#define B2_OFF P1_ELEMS                        // 18944
#define CHAIN_ELEMS (B2_OFF + 128 * NPAD)      // 36352
#define CHAIN_SM_BYTES (CHAIN_ELEMS * 2)       // 72704
#define SSM_BYTES (4 * HA_STG * 2)

// tf32 out-gemm
#define KB 32
#define APAD 36
#define BPAD 136
#define ASZ (128 * APAD)
#define BSZ (KB * BPAD)
#define TSM_BYTES ((2 * (ASZ + BSZ) + 256) * 4)

// ---------------- scratch ----------------
__device__ float g_wkvf[2 * CC * CIN];
__device__ float g_bkv [2 * CC];
__device__ float g_wq1f[CC * CIN];
__device__ float g_wq2f[CC * CC];
__device__ float g_wk2f[CC * CC];
__device__ float g_bq1[CC], g_bq2[CC], g_bk2[CC];
__device__ __nv_bfloat16 g_val[(size_t)BB * CC * HW];
__device__ __nv_bfloat16 g_key[(size_t)BB * CC * HW];
__device__ __nv_bfloat16 g_qr [(size_t)BB * CC * HW];
__device__ float g_S[BB * CC * CC];
__device__ float g_Z[BB * CC];

// ---------------- helpers ----------------
__device__ __forceinline__ float to_tf32(float x) {
    uint32_t u;
    asm("cvt.rna.tf32.f32 %0, %1;" : "=r"(u) : "f"(x));
    return __uint_as_float(u);
}
__device__ __forceinline__ float4 rnd4(float4 v) {
    return make_float4(to_tf32(v.x), to_tf32(v.y), to_tf32(v.z), to_tf32(v.w));
}
__device__ __forceinline__ float4 ld4(const float* p) { return *(const float4*)p; }
__device__ __forceinline__ float4 ld4(const __nv_bfloat16* p) {
    uint2 u = *(const uint2*)p;
    __nv_bfloat162 lo = *reinterpret_cast<__nv_bfloat162*>(&u.x);
    __nv_bfloat162 hi = *reinterpret_cast<__nv_bfloat162*>(&u.y);
    float2 f0 = __bfloat1622float2(lo), f1 = __bfloat1622float2(hi);
    return make_float4(f0.x, f0.y, f1.x, f1.y);
}
__device__ __forceinline__ void st4h(__nv_bfloat16* p, float4 v) {
    __nv_bfloat162 lo = __floats2bfloat162_rn(v.x, v.y);
    __nv_bfloat162 hi = __floats2bfloat162_rn(v.z, v.w);
    uint2 u = { *(uint32_t*)&lo, *(uint32_t*)&hi };
    *(uint2*)p = u;
}
__device__ __forceinline__ void ldsm4(uint32_t* r, uint32_t a) {
    asm volatile("ldmatrix.sync.aligned.m8n8.x4.shared.b16 {%0,%1,%2,%3}, [%4];"
                 : "=r"(r[0]), "=r"(r[1]), "=r"(r[2]), "=r"(r[3]) : "r"(a));
}
__device__ __forceinline__ void ldsm4t(uint32_t* r, uint32_t a) {
    asm volatile("ldmatrix.sync.aligned.m8n8.x4.trans.shared.b16 {%0,%1,%2,%3}, [%4];"
                 : "=r"(r[0]), "=r"(r[1]), "=r"(r[2]), "=r"(r[3]) : "r"(a));
}
__device__ __forceinline__ void mma16(float* c, const uint32_t* a, const uint32_t* b) {
    asm volatile("mma.sync.aligned.m16n8k16.row.col.f32.bf16.bf16.f32 "
                 "{%0,%1,%2,%3}, {%4,%5,%6,%7}, {%8,%9}, {%0,%1,%2,%3};"
                 : "+f"(c[0]), "+f"(c[1]), "+f"(c[2]), "+f"(c[3])
                 : "r"(a[0]), "r"(a[1]), "r"(a[2]), "r"(a[3]), "r"(b[0]), "r"(b[1]));
}
__device__ __forceinline__ void mma8(float* c, uint32_t a0, uint32_t a1,
                                     uint32_t a2, uint32_t a3,
                                     uint32_t b0, uint32_t b1) {
    asm volatile(
        "mma.sync.aligned.m16n8k8.row.col.f32.tf32.tf32.f32 "
        "{%0,%1,%2,%3}, {%4,%5,%6,%7}, {%8,%9}, {%0,%1,%2,%3};"
        : "+f"(c[0]), "+f"(c[1]), "+f"(c[2]), "+f"(c[3])
        : "r"(a0), "r"(a1), "r"(a2), "r"(a3), "r"(b0), "r"(b1));
}
__device__ __forceinline__ float softplus_fast(float x) {
    return fmaxf(x, 0.f) + log1pf(__expf(-fabsf(x)));
}

// ---------------- merged BN fold ----------------
struct PrepEnt { const float *w, *g, *b, *m, *v; float *wf, *bf; int K; };
struct PrepAll { PrepEnt e[5]; };

__global__ void fold5(PrepAll a) {
    PrepEnt p = a.e[blockIdx.y];
    int o = blockIdx.x;
    float s = p.g[o] * rsqrtf(p.v[o] + 1e-5f);
    if (threadIdx.x == 0) p.bf[o] = p.b[o] - p.m[o] * s;
    for (int c = threadIdx.x; c < p.K; c += blockDim.x)
        p.wf[o * p.K + c] = p.w[o * p.K + c] * s;
}

// ---------------- smem fills ----------------
__device__ __forceinline__ void fillA_h(__nv_bfloat16* Ad, const float* Ab,
                                        int KTOT, int k0, int tid) {
#pragma unroll
    for (int i = 0; i < 4; i++) {
        int m = (tid >> 3) + 32 * i, kf = (tid & 7) * 4;
        float4 v = *(const float4*)(Ab + (size_t)m * KTOT + k0 + kf);
        st4h(Ad + m * KPAD + kf, v);
    }
}
__device__ __forceinline__ void fillB_h(__nv_bfloat16* Bd, const float* Xb,
                                        int k0, int tid) {
#pragma unroll
    for (int i = 0; i < 4; i++) {
        int k = (tid >> 5) + 8 * i, nf = (tid & 31) * 4;
        float4 v = *(const float4*)(Xb + (size_t)(k0 + k) * HW + nf);
        st4h(Bd + k * NPAD + nf, v);
    }
}

__device__ __forceinline__ void zero_acc(float acc[2][8][4]) {
#pragma unroll
    for (int i = 0; i < 2; i++)
#pragma unroll
        for (int j = 0; j < 8; j++)
#pragma unroll
            for (int l = 0; l < 4; l++) acc[i][j][l] = 0.f;
}

// ---------------- phase-1 mainloop (K=256 from gmem fp32) ----------------
__device__ __forceinline__ void mainloop1(float acc[2][8][4], __nv_bfloat16* hsm,
                                          uint32_t sbase, const float* Ab,
                                          const float* Xb, int tid, int wm, int wn,
                                          uint32_t aLane, uint32_t bLane) {
    __nv_bfloat16* As = hsm + AS_OFF;
    __nv_bfloat16* Bs = hsm + BS_OFF;
    fillA_h(As, Ab, CIN, 0, tid);
    fillB_h(Bs, Xb, 0, tid);
    __syncthreads();
    constexpr int NKB = CIN / 32;
    for (int kb = 0; kb < NKB; kb++) {
        if (kb + 1 < NKB) {
            fillA_h(As + ((kb + 1) & 1) * HA_STG, Ab, CIN, (kb + 1) * 32, tid);
            fillB_h(Bs + ((kb + 1) & 1) * HB_STG, Xb, (kb + 1) * 32, tid);
        }
        const uint32_t sA = sbase + (AS_OFF + (kb & 1) * HA_STG) * 2;
        const uint32_t sB = sbase + (BS_OFF + (kb & 1) * HB_STG) * 2;
#pragma unroll
        for (int kk = 0; kk < 2; kk++) {
            uint32_t a[2][4], bq[8][2];
#pragma unroll
            for (int mw = 0; mw < 2; mw++)
                ldsm4(a[mw], sA + ((wm * 32 + mw * 16) * KPAD) * 2 + kk * 32 + aLane);
#pragma unroll
            for (int ng = 0; ng < 4; ng++) {
                uint32_t r[4];
                ldsm4t(r, sB + (kk * 16 * NPAD + wn * 64 + ng * 16) * 2 + bLane);
                bq[2 * ng][0] = r[0]; bq[2 * ng][1] = r[1];
                bq[2 * ng + 1][0] = r[2]; bq[2 * ng + 1][1] = r[3];
            }
#pragma unroll
            for (int mw = 0; mw < 2; mw++)
#pragma unroll
                for (int nw = 0; nw < 8; nw++)
                    mma16(acc[mw][nw], a[mw], bq[nw]);
        }
        __syncthreads();
    }
}

// ---------------- phase-2 mainloop (K=128, smem resident, A2PAD stride) ----
__device__ __forceinline__ void mainloop2(float acc[2][8][4], uint32_t sbase,
                                          int wm, int wn, uint32_t aLane2,
                                          uint32_t bLane) {
    const uint32_t sA2 = sbase + A2_OFF * 2;
    const uint32_t sB2 = sbase + B2_OFF * 2;
#pragma unroll
    for (int kb = 0; kb < 4; kb++) {
#pragma unroll
        for (int kk = 0; kk < 2; kk++) {
            const int kofs = kb * 32 + kk * 16;
            uint32_t a[2][4], bq[8][2];
#pragma unroll
            for (int mw = 0; mw < 2; mw++)
                ldsm4(a[mw], sA2 + ((wm * 32 + mw * 16) * A2PAD + kofs) * 2 + aLane2);
#pragma unroll
            for (int ng = 0; ng < 4; ng++) {
                uint32_t r[4];
                ldsm4t(r, sB2 + ((size_t)kofs * NPAD + wn * 64 + ng * 16) * 2 + bLane);
                bq[2 * ng][0] = r[0]; bq[2 * ng][1] = r[1];
                bq[2 * ng + 1][0] = r[2]; bq[2 * ng + 1][1] = r[3];
            }
#pragma unroll
            for (int mw = 0; mw < 2; mw++)
#pragma unroll
                for (int nw = 0; nw < 8; nw++)
                    mma16(acc[mw][nw], a[mw], bq[nw]);
        }
    }
}

// ---------------- chain body ----------------
__device__ __forceinline__ void chain_body(__nv_bfloat16* hsm, uint32_t sbase,
                                           const float* W1, const float* b1,
                                           const float* W2, const float* b2,
                                           const float* Xb, __nv_bfloat16* Yout,
                                           int tid, int wm, int wn, int qid, int tq,
                                           uint32_t aLane, uint32_t bLane) {
    const int lane = tid & 31;
    const uint32_t aLane2 = ((lane & 15) * A2PAD + (lane >> 4) * 8) * 2;

    float acc[2][8][4];
    zero_acc(acc);
    mainloop1(acc, hsm, sbase, W1, Xb, tid, wm, wn, aLane, bLane);
    // mainloop1 ends with __syncthreads(): AS/BS are dead, safe to alias A2.

    // load W2 (128x128 fp32 -> bf16) into A2 (stride A2PAD)
    {
        __nv_bfloat16* A2s = hsm + A2_OFF;
#pragma unroll
        for (int t = 0; t < 16; t++) {
            int f = tid + t * 256;
            int m = f >> 5, k = (f & 31) * 4;
            st4h(A2s + (size_t)m * A2PAD + k, ld4(W2 + (size_t)m * CC + k));
        }
    }
    // relu(acc + b1) -> B2s [k=channel][n]
    {
        __nv_bfloat16* B2s = hsm + B2_OFF;
#pragma unroll
        for (int mw = 0; mw < 2; mw++) {
            const int r0 = wm * 32 + mw * 16 + qid;
            float bv0 = b1[r0], bv1 = b1[r0 + 8];
#pragma unroll
            for (int nw = 0; nw < 8; nw++) {
                const int col = wn * 64 + nw * 8 + tq * 2;
                __nv_bfloat162 p0 = __floats2bfloat162_rn(
                    fmaxf(acc[mw][nw][0] + bv0, 0.f), fmaxf(acc[mw][nw][1] + bv0, 0.f));
                __nv_bfloat162 p1 = __floats2bfloat162_rn(
                    fmaxf(acc[mw][nw][2] + bv1, 0.f), fmaxf(acc[mw][nw][3] + bv1, 0.f));
                *(__nv_bfloat162*)(B2s + (size_t)r0 * NPAD + col) = p0;
                *(__nv_bfloat162*)(B2s + (size_t)(r0 + 8) * NPAD + col) = p1;
            }
        }
    }
    __syncthreads();

    zero_acc(acc);
    mainloop2(acc, sbase, wm, wn, aLane2, bLane);

    // softplus(acc + b2) -> gmem
#pragma unroll
    for (int mw = 0; mw < 2; mw++) {
        const int r0 = wm * 32 + mw * 16 + qid;
        float bv0 = b2[r0], bv1 = b2[r0 + 8];
#pragma unroll
        for (int nw = 0; nw < 8; nw++) {
            const int col = wn * 64 + nw * 8 + tq * 2;
            __nv_bfloat162 p0 = __floats2bfloat162_rn(
                softplus_fast(acc[mw][nw][0] + bv0), softplus_fast(acc[mw][nw][1] + bv0));
            __nv_bfloat162 p1 = __floats2bfloat162_rn(
                softplus_fast(acc[mw][nw][2] + bv1), softplus_fast(acc[mw][nw][3] + bv1));
            *(__nv_bfloat162*)(Yout + (size_t)r0 * HW + col) = p0;
            *(__nv_bfloat162*)(Yout + (size_t)(r0 + 8) * HW + col) = p1;
        }
    }
}

// ---------------- source kernel: mt0 = kh->key chain, mt1 = value ----------
__global__ void __launch_bounds__(256, 2)
src_k(const float* __restrict__ Wkv, const float* __restrict__ bkv,
      const float* __restrict__ Wk2, const float* __restrict__ bk2,
      const float* __restrict__ X,
      __nv_bfloat16* __restrict__ val, __nv_bfloat16* __restrict__ key) {
    extern __shared__ __nv_bfloat16 hsm[];
    const int tid = threadIdx.x;
    const int b = blockIdx.y;
    const int mt = blockIdx.x & 1;
    const int n0 = (blockIdx.x >> 1) * 128;
    const int warp = tid >> 5, lane = tid & 31;
    const int wm = warp >> 1, wn = warp & 1;
    const int qid = lane >> 2, tq = lane & 3;
    const uint32_t sbase = (uint32_t)__cvta_generic_to_shared(hsm);
    const uint32_t aLane = ((lane & 15) * KPAD + (lane >> 4) * 8) * 2;
    const uint32_t bLane = ((lane & 15) * NPAD + (lane >> 4) * 8) * 2;
    const float* Xb = X + (size_t)b * CIN * HW + n0;

    if (mt == 1) {
        float acc[2][8][4];
        zero_acc(acc);
        mainloop1(acc, hsm, sbase, Wkv + (size_t)128 * CIN, Xb, tid, wm, wn, aLane, bLane);
        __nv_bfloat16* Yb = val + (size_t)b * CC * HW + n0;
        const float* bp = bkv + 128;
#pragma unroll
        for (int mw = 0; mw < 2; mw++) {
            const int r0 = wm * 32 + mw * 16 + qid;
            float bv0 = bp[r0], bv1 = bp[r0 + 8];
#pragma unroll
            for (int nw = 0; nw < 8; nw++) {
                const int col = wn * 64 + nw * 8 + tq * 2;
                __nv_bfloat162 p0 = __floats2bfloat162_rn(
                    fmaxf(acc[mw][nw][0] + bv0, 0.f), fmaxf(acc[mw][nw][1] + bv0, 0.f));
                __nv_bfloat162 p1 = __floats2bfloat162_rn(
                    fmaxf(acc[mw][nw][2] + bv1, 0.f), fmaxf(acc[mw][nw][3] + bv1, 0.f));
                *(__nv_bfloat162*)(Yb + (size_t)r0 * HW + col) = p0;
                *(__nv_bfloat162*)(Yb + (size_t)(r0 + 8) * HW + col) = p1;
            }
        }
    } else {
        chain_body(hsm, sbase, Wkv, bkv, Wk2, bk2, Xb,
                   key + (size_t)b * CC * HW + n0, tid, wm, wn, qid, tq, aLane, bLane);
    }
}

// ---------------- target kernel: qh->qr chain ----------------
__global__ void __launch_bounds__(256, 2)
tgt_k(const float* __restrict__ Wq1, const float* __restrict__ bq1,
      const float* __restrict__ Wq2, const float* __restrict__ bq2,
      const float* __restrict__ X, __nv_bfloat16* __restrict__ qr) {
    extern __shared__ __nv_bfloat16 hsm[];
    const int tid = threadIdx.x;
    const int b = blockIdx.y;
    const int n0 = blockIdx.x * 128;
    const int warp = tid >> 5, lane = tid & 31;
    const int wm = warp >> 1, wn = warp & 1;
    const int qid = lane >> 2, tq = lane & 3;
    const uint32_t sbase = (uint32_t)__cvta_generic_to_shared(hsm);
    const uint32_t aLane = ((lane & 15) * KPAD + (lane >> 4) * 8) * 2;
    const uint32_t bLane = ((lane & 15) * NPAD + (lane >> 4) * 8) * 2;
    chain_body(hsm, sbase, Wq1, bq1, Wq2, bq2, X + (size_t)b * CIN * HW + n0,
               qr + (size_t)b * CC * HW + n0, tid, wm, wn, qid, tq, aLane, bLane);
}

// ============================================================================
// S[b,c,d] += sum_n V[b,c,n] K[b,d,n]  + fused Z
// ============================================================================
__global__ void __launch_bounds__(256, 2)
s_bf(const __nv_bfloat16* __restrict__ V, const __nv_bfloat16* __restrict__ Kt,
     float* __restrict__ S, float* __restrict__ Z) {
    extern __shared__ __nv_bfloat16 hsm[];
    __nv_bfloat16* As = hsm;
    __nv_bfloat16* Bs = hsm + 2 * HA_STG;
    const int tid = threadIdx.x;
    const int b = blockIdx.y;
    const int n0 = blockIdx.x * SCHUNK;
    const int warp = tid >> 5, lane = tid & 31;
    const int wm = warp >> 1, wn = warp & 1;
    const int qid = lane >> 2, tq = lane & 3;
    const __nv_bfloat16* Vb = V + (size_t)b * CC * HW + n0;
    const __nv_bfloat16* Kb = Kt + (size_t)b * CC * HW + n0;
    constexpr int NKB = SCHUNK / 32;

    float acc[2][8][4];
    zero_acc(acc);
    float zp[2] = {0.f, 0.f};
    const uint32_t sbase = (uint32_t)__cvta_generic_to_shared(hsm);
    const uint32_t lLane = ((lane & 15) * KPAD + (lane >> 4) * 8) * 2;

    auto fill = [&](int stage, int k0) {
        __nv_bfloat16* Ad = As + stage * HA_STG;
        __nv_bfloat16* Bd = Bs + stage * HA_STG;
#pragma unroll
        for (int t = 0; t < 2; t++) {
            int f = tid + 256 * t;
            int row = f >> 2, kf = (f & 3) * 8;
            *(uint4*)(Ad + row * KPAD + kf) = *(const uint4*)(Vb + (size_t)row * HW + k0 + kf);
            uint4 kv4 = *(const uint4*)(Kb + (size_t)row * HW + k0 + kf);
            *(uint4*)(Bd + row * KPAD + kf) = kv4;
            const __nv_bfloat162* h = (const __nv_bfloat162*)&kv4;
#pragma unroll
            for (int j = 0; j < 4; j++) {
                float2 f2 = __bfloat1622float2(h[j]);
                zp[t] += f2.x + f2.y;
            }
        }
    };

    fill(0, 0);
    __syncthreads();

    for (int kb = 0; kb < NKB; kb++) {
        if (kb + 1 < NKB) fill((kb + 1) & 1, (kb + 1) * 32);
        const uint32_t sA = sbase + ((kb & 1) * HA_STG) * 2;
        const uint32_t sB = sbase + (2 * HA_STG + (kb & 1) * HA_STG) * 2;
#pragma unroll
        for (int kk = 0; kk < 2; kk++) {
            uint32_t a[2][4], bq[8][2];
#pragma unroll
            for (int mw = 0; mw < 2; mw++)
                ldsm4(a[mw], sA + ((wm * 32 + mw * 16) * KPAD) * 2 + kk * 32 + lLane);
#pragma unroll
            for (int ng = 0; ng < 4; ng++) {
                uint32_t r[4];
                ldsm4(r, sB + ((wn * 64 + ng * 16) * KPAD) * 2 + kk * 32 + lLane);
                bq[2 * ng][0] = r[0]; bq[2 * ng][1] = r[2];
                bq[2 * ng + 1][0] = r[1]; bq[2 * ng + 1][1] = r[3];
            }
#pragma unroll
            for (int mw = 0; mw < 2; mw++)
#pragma unroll
                for (int nw = 0; nw < 8; nw++)
                    mma16(acc[mw][nw], a[mw], bq[nw]);
        }
        __syncthreads();
    }

#pragma unroll
    for (int o = 1; o < 4; o <<= 1) {
        zp[0] += __shfl_xor_sync(0xffffffff, zp[0], o);
        zp[1] += __shfl_xor_sync(0xffffffff, zp[1], o);
    }
    if ((lane & 3) == 0) {
        atomicAdd(&Z[b * CC + (tid >> 2)], zp[0]);
        atomicAdd(&Z[b * CC + 64 + (tid >> 2)], zp[1]);
    }

    float* Sb = S + (size_t)b * CC * CC;
#pragma unroll
    for (int mw = 0; mw < 2; mw++) {
        const int r0 = wm * 32 + mw * 16 + qid;
#pragma unroll
        for (int nw = 0; nw < 8; nw++) {
            const int col = wn * 64 + nw * 8 + tq * 2;
            atomicAdd(&Sb[(size_t)r0 * CC + col],           acc[mw][nw][0]);
            atomicAdd(&Sb[(size_t)r0 * CC + col + 1],       acc[mw][nw][1]);
            atomicAdd(&Sb[(size_t)(r0 + 8) * CC + col],     acc[mw][nw][2]);
            atomicAdd(&Sb[(size_t)(r0 + 8) * CC + col + 1], acc[mw][nw][3]);
        }
    }
}

// ============================================================================
// out GEMM (tf32, den fused)
// ============================================================================
__global__ void __launch_bounds__(256)
out_tc(const float* __restrict__ Sg, const __nv_bfloat16* __restrict__ Q,
       const float* __restrict__ Zvec, float* __restrict__ Y) {
    extern __shared__ float smd[];
    float* As = smd;
    float* Bs = smd + 2 * ASZ;
    float* den_s = smd + 2 * (ASZ + BSZ);
    float* Zs = den_s + 128;
    const int tid = threadIdx.x;
    const int b = blockIdx.y;
    const int n0 = blockIdx.x * 128;
    const int warp = tid >> 5, lane = tid & 31;
    const int wm = warp >> 1, wn = warp & 1;
    const int qid = lane >> 2, tq = lane & 3;
    const float* Ab = Sg + (size_t)b * CC * CC;
    const __nv_bfloat16* Xb = Q + (size_t)b * CC * HW + n0;
    constexpr int NKB = CC / KB;

    float acc[2][8][4];
    zero_acc(acc);
    const int am = tid >> 3, ak = (tid & 7) * 4;
    const int bk = tid >> 5, bn = (tid & 31) * 4;
    float dreg[4] = {0.f, 0.f, 0.f, 0.f};

    if (tid < 128) { Zs[tid] = Zvec[b * CC + tid]; den_s[tid] = 0.f; }
    __syncthreads();

    {
#pragma unroll
        for (int i = 0; i < 4; i++) {
            int m = am + i * 32;
            *(float4*)(As + m * APAD + ak) = rnd4(ld4(Ab + (size_t)m * CC + ak));
        }
#pragma unroll
        for (int i = 0; i < 4; i++) {
            int k = bk + i * 8;
            float4 v = ld4(Xb + (size_t)k * HW + bn);
            float z = Zs[k];
            dreg[0] = fmaf(z, v.x, dreg[0]); dreg[1] = fmaf(z, v.y, dreg[1]);
            dreg[2] = fmaf(z, v.z, dreg[2]); dreg[3] = fmaf(z, v.w, dreg[3]);
            *(float4*)(Bs + k * BPAD + bn) = v;
        }
    }
    __syncthreads();

    for (int kb = 0; kb < NKB; kb++) {
        float4 ra[4], rb[4];
        if (kb + 1 < NKB) {
            const int k0 = (kb + 1) * KB;
#pragma unroll
            for (int i = 0; i < 4; i++)
                ra[i] = ld4(Ab + (size_t)(am + i * 32) * CC + k0 + ak);
#pragma unroll
            for (int i = 0; i < 4; i++) {
                rb[i] = ld4(Xb + (size_t)(k0 + bk + i * 8) * HW + bn);
                float z = Zs[k0 + bk + i * 8];
                dreg[0] = fmaf(z, rb[i].x, dreg[0]); dreg[1] = fmaf(z, rb[i].y, dreg[1]);
                dreg[2] = fmaf(z, rb[i].z, dreg[2]); dreg[3] = fmaf(z, rb[i].w, dreg[3]);
            }
        }
        {
            float* Ad = As + (kb & 1) * ASZ;
            float* Bd = Bs + (kb & 1) * BSZ;
#pragma unroll
            for (int kk = 0; kk < 4; kk++) {
                uint32_t a[2][4], bf[8][2];
#pragma unroll
                for (int mw = 0; mw < 2; mw++) {
                    const float* ap = Ad + (wm * 32 + mw * 16 + qid) * APAD + kk * 8 + tq;
                    a[mw][0] = __float_as_uint(ap[0]);
                    a[mw][1] = __float_as_uint(ap[8 * APAD]);
                    a[mw][2] = __float_as_uint(ap[4]);
                    a[mw][3] = __float_as_uint(ap[8 * APAD + 4]);
                }
#pragma unroll
                for (int nw = 0; nw < 8; nw++) {
                    const float* bp = Bd + (kk * 8 + tq) * BPAD + wn * 64 + nw * 8 + qid;
                    bf[nw][0] = __float_as_uint(bp[0]);
                    bf[nw][1] = __float_as_uint(bp[4 * BPAD]);
                }
#pragma unroll
                for (int mw = 0; mw < 2; mw++)
#pragma unroll
                    for (int nw = 0; nw < 8; nw++)
                        mma8(acc[mw][nw], a[mw][0], a[mw][1], a[mw][2], a[mw][3],
                             bf[nw][0], bf[nw][1]);
            }
        }
        if (kb + 1 < NKB) {
            float* Ad = As + ((kb + 1) & 1) * ASZ;
            float* Bd = Bs + ((kb + 1) & 1) * BSZ;
#pragma unroll
            for (int i = 0; i < 4; i++)
                *(float4*)(Ad + (am + i * 32) * APAD + ak) = rnd4(ra[i]);
#pragma unroll
            for (int i = 0; i < 4; i++)
                *(float4*)(Bd + (bk + i * 8) * BPAD + bn) = rb[i];
        }
        __syncthreads();
    }

#pragma unroll
    for (int j = 0; j < 4; j++) atomicAdd(&den_s[bn + j], dreg[j]);
    __syncthreads();

    float* Yb = Y + (size_t)b * CC * HW + n0;
#pragma unroll
    for (int mw = 0; mw < 2; mw++) {
        const int r0 = wm * 32 + mw * 16 + qid;
#pragma unroll
        for (int nw = 0; nw < 8; nw++) {
            const int col = wn * 64 + nw * 8 + tq * 2;
            float i0 = 1.f / fmaxf(den_s[col], 1e-12f);
            float i1 = 1.f / fmaxf(den_s[col + 1], 1e-12f);
            float2 p0 = { acc[mw][nw][0] * i0, acc[mw][nw][1] * i1 };
            float2 p1 = { acc[mw][nw][2] * i0, acc[mw][nw][3] * i1 };
            *(float2*)(Yb + (size_t)r0 * HW + col) = p0;
            *(float2*)(Yb + (size_t)(r0 + 8) * HW + col) = p1;
        }
    }
}

// ---------------- launch ----------------
extern "C" void kernel_launch(void* const* d_in, const int* in_sizes, int n_in,
                              void* d_out, int out_size) {
    const float* target = (const float*)d_in[0];
    const float* source = (const float*)d_in[1];
    const float* q_w1 = (const float*)d_in[2];
    const float* q_w2 = (const float*)d_in[3];
    const float* k_w1 = (const float*)d_in[4];
    const float* k_w2 = (const float*)d_in[5];
    const float* v_w  = (const float*)d_in[6];

    float *wkvf, *bkv, *wq1f, *wq2f, *wk2f, *bq1, *bq2, *bk2, *S, *Z;
    __nv_bfloat16 *val, *key, *qr;
    cudaGetSymbolAddress((void**)&wkvf, g_wkvf);
    cudaGetSymbolAddress((void**)&bkv,  g_bkv);
    cudaGetSymbolAddress((void**)&wq1f, g_wq1f);
    cudaGetSymbolAddress((void**)&wq2f, g_wq2f);
    cudaGetSymbolAddress((void**)&wk2f, g_wk2f);
    cudaGetSymbolAddress((void**)&bq1, g_bq1);
    cudaGetSymbolAddress((void**)&bq2, g_bq2);
    cudaGetSymbolAddress((void**)&bk2, g_bk2);
    cudaGetSymbolAddress((void**)&val, g_val);
    cudaGetSymbolAddress((void**)&key, g_key);
    cudaGetSymbolAddress((void**)&qr,  g_qr);
    cudaGetSymbolAddress((void**)&S,   g_S);
    cudaGetSymbolAddress((void**)&Z,   g_Z);

    cudaFuncSetAttribute(src_k, cudaFuncAttributeMaxDynamicSharedMemorySize, CHAIN_SM_BYTES);
    cudaFuncSetAttribute(tgt_k, cudaFuncAttributeMaxDynamicSharedMemorySize, CHAIN_SM_BYTES);
    cudaFuncSetAttribute(s_bf,  cudaFuncAttributeMaxDynamicSharedMemorySize, SSM_BYTES);
    cudaFuncSetAttribute(out_tc, cudaFuncAttributeMaxDynamicSharedMemorySize, TSM_BYTES);

    PrepAll pa;
    pa.e[0] = { k_w1, (const float*)d_in[15], (const float*)d_in[16], (const float*)d_in[17], (const float*)d_in[18], wkvf, bkv, CIN };
    pa.e[1] = { v_w,  (const float*)d_in[23], (const float*)d_in[24], (const float*)d_in[25], (const float*)d_in[26], wkvf + CC * CIN, bkv + CC, CIN };
    pa.e[2] = { q_w1, (const float*)d_in[7],  (const float*)d_in[8],  (const float*)d_in[9],  (const float*)d_in[10], wq1f, bq1, CIN };
    pa.e[3] = { q_w2, (const float*)d_in[11], (const float*)d_in[12], (const float*)d_in[13], (const float*)d_in[14], wq2f, bq2, CC };
    pa.e[4] = { k_w2, (const float*)d_in[19], (const float*)d_in[20], (const float*)d_in[21], (const float*)d_in[22], wk2f, bk2, CC };
    fold5<<<dim3(CC, 5), 256>>>(pa);

    cudaMemsetAsync(S, 0, BB * CC * CC * sizeof(float));
    cudaMemsetAsync(Z, 0, BB * CC * sizeof(float));

    // source: value + (kh -> key) chain
    src_k<<<dim3(HW / 128 * 2, BB), 256, CHAIN_SM_BYTES>>>(wkvf, bkv, wk2f, bk2, source, val, key);
    // target: qh -> qr chain
    tgt_k<<<dim3(HW / 128, BB), 256, CHAIN_SM_BYTES>>>(wq1f, bq1, wq2f, bq2, target, qr);
    // S = V K^T + fused Z
    s_bf<<<dim3(NSPLIT, BB), 256, SSM_BYTES>>>(val, key, S, Z);
    // out
    out_tc<<<dim3(HW / 128, BB), 256, TSM_BYTES>>>(S, qr, Z, (float*)d_out);
}

// round 10
// speedup vs baseline: 3.8383x; 1.0379x over previous
#include <cuda_runtime.h>
#include <cuda_bf16.h>
#include <math.h>
#include <stdint.h>

#define BB 8
#define CIN 256
#define CC 128
#define HW 16384
#define NSPLIT 32
#define SCHUNK 512

#define KPAD 40
#define NPAD 136
#define A2PAD 136
#define HA_STG (128 * KPAD)      // 5120 elems
#define HB_STG (32 * NPAD)       // 4352 elems

// chain kernel smem layout (bf16 elems)
#define AS_OFF 0
#define BS_OFF (AS_OFF + 2 * HA_STG)          // 10240
#define P1_ELEMS (BS_OFF + 2 * HB_STG)        // 18944
#define A2_OFF 0
#define B2_OFF P1_ELEMS                        // 18944
#define CHAIN_ELEMS (B2_OFF + 128 * NPAD)      // 36352
#define CHAIN_SM_BYTES (CHAIN_ELEMS * 2)       // 72704

// s_bf: 4-stage cp.async pipeline
#define SSTAGES 4
#define SSTG_ELEMS (2 * HA_STG)                // V + K per stage
#define SSM_BYTES (SSTAGES * SSTG_ELEMS * 2)   // 81920

// out_bf smem layout (bf16 elems)
#define OA_OFF 0
#define OB_OFF (128 * A2PAD)                   // 17408
#define O_ELEMS (OB_OFF + 128 * NPAD)          // 34816
#define OSM_BYTES (O_ELEMS * 2 + 256 * 4)      // 70656

// ---------------- scratch ----------------
__device__ float g_wkvf[2 * CC * CIN];
__device__ float g_bkv [2 * CC];
__device__ float g_wq1f[CC * CIN];
__device__ float g_wq2f[CC * CC];
__device__ float g_wk2f[CC * CC];
__device__ float g_bq1[CC], g_bq2[CC], g_bk2[CC];
__device__ __nv_bfloat16 g_val[(size_t)BB * CC * HW];
__device__ __nv_bfloat16 g_key[(size_t)BB * CC * HW];
__device__ __nv_bfloat16 g_qr [(size_t)BB * CC * HW];
__device__ float g_S[BB * CC * CC];
__device__ __nv_bfloat16 g_Sbf[BB * CC * CC];
__device__ float g_Z[BB * CC];

// ---------------- helpers ----------------
__device__ __forceinline__ float4 ld4(const float* p) { return *(const float4*)p; }
__device__ __forceinline__ float4 ld4(const __nv_bfloat16* p) {
    uint2 u = *(const uint2*)p;
    __nv_bfloat162 lo = *reinterpret_cast<__nv_bfloat162*>(&u.x);
    __nv_bfloat162 hi = *reinterpret_cast<__nv_bfloat162*>(&u.y);
    float2 f0 = __bfloat1622float2(lo), f1 = __bfloat1622float2(hi);
    return make_float4(f0.x, f0.y, f1.x, f1.y);
}
__device__ __forceinline__ void st4h(__nv_bfloat16* p, float4 v) {
    __nv_bfloat162 lo = __floats2bfloat162_rn(v.x, v.y);
    __nv_bfloat162 hi = __floats2bfloat162_rn(v.z, v.w);
    uint2 u = { *(uint32_t*)&lo, *(uint32_t*)&hi };
    *(uint2*)p = u;
}
__device__ __forceinline__ void ldsm4(uint32_t* r, uint32_t a) {
    asm volatile("ldmatrix.sync.aligned.m8n8.x4.shared.b16 {%0,%1,%2,%3}, [%4];"
                 : "=r"(r[0]), "=r"(r[1]), "=r"(r[2]), "=r"(r[3]) : "r"(a));
}
__device__ __forceinline__ void ldsm4t(uint32_t* r, uint32_t a) {
    asm volatile("ldmatrix.sync.aligned.m8n8.x4.trans.shared.b16 {%0,%1,%2,%3}, [%4];"
                 : "=r"(r[0]), "=r"(r[1]), "=r"(r[2]), "=r"(r[3]) : "r"(a));
}
__device__ __forceinline__ void mma16(float* c, const uint32_t* a, const uint32_t* b) {
    asm volatile("mma.sync.aligned.m16n8k16.row.col.f32.bf16.bf16.f32 "
                 "{%0,%1,%2,%3}, {%4,%5,%6,%7}, {%8,%9}, {%0,%1,%2,%3};"
                 : "+f"(c[0]), "+f"(c[1]), "+f"(c[2]), "+f"(c[3])
                 : "r"(a[0]), "r"(a[1]), "r"(a[2]), "r"(a[3]), "r"(b[0]), "r"(b[1]));
}
__device__ __forceinline__ void cpa16(uint32_t dst, const void* src) {
    asm volatile("cp.async.cg.shared.global [%0], [%1], 16;" :: "r"(dst), "l"(src));
}
#define CPA_COMMIT() asm volatile("cp.async.commit_group;" ::: "memory")
__device__ __forceinline__ float softplus_fast(float x) {
    return fmaxf(x, 0.f) + log1pf(__expf(-fabsf(x)));
}

// ---------------- merged BN fold ----------------
struct PrepEnt { const float *w, *g, *b, *m, *v; float *wf, *bf; int K; };
struct PrepAll { PrepEnt e[5]; };

__global__ void fold5(PrepAll a) {
    PrepEnt p = a.e[blockIdx.y];
    int o = blockIdx.x;
    float s = p.g[o] * rsqrtf(p.v[o] + 1e-5f);
    if (threadIdx.x == 0) p.bf[o] = p.b[o] - p.m[o] * s;
    for (int c = threadIdx.x; c < p.K; c += blockDim.x)
        p.wf[o * p.K + c] = p.w[o * p.K + c] * s;
}

// ---------------- S fp32 -> bf16 ----------------
__global__ void s2bf(const float* __restrict__ S, __nv_bfloat16* __restrict__ Sb) {
    int i = (blockIdx.x * 256 + threadIdx.x) * 4;
    float4 v = *(const float4*)(S + i);
    st4h(Sb + i, v);
}

// ---------------- smem fills (chain) ----------------
__device__ __forceinline__ void fillA_h(__nv_bfloat16* Ad, const float* Ab,
                                        int KTOT, int k0, int tid) {
#pragma unroll
    for (int i = 0; i < 4; i++) {
        int m = (tid >> 3) + 32 * i, kf = (tid & 7) * 4;
        float4 v = *(const float4*)(Ab + (size_t)m * KTOT + k0 + kf);
        st4h(Ad + m * KPAD + kf, v);
    }
}
__device__ __forceinline__ void fillB_h(__nv_bfloat16* Bd, const float* Xb,
                                        int k0, int tid) {
#pragma unroll
    for (int i = 0; i < 4; i++) {
        int k = (tid >> 5) + 8 * i, nf = (tid & 31) * 4;
        float4 v = *(const float4*)(Xb + (size_t)(k0 + k) * HW + nf);
        st4h(Bd + k * NPAD + nf, v);
    }
}

__device__ __forceinline__ void zero_acc(float acc[2][8][4]) {
#pragma unroll
    for (int i = 0; i < 2; i++)
#pragma unroll
        for (int j = 0; j < 8; j++)
#pragma unroll
            for (int l = 0; l < 4; l++) acc[i][j][l] = 0.f;
}

// ---------------- phase-1 mainloop (K=256 from gmem fp32) ----------------
__device__ __forceinline__ void mainloop1(float acc[2][8][4], __nv_bfloat16* hsm,
                                          uint32_t sbase, const float* Ab,
                                          const float* Xb, int tid, int wm, int wn,
                                          uint32_t aLane, uint32_t bLane) {
    __nv_bfloat16* As = hsm + AS_OFF;
    __nv_bfloat16* Bs = hsm + BS_OFF;
    fillA_h(As, Ab, CIN, 0, tid);
    fillB_h(Bs, Xb, 0, tid);
    __syncthreads();
    constexpr int NKB = CIN / 32;
    for (int kb = 0; kb < NKB; kb++) {
        if (kb + 1 < NKB) {
            fillA_h(As + ((kb + 1) & 1) * HA_STG, Ab, CIN, (kb + 1) * 32, tid);
            fillB_h(Bs + ((kb + 1) & 1) * HB_STG, Xb, (kb + 1) * 32, tid);
        }
        const uint32_t sA = sbase + (AS_OFF + (kb & 1) * HA_STG) * 2;
        const uint32_t sB = sbase + (BS_OFF + (kb & 1) * HB_STG) * 2;
#pragma unroll
        for (int kk = 0; kk < 2; kk++) {
            uint32_t a[2][4], bq[8][2];
#pragma unroll
            for (int mw = 0; mw < 2; mw++)
                ldsm4(a[mw], sA + ((wm * 32 + mw * 16) * KPAD) * 2 + kk * 32 + aLane);
#pragma unroll
            for (int ng = 0; ng < 4; ng++) {
                uint32_t r[4];
                ldsm4t(r, sB + (kk * 16 * NPAD + wn * 64 + ng * 16) * 2 + bLane);
                bq[2 * ng][0] = r[0]; bq[2 * ng][1] = r[1];
                bq[2 * ng + 1][0] = r[2]; bq[2 * ng + 1][1] = r[3];
            }
#pragma unroll
            for (int mw = 0; mw < 2; mw++)
#pragma unroll
                for (int nw = 0; nw < 8; nw++)
                    mma16(acc[mw][nw], a[mw], bq[nw]);
        }
        __syncthreads();
    }
}

// ---------------- smem-resident K=128 mainloop (A stride A2PAD, B stride NPAD)
__device__ __forceinline__ void mainloop2p(float acc[2][8][4], uint32_t sbase,
                                           uint32_t a_off_b, uint32_t b_off_b,
                                           int wm, int wn, uint32_t aLane2,
                                           uint32_t bLane) {
    const uint32_t sA2 = sbase + a_off_b;
    const uint32_t sB2 = sbase + b_off_b;
#pragma unroll
    for (int kb = 0; kb < 4; kb++) {
#pragma unroll
        for (int kk = 0; kk < 2; kk++) {
            const int kofs = kb * 32 + kk * 16;
            uint32_t a[2][4], bq[8][2];
#pragma unroll
            for (int mw = 0; mw < 2; mw++)
                ldsm4(a[mw], sA2 + ((wm * 32 + mw * 16) * A2PAD + kofs) * 2 + aLane2);
#pragma unroll
            for (int ng = 0; ng < 4; ng++) {
                uint32_t r[4];
                ldsm4t(r, sB2 + ((size_t)kofs * NPAD + wn * 64 + ng * 16) * 2 + bLane);
                bq[2 * ng][0] = r[0]; bq[2 * ng][1] = r[1];
                bq[2 * ng + 1][0] = r[2]; bq[2 * ng + 1][1] = r[3];
            }
#pragma unroll
            for (int mw = 0; mw < 2; mw++)
#pragma unroll
                for (int nw = 0; nw < 8; nw++)
                    mma16(acc[mw][nw], a[mw], bq[nw]);
        }
    }
}

// ---------------- chain body ----------------
__device__ __forceinline__ void chain_body(__nv_bfloat16* hsm, uint32_t sbase,
                                           const float* W1, const float* b1,
                                           const float* W2, const float* b2,
                                           const float* Xb, __nv_bfloat16* Yout,
                                           int tid, int wm, int wn, int qid, int tq,
                                           uint32_t aLane, uint32_t bLane) {
    const int lane = tid & 31;
    const uint32_t aLane2 = ((lane & 15) * A2PAD + (lane >> 4) * 8) * 2;

    float acc[2][8][4];
    zero_acc(acc);
    mainloop1(acc, hsm, sbase, W1, Xb, tid, wm, wn, aLane, bLane);
    // mainloop1 ends with __syncthreads(): AS/BS dead, safe to alias A2.

    {
        __nv_bfloat16* A2s = hsm + A2_OFF;
#pragma unroll
        for (int t = 0; t < 16; t++) {
            int f = tid + t * 256;
            int m = f >> 5, k = (f & 31) * 4;
            st4h(A2s + (size_t)m * A2PAD + k, ld4(W2 + (size_t)m * CC + k));
        }
    }
    {
        __nv_bfloat16* B2s = hsm + B2_OFF;
#pragma unroll
        for (int mw = 0; mw < 2; mw++) {
            const int r0 = wm * 32 + mw * 16 + qid;
            float bv0 = b1[r0], bv1 = b1[r0 + 8];
#pragma unroll
            for (int nw = 0; nw < 8; nw++) {
                const int col = wn * 64 + nw * 8 + tq * 2;
                __nv_bfloat162 p0 = __floats2bfloat162_rn(
                    fmaxf(acc[mw][nw][0] + bv0, 0.f), fmaxf(acc[mw][nw][1] + bv0, 0.f));
                __nv_bfloat162 p1 = __floats2bfloat162_rn(
                    fmaxf(acc[mw][nw][2] + bv1, 0.f), fmaxf(acc[mw][nw][3] + bv1, 0.f));
                *(__nv_bfloat162*)(B2s + (size_t)r0 * NPAD + col) = p0;
                *(__nv_bfloat162*)(B2s + (size_t)(r0 + 8) * NPAD + col) = p1;
            }
        }
    }
    __syncthreads();

    zero_acc(acc);
    mainloop2p(acc, sbase, A2_OFF * 2, B2_OFF * 2, wm, wn, aLane2, bLane);

#pragma unroll
    for (int mw = 0; mw < 2; mw++) {
        const int r0 = wm * 32 + mw * 16 + qid;
        float bv0 = b2[r0], bv1 = b2[r0 + 8];
#pragma unroll
        for (int nw = 0; nw < 8; nw++) {
            const int col = wn * 64 + nw * 8 + tq * 2;
            __nv_bfloat162 p0 = __floats2bfloat162_rn(
                softplus_fast(acc[mw][nw][0] + bv0), softplus_fast(acc[mw][nw][1] + bv0));
            __nv_bfloat162 p1 = __floats2bfloat162_rn(
                softplus_fast(acc[mw][nw][2] + bv1), softplus_fast(acc[mw][nw][3] + bv1));
            *(__nv_bfloat162*)(Yout + (size_t)r0 * HW + col) = p0;
            *(__nv_bfloat162*)(Yout + (size_t)(r0 + 8) * HW + col) = p1;
        }
    }
}

// ---------------- source kernel: mt0 = kh->key chain, mt1 = value ----------
__global__ void __launch_bounds__(256, 2)
src_k(const float* __restrict__ Wkv, const float* __restrict__ bkv,
      const float* __restrict__ Wk2, const float* __restrict__ bk2,
      const float* __restrict__ X,
      __nv_bfloat16* __restrict__ val, __nv_bfloat16* __restrict__ key) {
    extern __shared__ __nv_bfloat16 hsm[];
    const int tid = threadIdx.x;
    const int b = blockIdx.y;
    const int mt = blockIdx.x & 1;
    const int n0 = (blockIdx.x >> 1) * 128;
    const int warp = tid >> 5, lane = tid & 31;
    const int wm = warp >> 1, wn = warp & 1;
    const int qid = lane >> 2, tq = lane & 3;
    const uint32_t sbase = (uint32_t)__cvta_generic_to_shared(hsm);
    const uint32_t aLane = ((lane & 15) * KPAD + (lane >> 4) * 8) * 2;
    const uint32_t bLane = ((lane & 15) * NPAD + (lane >> 4) * 8) * 2;
    const float* Xb = X + (size_t)b * CIN * HW + n0;

    if (mt == 1) {
        float acc[2][8][4];
        zero_acc(acc);
        mainloop1(acc, hsm, sbase, Wkv + (size_t)128 * CIN, Xb, tid, wm, wn, aLane, bLane);
        __nv_bfloat16* Yb = val + (size_t)b * CC * HW + n0;
        const float* bp = bkv + 128;
#pragma unroll
        for (int mw = 0; mw < 2; mw++) {
            const int r0 = wm * 32 + mw * 16 + qid;
            float bv0 = bp[r0], bv1 = bp[r0 + 8];
#pragma unroll
            for (int nw = 0; nw < 8; nw++) {
                const int col = wn * 64 + nw * 8 + tq * 2;
                __nv_bfloat162 p0 = __floats2bfloat162_rn(
                    fmaxf(acc[mw][nw][0] + bv0, 0.f), fmaxf(acc[mw][nw][1] + bv0, 0.f));
                __nv_bfloat162 p1 = __floats2bfloat162_rn(
                    fmaxf(acc[mw][nw][2] + bv1, 0.f), fmaxf(acc[mw][nw][3] + bv1, 0.f));
                *(__nv_bfloat162*)(Yb + (size_t)r0 * HW + col) = p0;
                *(__nv_bfloat162*)(Yb + (size_t)(r0 + 8) * HW + col) = p1;
            }
        }
    } else {
        chain_body(hsm, sbase, Wkv, bkv, Wk2, bk2, Xb,
                   key + (size_t)b * CC * HW + n0, tid, wm, wn, qid, tq, aLane, bLane);
    }
}

// ---------------- target kernel: qh->qr chain ----------------
__global__ void __launch_bounds__(256, 2)
tgt_k(const float* __restrict__ Wq1, const float* __restrict__ bq1,
      const float* __restrict__ Wq2, const float* __restrict__ bq2,
      const float* __restrict__ X, __nv_bfloat16* __restrict__ qr) {
    extern __shared__ __nv_bfloat16 hsm[];
    const int tid = threadIdx.x;
    const int b = blockIdx.y;
    const int n0 = blockIdx.x * 128;
    const int warp = tid >> 5, lane = tid & 31;
    const int wm = warp >> 1, wn = warp & 1;
    const int qid = lane >> 2, tq = lane & 3;
    const uint32_t sbase = (uint32_t)__cvta_generic_to_shared(hsm);
    const uint32_t aLane = ((lane & 15) * KPAD + (lane >> 4) * 8) * 2;
    const uint32_t bLane = ((lane & 15) * NPAD + (lane >> 4) * 8) * 2;
    chain_body(hsm, sbase, Wq1, bq1, Wq2, bq2, X + (size_t)b * CIN * HW + n0,
               qr + (size_t)b * CC * HW + n0, tid, wm, wn, qid, tq, aLane, bLane);
}

// ============================================================================
// S[b,c,d] += sum_n V K^T (+ fused Z), 4-stage cp.async pipeline
// ============================================================================
__global__ void __launch_bounds__(256, 2)
s_bf(const __nv_bfloat16* __restrict__ V, const __nv_bfloat16* __restrict__ Kt,
     float* __restrict__ S, float* __restrict__ Z) {
    extern __shared__ __nv_bfloat16 hsm[];
    const int tid = threadIdx.x;
    const int b = blockIdx.y;
    const int n0 = blockIdx.x * SCHUNK;
    const int warp = tid >> 5, lane = tid & 31;
    const int wm = warp >> 1, wn = warp & 1;
    const int qid = lane >> 2, tq = lane & 3;
    const __nv_bfloat16* Vb = V + (size_t)b * CC * HW + n0;
    const __nv_bfloat16* Kb = Kt + (size_t)b * CC * HW + n0;
    constexpr int NKB = SCHUNK / 32;

    float acc[2][8][4];
    zero_acc(acc);
    float zp[2] = {0.f, 0.f};
    const uint32_t sbase = (uint32_t)__cvta_generic_to_shared(hsm);
    const uint32_t lLane = ((lane & 15) * KPAD + (lane >> 4) * 8) * 2;

    // per-thread fill mapping: rows of V and K, 16B chunks
    const int frow = tid >> 2;            // with +64 for second half
    const int fk8 = (tid & 3) * 8;

    auto issue_fill = [&](int stage, int k0) {
        uint32_t vdst = sbase + (stage * SSTG_ELEMS) * 2;
        uint32_t kdst = vdst + HA_STG * 2;
#pragma unroll
        for (int t = 0; t < 2; t++) {
            int row = frow + 64 * t;
            cpa16(vdst + (row * KPAD + fk8) * 2, Vb + (size_t)row * HW + k0 + fk8);
            cpa16(kdst + (row * KPAD + fk8) * 2, Kb + (size_t)row * HW + k0 + fk8);
        }
        CPA_COMMIT();
    };

    issue_fill(0, 0);
    issue_fill(1, 32);
    issue_fill(2, 64);

    for (int kb = 0; kb < NKB; kb++) {
        if (kb < NKB - 2)      asm volatile("cp.async.wait_group 2;" ::: "memory");
        else if (kb == NKB - 2) asm volatile("cp.async.wait_group 1;" ::: "memory");
        else                    asm volatile("cp.async.wait_group 0;" ::: "memory");
        __syncthreads();
        if (kb + 3 < NKB) issue_fill((kb + 3) & (SSTAGES - 1), (kb + 3) * 32);

        const int st = kb & (SSTAGES - 1);
        // Z accumulation from K tile in smem
        {
            const __nv_bfloat16* Kd = hsm + st * SSTG_ELEMS + HA_STG;
#pragma unroll
            for (int t = 0; t < 2; t++) {
                int row = frow + 64 * t;
                uint4 kv4 = *(const uint4*)(Kd + row * KPAD + fk8);
                const __nv_bfloat162* h = (const __nv_bfloat162*)&kv4;
#pragma unroll
                for (int j = 0; j < 4; j++) {
                    float2 f2 = __bfloat1622float2(h[j]);
                    zp[t] += f2.x + f2.y;
                }
            }
        }
        const uint32_t sA = sbase + (st * SSTG_ELEMS) * 2;
        const uint32_t sB = sA + HA_STG * 2;
#pragma unroll
        for (int kk = 0; kk < 2; kk++) {
            uint32_t a[2][4], bq[8][2];
#pragma unroll
            for (int mw = 0; mw < 2; mw++)
                ldsm4(a[mw], sA + ((wm * 32 + mw * 16) * KPAD) * 2 + kk * 32 + lLane);
#pragma unroll
            for (int ng = 0; ng < 4; ng++) {
                uint32_t r[4];
                ldsm4(r, sB + ((wn * 64 + ng * 16) * KPAD) * 2 + kk * 32 + lLane);
                bq[2 * ng][0] = r[0]; bq[2 * ng][1] = r[2];
                bq[2 * ng + 1][0] = r[1]; bq[2 * ng + 1][1] = r[3];
            }
#pragma unroll
            for (int mw = 0; mw < 2; mw++)
#pragma unroll
                for (int nw = 0; nw < 8; nw++)
                    mma16(acc[mw][nw], a[mw], bq[nw]);
        }
        __syncthreads();
    }

#pragma unroll
    for (int o = 1; o < 4; o <<= 1) {
        zp[0] += __shfl_xor_sync(0xffffffff, zp[0], o);
        zp[1] += __shfl_xor_sync(0xffffffff, zp[1], o);
    }
    if ((lane & 3) == 0) {
        atomicAdd(&Z[b * CC + (tid >> 2)], zp[0]);
        atomicAdd(&Z[b * CC + 64 + (tid >> 2)], zp[1]);
    }

    float* Sb = S + (size_t)b * CC * CC;
#pragma unroll
    for (int mw = 0; mw < 2; mw++) {
        const int r0 = wm * 32 + mw * 16 + qid;
#pragma unroll
        for (int nw = 0; nw < 8; nw++) {
            const int col = wn * 64 + nw * 8 + tq * 2;
            atomicAdd(&Sb[(size_t)r0 * CC + col],           acc[mw][nw][0]);
            atomicAdd(&Sb[(size_t)r0 * CC + col + 1],       acc[mw][nw][1]);
            atomicAdd(&Sb[(size_t)(r0 + 8) * CC + col],     acc[mw][nw][2]);
            atomicAdd(&Sb[(size_t)(r0 + 8) * CC + col + 1], acc[mw][nw][3]);
        }
    }
}

// ============================================================================
// out GEMM (bf16 MMA, den fused): out[b,c,n] = (S_bf q) / max(Z.q, eps)
// ============================================================================
__global__ void __launch_bounds__(256, 2)
out_bf(const __nv_bfloat16* __restrict__ Sbf, const __nv_bfloat16* __restrict__ Q,
       const float* __restrict__ Zvec, float* __restrict__ Y) {
    extern __shared__ __nv_bfloat16 hsm[];
    float* den_s = (float*)(hsm + O_ELEMS);
    float* Zs = den_s + 128;
    const int tid = threadIdx.x;
    const int b = blockIdx.y;
    const int n0 = blockIdx.x * 128;
    const int warp = tid >> 5, lane = tid & 31;
    const int wm = warp >> 1, wn = warp & 1;
    const int qid = lane >> 2, tq = lane & 3;
    const uint32_t sbase = (uint32_t)__cvta_generic_to_shared(hsm);
    const uint32_t aLane2 = ((lane & 15) * A2PAD + (lane >> 4) * 8) * 2;
    const uint32_t bLane = ((lane & 15) * NPAD + (lane >> 4) * 8) * 2;
    const __nv_bfloat16* Ab = Sbf + (size_t)b * CC * CC;
    const __nv_bfloat16* Xb = Q + (size_t)b * CC * HW + n0;

    if (tid < 128) { Zs[tid] = Zvec[b * CC + tid]; den_s[tid] = 0.f; }
    __syncthreads();

    // A: S_bf [128m x 128k] -> stride A2PAD
    {
        __nv_bfloat16* A2s = hsm + OA_OFF;
#pragma unroll
        for (int t = 0; t < 8; t++) {
            int id = tid + t * 256;
            int m = id >> 4, k8 = (id & 15) * 8;
            *(uint4*)(A2s + (size_t)m * A2PAD + k8) = *(const uint4*)(Ab + (size_t)m * CC + k8);
        }
    }
    // B: q tile [128k x 128n] -> stride NPAD, with fused den accumulation
    {
        __nv_bfloat16* B2s = hsm + OB_OFF;
        const int n8 = (tid & 15) * 8;
        float dreg[8] = {0.f, 0.f, 0.f, 0.f, 0.f, 0.f, 0.f, 0.f};
#pragma unroll
        for (int t = 0; t < 8; t++) {
            int k = (tid >> 4) + t * 16;
            uint4 q4 = *(const uint4*)(Xb + (size_t)k * HW + n8);
            *(uint4*)(B2s + (size_t)k * NPAD + n8) = q4;
            float z = Zs[k];
            const __nv_bfloat162* h = (const __nv_bfloat162*)&q4;
#pragma unroll
            for (int j = 0; j < 4; j++) {
                float2 f2 = __bfloat1622float2(h[j]);
                dreg[2 * j]     = fmaf(z, f2.x, dreg[2 * j]);
                dreg[2 * j + 1] = fmaf(z, f2.y, dreg[2 * j + 1]);
            }
        }
#pragma unroll
        for (int j = 0; j < 8; j++) atomicAdd(&den_s[n8 + j], dreg[j]);
    }
    __syncthreads();

    float acc[2][8][4];
    zero_acc(acc);
    mainloop2p(acc, sbase, OA_OFF * 2, OB_OFF * 2, wm, wn, aLane2, bLane);

    float* Yb = Y + (size_t)b * CC * HW + n0;
#pragma unroll
    for (int mw = 0; mw < 2; mw++) {
        const int r0 = wm * 32 + mw * 16 + qid;
#pragma unroll
        for (int nw = 0; nw < 8; nw++) {
            const int col = wn * 64 + nw * 8 + tq * 2;
            float i0 = 1.f / fmaxf(den_s[col], 1e-12f);
            float i1 = 1.f / fmaxf(den_s[col + 1], 1e-12f);
            float2 p0 = { acc[mw][nw][0] * i0, acc[mw][nw][1] * i1 };
            float2 p1 = { acc[mw][nw][2] * i0, acc[mw][nw][3] * i1 };
            *(float2*)(Yb + (size_t)r0 * HW + col) = p0;
            *(float2*)(Yb + (size_t)(r0 + 8) * HW + col) = p1;
        }
    }
}

// ---------------- launch ----------------
extern "C" void kernel_launch(void* const* d_in, const int* in_sizes, int n_in,
                              void* d_out, int out_size) {
    const float* target = (const float*)d_in[0];
    const float* source = (const float*)d_in[1];
    const float* q_w1 = (const float*)d_in[2];
    const float* q_w2 = (const float*)d_in[3];
    const float* k_w1 = (const float*)d_in[4];
    const float* k_w2 = (const float*)d_in[5];
    const float* v_w  = (const float*)d_in[6];

    float *wkvf, *bkv, *wq1f, *wq2f, *wk2f, *bq1, *bq2, *bk2, *S, *Z;
    __nv_bfloat16 *val, *key, *qr, *Sbf;
    cudaGetSymbolAddress((void**)&wkvf, g_wkvf);
    cudaGetSymbolAddress((void**)&bkv,  g_bkv);
    cudaGetSymbolAddress((void**)&wq1f, g_wq1f);
    cudaGetSymbolAddress((void**)&wq2f, g_wq2f);
    cudaGetSymbolAddress((void**)&wk2f, g_wk2f);
    cudaGetSymbolAddress((void**)&bq1, g_bq1);
    cudaGetSymbolAddress((void**)&bq2, g_bq2);
    cudaGetSymbolAddress((void**)&bk2, g_bk2);
    cudaGetSymbolAddress((void**)&val, g_val);
    cudaGetSymbolAddress((void**)&key, g_key);
    cudaGetSymbolAddress((void**)&qr,  g_qr);
    cudaGetSymbolAddress((void**)&S,   g_S);
    cudaGetSymbolAddress((void**)&Sbf, g_Sbf);
    cudaGetSymbolAddress((void**)&Z,   g_Z);

    cudaFuncSetAttribute(src_k, cudaFuncAttributeMaxDynamicSharedMemorySize, CHAIN_SM_BYTES);
    cudaFuncSetAttribute(tgt_k, cudaFuncAttributeMaxDynamicSharedMemorySize, CHAIN_SM_BYTES);
    cudaFuncSetAttribute(s_bf,  cudaFuncAttributeMaxDynamicSharedMemorySize, SSM_BYTES);
    cudaFuncSetAttribute(out_bf, cudaFuncAttributeMaxDynamicSharedMemorySize, OSM_BYTES);

    PrepAll pa;
    pa.e[0] = { k_w1, (const float*)d_in[15], (const float*)d_in[16], (const float*)d_in[17], (const float*)d_in[18], wkvf, bkv, CIN };
    pa.e[1] = { v_w,  (const float*)d_in[23], (const float*)d_in[24], (const float*)d_in[25], (const float*)d_in[26], wkvf + CC * CIN, bkv + CC, CIN };
    pa.e[2] = { q_w1, (const float*)d_in[7],  (const float*)d_in[8],  (const float*)d_in[9],  (const float*)d_in[10], wq1f, bq1, CIN };
    pa.e[3] = { q_w2, (const float*)d_in[11], (const float*)d_in[12], (const float*)d_in[13], (const float*)d_in[14], wq2f, bq2, CC };
    pa.e[4] = { k_w2, (const float*)d_in[19], (const float*)d_in[20], (const float*)d_in[21], (const float*)d_in[22], wk2f, bk2, CC };
    fold5<<<dim3(CC, 5), 256>>>(pa);

    cudaMemsetAsync(S, 0, BB * CC * CC * sizeof(float));
    cudaMemsetAsync(Z, 0, BB * CC * sizeof(float));

    // source: value + (kh -> key) chain
    src_k<<<dim3(HW / 128 * 2, BB), 256, CHAIN_SM_BYTES>>>(wkvf, bkv, wk2f, bk2, source, val, key);
    // target: qh -> qr chain
    tgt_k<<<dim3(HW / 128, BB), 256, CHAIN_SM_BYTES>>>(wq1f, bq1, wq2f, bq2, target, qr);
    // S = V K^T + fused Z
    s_bf<<<dim3(NSPLIT, BB), 256, SSM_BYTES>>>(val, key, S, Z);
    // S -> bf16
    s2bf<<<BB * CC * CC / 1024, 256>>>(S, Sbf);
    // out (bf16 MMA, den fused)
    out_bf<<<dim3(HW / 128, BB), 256, OSM_BYTES>>>(Sbf, qr, Z, (float*)d_out);
}

// round 12
// speedup vs baseline: 4.4149x; 1.1502x over previous
#include <cuda_runtime.h>
#include <cuda_bf16.h>
#include <math.h>
#include <stdint.h>

#define BB 8
#define CIN 256
#define CC 128
#define HW 16384
#define NSPLIT 32
#define SCHUNK 512

#define KPAD 40
#define NPAD 136
#define A2PAD 136
#define HA_STG (128 * KPAD)      // 5120 elems
#define HB_STG (32 * NPAD)       // 4352 elems

// chain kernel smem layout (bf16 elems)
#define AS_OFF 0
#define BS_OFF (AS_OFF + 2 * HA_STG)          // 10240
#define P1_ELEMS (BS_OFF + 2 * HB_STG)        // 18944
#define A2_OFF 0
#define B2_OFF P1_ELEMS                        // 18944
#define CHAIN_ELEMS (B2_OFF + 128 * NPAD)      // 36352
#define CHAIN_SM_BYTES (CHAIN_ELEMS * 2)       // 72704

// s_bf: 4-stage cp.async pipeline
#define SSTAGES 4
#define SSTG_ELEMS (2 * HA_STG)
#define SSM_BYTES (SSTAGES * SSTG_ELEMS * 2)   // 81920

// out_bf smem layout
#define OA_OFF 0
#define OB_OFF (128 * A2PAD)
#define O_ELEMS (OB_OFF + 128 * NPAD)
#define OSM_BYTES (O_ELEMS * 2 + 256 * 4)

// ---------------- scratch ----------------
__device__ __nv_bfloat16 g_wkvh[2 * CC * CIN];   // bf16 folded [k1 ; v]
__device__ __nv_bfloat16 g_wq1h[CC * CIN];
__device__ __nv_bfloat16 g_wq2h[CC * CC];
__device__ __nv_bfloat16 g_wk2h[CC * CC];
__device__ float g_bkv[2 * CC], g_bq1[CC], g_bq2[CC], g_bk2[CC];
__device__ __nv_bfloat16 g_val[(size_t)BB * CC * HW];
__device__ __nv_bfloat16 g_key[(size_t)BB * CC * HW];
__device__ __nv_bfloat16 g_qr [(size_t)BB * CC * HW];
__device__ float g_S[BB * CC * CC];
__device__ __nv_bfloat16 g_Sbf[BB * CC * CC];
__device__ float g_Z[BB * CC];

// ---------------- helpers ----------------
__device__ __forceinline__ void st4h(__nv_bfloat16* p, float4 v) {
    __nv_bfloat162 lo = __floats2bfloat162_rn(v.x, v.y);
    __nv_bfloat162 hi = __floats2bfloat162_rn(v.z, v.w);
    uint2 u = { *(uint32_t*)&lo, *(uint32_t*)&hi };
    *(uint2*)p = u;
}
__device__ __forceinline__ void ldsm4(uint32_t* r, uint32_t a) {
    asm volatile("ldmatrix.sync.aligned.m8n8.x4.shared.b16 {%0,%1,%2,%3}, [%4];"
                 : "=r"(r[0]), "=r"(r[1]), "=r"(r[2]), "=r"(r[3]) : "r"(a));
}
__device__ __forceinline__ void ldsm4t(uint32_t* r, uint32_t a) {
    asm volatile("ldmatrix.sync.aligned.m8n8.x4.trans.shared.b16 {%0,%1,%2,%3}, [%4];"
                 : "=r"(r[0]), "=r"(r[1]), "=r"(r[2]), "=r"(r[3]) : "r"(a));
}
__device__ __forceinline__ void mma16(float* c, const uint32_t* a, const uint32_t* b) {
    asm volatile("mma.sync.aligned.m16n8k16.row.col.f32.bf16.bf16.f32 "
                 "{%0,%1,%2,%3}, {%4,%5,%6,%7}, {%8,%9}, {%0,%1,%2,%3};"
                 : "+f"(c[0]), "+f"(c[1]), "+f"(c[2]), "+f"(c[3])
                 : "r"(a[0]), "r"(a[1]), "r"(a[2]), "r"(a[3]), "r"(b[0]), "r"(b[1]));
}
__device__ __forceinline__ void cpa16(uint32_t dst, const void* src) {
    asm volatile("cp.async.cg.shared.global [%0], [%1], 16;" :: "r"(dst), "l"(src));
}
#define CPA_COMMIT() asm volatile("cp.async.commit_group;" ::: "memory")
#define CPA_WAIT0()  asm volatile("cp.async.wait_group 0;" ::: "memory")
__device__ __forceinline__ float softplus_fast(float x) {
    return fmaxf(x, 0.f) + log1pf(__expf(-fabsf(x)));
}

// ---------------- merged BN fold (weights -> bf16) ----------------
struct PrepEnt { const float *w, *g, *b, *m, *v; __nv_bfloat16* wf; float* bf; int K; };
struct PrepAll { PrepEnt e[5]; };

__global__ void fold5(PrepAll a) {
    PrepEnt p = a.e[blockIdx.y];
    int o = blockIdx.x;
    float s = p.g[o] * rsqrtf(p.v[o] + 1e-5f);
    if (threadIdx.x == 0) p.bf[o] = p.b[o] - p.m[o] * s;
    for (int c = threadIdx.x; c < p.K; c += blockDim.x)
        p.wf[o * p.K + c] = __float2bfloat16(p.w[o * p.K + c] * s);
}

// ---------------- S fp32 -> bf16 ----------------
__global__ void s2bf(const float* __restrict__ S, __nv_bfloat16* __restrict__ Sb) {
    int i = (blockIdx.x * 256 + threadIdx.x) * 4;
    float4 v = *(const float4*)(S + i);
    st4h(Sb + i, v);
}

__device__ __forceinline__ void zero_acc(float acc[2][8][4]) {
#pragma unroll
    for (int i = 0; i < 2; i++)
#pragma unroll
        for (int j = 0; j < 8; j++)
#pragma unroll
            for (int l = 0; l < 4; l++) acc[i][j][l] = 0.f;
}

// B fill: X fp32 -> bf16 smem [32k x 128n]
__device__ __forceinline__ void fillB_h(__nv_bfloat16* Bd, const float* Xb,
                                        int k0, int tid) {
#pragma unroll
    for (int i = 0; i < 4; i++) {
        int k = (tid >> 5) + 8 * i, nf = (tid & 31) * 4;
        float4 v = *(const float4*)(Xb + (size_t)(k0 + k) * HW + nf);
        st4h(Bd + k * NPAD + nf, v);
    }
}

// ---------------- phase-1 mainloop: A bf16 via cp.async, B fp32 via cvt ----
__device__ __forceinline__ void mainloop1(float acc[2][8][4], __nv_bfloat16* hsm,
                                          uint32_t sbase, const __nv_bfloat16* Ab,
                                          const float* Xb, int tid, int wm, int wn,
                                          uint32_t aLane, uint32_t bLane) {
    __nv_bfloat16* Bs = hsm + BS_OFF;
    auto fillA = [&](int stage, int k0) {
        uint32_t dst = sbase + (AS_OFF + stage * HA_STG) * 2;
#pragma unroll
        for (int t = 0; t < 2; t++) {
            int id = tid + t * 256;
            int row = id >> 2, k8 = (id & 3) * 8;
            cpa16(dst + (row * KPAD + k8) * 2, Ab + (size_t)row * CIN + k0 + k8);
        }
    };
    fillA(0, 0);
    CPA_COMMIT();
    fillB_h(Bs, Xb, 0, tid);
    CPA_WAIT0();
    __syncthreads();
    constexpr int NKB = CIN / 32;
    for (int kb = 0; kb < NKB; kb++) {
        if (kb + 1 < NKB) {
            fillA((kb + 1) & 1, (kb + 1) * 32);
            CPA_COMMIT();
            fillB_h(Bs + ((kb + 1) & 1) * HB_STG, Xb, (kb + 1) * 32, tid);
        }
        const uint32_t sA = sbase + (AS_OFF + (kb & 1) * HA_STG) * 2;
        const uint32_t sB = sbase + (BS_OFF + (kb & 1) * HB_STG) * 2;
#pragma unroll
        for (int kk = 0; kk < 2; kk++) {
            uint32_t a[2][4], bq[8][2];
#pragma unroll
            for (int mw = 0; mw < 2; mw++)
                ldsm4(a[mw], sA + ((wm * 32 + mw * 16) * KPAD) * 2 + kk * 32 + aLane);
#pragma unroll
            for (int ng = 0; ng < 4; ng++) {
                uint32_t r[4];
                ldsm4t(r, sB + (kk * 16 * NPAD + wn * 64 + ng * 16) * 2 + bLane);
                bq[2 * ng][0] = r[0]; bq[2 * ng][1] = r[1];
                bq[2 * ng + 1][0] = r[2]; bq[2 * ng + 1][1] = r[3];
            }
#pragma unroll
            for (int mw = 0; mw < 2; mw++)
#pragma unroll
                for (int nw = 0; nw < 8; nw++)
                    mma16(acc[mw][nw], a[mw], bq[nw]);
        }
        if (kb + 1 < NKB) CPA_WAIT0();
        __syncthreads();
    }
}

// ---------------- smem-resident K=128 mainloop ----------------
__device__ __forceinline__ void mainloop2p(float acc[2][8][4], uint32_t sbase,
                                           uint32_t a_off_b, uint32_t b_off_b,
                                           int wm, int wn, uint32_t aLane2,
                                           uint32_t bLane) {
    const uint32_t sA2 = sbase + a_off_b;
    const uint32_t sB2 = sbase + b_off_b;
#pragma unroll
    for (int kb = 0; kb < 4; kb++) {
#pragma unroll
        for (int kk = 0; kk < 2; kk++) {
            const int kofs = kb * 32 + kk * 16;
            uint32_t a[2][4], bq[8][2];
#pragma unroll
            for (int mw = 0; mw < 2; mw++)
                ldsm4(a[mw], sA2 + ((wm * 32 + mw * 16) * A2PAD + kofs) * 2 + aLane2);
#pragma unroll
            for (int ng = 0; ng < 4; ng++) {
                uint32_t r[4];
                ldsm4t(r, sB2 + ((size_t)kofs * NPAD + wn * 64 + ng * 16) * 2 + bLane);
                bq[2 * ng][0] = r[0]; bq[2 * ng][1] = r[1];
                bq[2 * ng + 1][0] = r[2]; bq[2 * ng + 1][1] = r[3];
            }
#pragma unroll
            for (int mw = 0; mw < 2; mw++)
#pragma unroll
                for (int nw = 0; nw < 8; nw++)
                    mma16(acc[mw][nw], a[mw], bq[nw]);
        }
    }
}

// ---------------- chain body ----------------
__device__ __forceinline__ void chain_body(__nv_bfloat16* hsm, uint32_t sbase,
                                           const __nv_bfloat16* W1, const float* b1,
                                           const __nv_bfloat16* W2, const float* b2,
                                           const float* Xb, __nv_bfloat16* Yout,
                                           int tid, int wm, int wn, int qid, int tq,
                                           uint32_t aLane, uint32_t bLane) {
    const int lane = tid & 31;
    const uint32_t aLane2 = ((lane & 15) * A2PAD + (lane >> 4) * 8) * 2;

    float acc[2][8][4];
    zero_acc(acc);
    mainloop1(acc, hsm, sbase, W1, Xb, tid, wm, wn, aLane, bLane);
    // AS/BS dead after final sync; alias A2 over them.

    // W2 bf16 -> A2 via cp.async (overlaps with the relu/B2 stores below)
    {
        uint32_t dst = sbase + A2_OFF * 2;
#pragma unroll
        for (int t = 0; t < 8; t++) {
            int id = tid + t * 256;
            int m = id >> 4, k8 = (id & 15) * 8;
            cpa16(dst + (m * A2PAD + k8) * 2, W2 + (size_t)m * CC + k8);
        }
        CPA_COMMIT();
    }
    // relu(acc + b1) -> B2s [k=channel][n]
    {
        __nv_bfloat16* B2s = hsm + B2_OFF;
#pragma unroll
        for (int mw = 0; mw < 2; mw++) {
            const int r0 = wm * 32 + mw * 16 + qid;
            float bv0 = b1[r0], bv1 = b1[r0 + 8];
#pragma unroll
            for (int nw = 0; nw < 8; nw++) {
                const int col = wn * 64 + nw * 8 + tq * 2;
                __nv_bfloat162 p0 = __floats2bfloat162_rn(
                    fmaxf(acc[mw][nw][0] + bv0, 0.f), fmaxf(acc[mw][nw][1] + bv0, 0.f));
                __nv_bfloat162 p1 = __floats2bfloat162_rn(
                    fmaxf(acc[mw][nw][2] + bv1, 0.f), fmaxf(acc[mw][nw][3] + bv1, 0.f));
                *(__nv_bfloat162*)(B2s + (size_t)r0 * NPAD + col) = p0;
                *(__nv_bfloat162*)(B2s + (size_t)(r0 + 8) * NPAD + col) = p1;
            }
        }
    }
    CPA_WAIT0();
    __syncthreads();

    zero_acc(acc);
    mainloop2p(acc, sbase, A2_OFF * 2, B2_OFF * 2, wm, wn, aLane2, bLane);

#pragma unroll
    for (int mw = 0; mw < 2; mw++) {
        const int r0 = wm * 32 + mw * 16 + qid;
        float bv0 = b2[r0], bv1 = b2[r0 + 8];
#pragma unroll
        for (int nw = 0; nw < 8; nw++) {
            const int col = wn * 64 + nw * 8 + tq * 2;
            __nv_bfloat162 p0 = __floats2bfloat162_rn(
                softplus_fast(acc[mw][nw][0] + bv0), softplus_fast(acc[mw][nw][1] + bv0));
            __nv_bfloat162 p1 = __floats2bfloat162_rn(
                softplus_fast(acc[mw][nw][2] + bv1), softplus_fast(acc[mw][nw][3] + bv1));
            *(__nv_bfloat162*)(Yout + (size_t)r0 * HW + col) = p0;
            *(__nv_bfloat162*)(Yout + (size_t)(r0 + 8) * HW + col) = p1;
        }
    }
}

// ---------------- merged conv kernel: role 0 kh->key, 1 value, 2 q chain ----
__global__ void __launch_bounds__(256, 2)
conv_all(const __nv_bfloat16* __restrict__ Wkv, const float* __restrict__ bkv,
         const __nv_bfloat16* __restrict__ Wk2, const float* __restrict__ bk2,
         const __nv_bfloat16* __restrict__ Wq1, const float* __restrict__ bq1,
         const __nv_bfloat16* __restrict__ Wq2, const float* __restrict__ bq2,
         const float* __restrict__ Xsrc, const float* __restrict__ Xtgt,
         __nv_bfloat16* __restrict__ val, __nv_bfloat16* __restrict__ key,
         __nv_bfloat16* __restrict__ qr) {
    extern __shared__ __nv_bfloat16 hsm[];
    const int tid = threadIdx.x;
    const int b = blockIdx.y;
    const int role = blockIdx.x % 3;
    const int n0 = (blockIdx.x / 3) * 128;
    const int warp = tid >> 5, lane = tid & 31;
    const int wm = warp >> 1, wn = warp & 1;
    const int qid = lane >> 2, tq = lane & 3;
    const uint32_t sbase = (uint32_t)__cvta_generic_to_shared(hsm);
    const uint32_t aLane = ((lane & 15) * KPAD + (lane >> 4) * 8) * 2;
    const uint32_t bLane = ((lane & 15) * NPAD + (lane >> 4) * 8) * 2;

    if (role == 1) {
        const float* Xb = Xsrc + (size_t)b * CIN * HW + n0;
        float acc[2][8][4];
        zero_acc(acc);
        mainloop1(acc, hsm, sbase, Wkv + (size_t)128 * CIN, Xb, tid, wm, wn, aLane, bLane);
        __nv_bfloat16* Yb = val + (size_t)b * CC * HW + n0;
        const float* bp = bkv + 128;
#pragma unroll
        for (int mw = 0; mw < 2; mw++) {
            const int r0 = wm * 32 + mw * 16 + qid;
            float bv0 = bp[r0], bv1 = bp[r0 + 8];
#pragma unroll
            for (int nw = 0; nw < 8; nw++) {
                const int col = wn * 64 + nw * 8 + tq * 2;
                __nv_bfloat162 p0 = __floats2bfloat162_rn(
                    fmaxf(acc[mw][nw][0] + bv0, 0.f), fmaxf(acc[mw][nw][1] + bv0, 0.f));
                __nv_bfloat162 p1 = __floats2bfloat162_rn(
                    fmaxf(acc[mw][nw][2] + bv1, 0.f), fmaxf(acc[mw][nw][3] + bv1, 0.f));
                *(__nv_bfloat162*)(Yb + (size_t)r0 * HW + col) = p0;
                *(__nv_bfloat162*)(Yb + (size_t)(r0 + 8) * HW + col) = p1;
            }
        }
    } else if (role == 0) {
        chain_body(hsm, sbase, Wkv, bkv, Wk2, bk2,
                   Xsrc + (size_t)b * CIN * HW + n0,
                   key + (size_t)b * CC * HW + n0, tid, wm, wn, qid, tq, aLane, bLane);
    } else {
        chain_body(hsm, sbase, Wq1, bq1, Wq2, bq2,
                   Xtgt + (size_t)b * CIN * HW + n0,
                   qr + (size_t)b * CC * HW + n0, tid, wm, wn, qid, tq, aLane, bLane);
    }
}

// ============================================================================
// S[b,c,d] += sum_n V K^T (+ fused Z), 4-stage cp.async pipeline
// ============================================================================
__global__ void __launch_bounds__(256, 2)
s_bf(const __nv_bfloat16* __restrict__ V, const __nv_bfloat16* __restrict__ Kt,
     float* __restrict__ S, float* __restrict__ Z) {
    extern __shared__ __nv_bfloat16 hsm[];
    const int tid = threadIdx.x;
    const int b = blockIdx.y;
    const int n0 = blockIdx.x * SCHUNK;
    const int warp = tid >> 5, lane = tid & 31;
    const int wm = warp >> 1, wn = warp & 1;
    const int qid = lane >> 2, tq = lane & 3;
    const __nv_bfloat16* Vb = V + (size_t)b * CC * HW + n0;
    const __nv_bfloat16* Kb = Kt + (size_t)b * CC * HW + n0;
    constexpr int NKB = SCHUNK / 32;

    float acc[2][8][4];
    zero_acc(acc);
    float zp[2] = {0.f, 0.f};
    const uint32_t sbase = (uint32_t)__cvta_generic_to_shared(hsm);
    const uint32_t lLane = ((lane & 15) * KPAD + (lane >> 4) * 8) * 2;
    const int frow = tid >> 2;
    const int fk8 = (tid & 3) * 8;

    auto issue_fill = [&](int stage, int k0) {
        uint32_t vdst = sbase + (stage * SSTG_ELEMS) * 2;
        uint32_t kdst = vdst + HA_STG * 2;
#pragma unroll
        for (int t = 0; t < 2; t++) {
            int row = frow + 64 * t;
            cpa16(vdst + (row * KPAD + fk8) * 2, Vb + (size_t)row * HW + k0 + fk8);
            cpa16(kdst + (row * KPAD + fk8) * 2, Kb + (size_t)row * HW + k0 + fk8);
        }
        CPA_COMMIT();
    };

    issue_fill(0, 0);
    issue_fill(1, 32);
    issue_fill(2, 64);

    for (int kb = 0; kb < NKB; kb++) {
        if (kb < NKB - 2)       asm volatile("cp.async.wait_group 2;" ::: "memory");
        else if (kb == NKB - 2) asm volatile("cp.async.wait_group 1;" ::: "memory");
        else                    asm volatile("cp.async.wait_group 0;" ::: "memory");
        __syncthreads();
        if (kb + 3 < NKB) issue_fill((kb + 3) & (SSTAGES - 1), (kb + 3) * 32);

        const int st = kb & (SSTAGES - 1);
        {
            const __nv_bfloat16* Kd = hsm + st * SSTG_ELEMS + HA_STG;
#pragma unroll
            for (int t = 0; t < 2; t++) {
                int row = frow + 64 * t;
                uint4 kv4 = *(const uint4*)(Kd + row * KPAD + fk8);
                const __nv_bfloat162* h = (const __nv_bfloat162*)&kv4;
#pragma unroll
                for (int j = 0; j < 4; j++) {
                    float2 f2 = __bfloat1622float2(h[j]);
                    zp[t] += f2.x + f2.y;
                }
            }
        }
        const uint32_t sA = sbase + (st * SSTG_ELEMS) * 2;
        const uint32_t sB = sA + HA_STG * 2;
#pragma unroll
        for (int kk = 0; kk < 2; kk++) {
            uint32_t a[2][4], bq[8][2];
#pragma unroll
            for (int mw = 0; mw < 2; mw++)
                ldsm4(a[mw], sA + ((wm * 32 + mw * 16) * KPAD) * 2 + kk * 32 + lLane);
#pragma unroll
            for (int ng = 0; ng < 4; ng++) {
                uint32_t r[4];
                ldsm4(r, sB + ((wn * 64 + ng * 16) * KPAD) * 2 + kk * 32 + lLane);
                bq[2 * ng][0] = r[0]; bq[2 * ng][1] = r[2];
                bq[2 * ng + 1][0] = r[1]; bq[2 * ng + 1][1] = r[3];
            }
#pragma unroll
            for (int mw = 0; mw < 2; mw++)
#pragma unroll
                for (int nw = 0; nw < 8; nw++)
                    mma16(acc[mw][nw], a[mw], bq[nw]);
        }
        __syncthreads();
    }

#pragma unroll
    for (int o = 1; o < 4; o <<= 1) {
        zp[0] += __shfl_xor_sync(0xffffffff, zp[0], o);
        zp[1] += __shfl_xor_sync(0xffffffff, zp[1], o);
    }
    if ((lane & 3) == 0) {
        atomicAdd(&Z[b * CC + (tid >> 2)], zp[0]);
        atomicAdd(&Z[b * CC + 64 + (tid >> 2)], zp[1]);
    }

    float* Sb = S + (size_t)b * CC * CC;
#pragma unroll
    for (int mw = 0; mw < 2; mw++) {
        const int r0 = wm * 32 + mw * 16 + qid;
#pragma unroll
        for (int nw = 0; nw < 8; nw++) {
            const int col = wn * 64 + nw * 8 + tq * 2;
            atomicAdd(&Sb[(size_t)r0 * CC + col],           acc[mw][nw][0]);
            atomicAdd(&Sb[(size_t)r0 * CC + col + 1],       acc[mw][nw][1]);
            atomicAdd(&Sb[(size_t)(r0 + 8) * CC + col],     acc[mw][nw][2]);
            atomicAdd(&Sb[(size_t)(r0 + 8) * CC + col + 1], acc[mw][nw][3]);
        }
    }
}

// ============================================================================
// out GEMM (bf16 MMA, den fused)
// ============================================================================
__global__ void __launch_bounds__(256, 2)
out_bf(const __nv_bfloat16* __restrict__ Sbf, const __nv_bfloat16* __restrict__ Q,
       const float* __restrict__ Zvec, float* __restrict__ Y) {
    extern __shared__ __nv_bfloat16 hsm[];
    float* den_s = (float*)(hsm + O_ELEMS);
    float* Zs = den_s + 128;
    const int tid = threadIdx.x;
    const int b = blockIdx.y;
    const int n0 = blockIdx.x * 128;
    const int warp = tid >> 5, lane = tid & 31;
    const int wm = warp >> 1, wn = warp & 1;
    const int qid = lane >> 2, tq = lane & 3;
    const uint32_t sbase = (uint32_t)__cvta_generic_to_shared(hsm);
    const uint32_t aLane2 = ((lane & 15) * A2PAD + (lane >> 4) * 8) * 2;
    const uint32_t bLane = ((lane & 15) * NPAD + (lane >> 4) * 8) * 2;
    const __nv_bfloat16* Ab = Sbf + (size_t)b * CC * CC;
    const __nv_bfloat16* Xb = Q + (size_t)b * CC * HW + n0;

    if (tid < 128) { Zs[tid] = Zvec[b * CC + tid]; den_s[tid] = 0.f; }
    __syncthreads();

    {
        __nv_bfloat16* A2s = hsm + OA_OFF;
#pragma unroll
        for (int t = 0; t < 8; t++) {
            int id = tid + t * 256;
            int m = id >> 4, k8 = (id & 15) * 8;
            *(uint4*)(A2s + (size_t)m * A2PAD + k8) = *(const uint4*)(Ab + (size_t)m * CC + k8);
        }
    }
    {
        __nv_bfloat16* B2s = hsm + OB_OFF;
        const int n8 = (tid & 15) * 8;
        float dreg[8] = {0.f, 0.f, 0.f, 0.f, 0.f, 0.f, 0.f, 0.f};
#pragma unroll
        for (int t = 0; t < 8; t++) {
            int k = (tid >> 4) + t * 16;
            uint4 q4 = *(const uint4*)(Xb + (size_t)k * HW + n8);
            *(uint4*)(B2s + (size_t)k * NPAD + n8) = q4;
            float z = Zs[k];
            const __nv_bfloat162* h = (const __nv_bfloat162*)&q4;
#pragma unroll
            for (int j = 0; j < 4; j++) {
                float2 f2 = __bfloat1622float2(h[j]);
                dreg[2 * j]     = fmaf(z, f2.x, dreg[2 * j]);
                dreg[2 * j + 1] = fmaf(z, f2.y, dreg[2 * j + 1]);
            }
        }
#pragma unroll
        for (int j = 0; j < 8; j++) atomicAdd(&den_s[n8 + j], dreg[j]);
    }
    __syncthreads();

    float acc[2][8][4];
    zero_acc(acc);
    mainloop2p(acc, sbase, OA_OFF * 2, OB_OFF * 2, wm, wn, aLane2, bLane);

    float* Yb = Y + (size_t)b * CC * HW + n0;
#pragma unroll
    for (int mw = 0; mw < 2; mw++) {
        const int r0 = wm * 32 + mw * 16 + qid;
#pragma unroll
        for (int nw = 0; nw < 8; nw++) {
            const int col = wn * 64 + nw * 8 + tq * 2;
            float i0 = 1.f / fmaxf(den_s[col], 1e-12f);
            float i1 = 1.f / fmaxf(den_s[col + 1], 1e-12f);
            float2 p0 = { acc[mw][nw][0] * i0, acc[mw][nw][1] * i1 };
            float2 p1 = { acc[mw][nw][2] * i0, acc[mw][nw][3] * i1 };
            *(float2*)(Yb + (size_t)r0 * HW + col) = p0;
            *(float2*)(Yb + (size_t)(r0 + 8) * HW + col) = p1;
        }
    }
}

// ---------------- launch ----------------
extern "C" void kernel_launch(void* const* d_in, const int* in_sizes, int n_in,
                              void* d_out, int out_size) {
    const float* target = (const float*)d_in[0];
    const float* source = (const float*)d_in[1];
    const float* q_w1 = (const float*)d_in[2];
    const float* q_w2 = (const float*)d_in[3];
    const float* k_w1 = (const float*)d_in[4];
    const float* k_w2 = (const float*)d_in[5];
    const float* v_w  = (const float*)d_in[6];

    __nv_bfloat16 *wkvh, *wq1h, *wq2h, *wk2h, *val, *key, *qr, *Sbf;
    float *bkv, *bq1, *bq2, *bk2, *S, *Z;
    cudaGetSymbolAddress((void**)&wkvh, g_wkvh);
    cudaGetSymbolAddress((void**)&wq1h, g_wq1h);
    cudaGetSymbolAddress((void**)&wq2h, g_wq2h);
    cudaGetSymbolAddress((void**)&wk2h, g_wk2h);
    cudaGetSymbolAddress((void**)&bkv, g_bkv);
    cudaGetSymbolAddress((void**)&bq1, g_bq1);
    cudaGetSymbolAddress((void**)&bq2, g_bq2);
    cudaGetSymbolAddress((void**)&bk2, g_bk2);
    cudaGetSymbolAddress((void**)&val, g_val);
    cudaGetSymbolAddress((void**)&key, g_key);
    cudaGetSymbolAddress((void**)&qr,  g_qr);
    cudaGetSymbolAddress((void**)&S,   g_S);
    cudaGetSymbolAddress((void**)&Sbf, g_Sbf);
    cudaGetSymbolAddress((void**)&Z,   g_Z);

    cudaFuncSetAttribute(conv_all, cudaFuncAttributeMaxDynamicSharedMemorySize, CHAIN_SM_BYTES);
    cudaFuncSetAttribute(s_bf,  cudaFuncAttributeMaxDynamicSharedMemorySize, SSM_BYTES);
    cudaFuncSetAttribute(out_bf, cudaFuncAttributeMaxDynamicSharedMemorySize, OSM_BYTES);

    PrepAll pa;
    pa.e[0] = { k_w1, (const float*)d_in[15], (const float*)d_in[16], (const float*)d_in[17], (const float*)d_in[18], wkvh, bkv, CIN };
    pa.e[1] = { v_w,  (const float*)d_in[23], (const float*)d_in[24], (const float*)d_in[25], (const float*)d_in[26], wkvh + CC * CIN, bkv + CC, CIN };
    pa.e[2] = { q_w1, (const float*)d_in[7],  (const float*)d_in[8],  (const float*)d_in[9],  (const float*)d_in[10], wq1h, bq1, CIN };
    pa.e[3] = { q_w2, (const float*)d_in[11], (const float*)d_in[12], (const float*)d_in[13], (const float*)d_in[14], wq2h, bq2, CC };
    pa.e[4] = { k_w2, (const float*)d_in[19], (const float*)d_in[20], (const float*)d_in[21], (const float*)d_in[22], wk2h, bk2, CC };
    fold5<<<dim3(CC, 5), 256>>>(pa);

    cudaMemsetAsync(S, 0, BB * CC * CC * sizeof(float));
    cudaMemsetAsync(Z, 0, BB * CC * sizeof(float));

    // all conv chains in one launch
    conv_all<<<dim3(HW / 128 * 3, BB), 256, CHAIN_SM_BYTES>>>(
        wkvh, bkv, wk2h, bk2, wq1h, bq1, wq2h, bq2, source, target, val, key, qr);
    // S = V K^T + fused Z
    s_bf<<<dim3(NSPLIT, BB), 256, SSM_BYTES>>>(val, key, S, Z);
    // S -> bf16
    s2bf<<<BB * CC * CC / 1024, 256>>>(S, Sbf);
    // out (bf16 MMA, den fused)
    out_bf<<<dim3(HW / 128, BB), 256, OSM_BYTES>>>(Sbf, qr, Z, (float*)d_out);
}

// round 14
// speedup vs baseline: 4.4491x; 1.0078x over previous
#include <cuda_runtime.h>
#include <cuda_bf16.h>
#include <math.h>
#include <stdint.h>

#define BB 8
#define CIN 256
#define CC 128
#define HW 16384
#define NSPLIT 32
#define SCHUNK 512

#define KPAD 40
#define NPAD 136
#define A2PAD 136
#define HA_STG (128 * KPAD)      // 5120 elems
#define HB_STG (32 * NPAD)       // 4352 elems

// chain kernel smem layout (bf16 elems)
#define AS_OFF 0
#define BS_OFF (AS_OFF + 2 * HA_STG)          // 10240
#define P1_ELEMS (BS_OFF + 2 * HB_STG)        // 18944
#define A2_OFF 0
#define B2_OFF P1_ELEMS                        // 18944
#define CHAIN_ELEMS (B2_OFF + 128 * NPAD)      // 36352
#define CHAIN_SM_BYTES (CHAIN_ELEMS * 2)       // 72704

// s_bf: 4-stage cp.async pipeline
#define SSTAGES 4
#define SSTG_ELEMS (2 * HA_STG)
#define SSM_BYTES (SSTAGES * SSTG_ELEMS * 2)   // 81920

// out_bf smem layout
#define OA_OFF 0
#define OB_OFF (128 * A2PAD)
#define O_ELEMS (OB_OFF + 128 * NPAD)
#define OSM_BYTES (O_ELEMS * 2 + 256 * 4)

// ---------------- scratch ----------------
__device__ __nv_bfloat16 g_wkvh[2 * CC * CIN];
__device__ __nv_bfloat16 g_wq1h[CC * CIN];
__device__ __nv_bfloat16 g_wq2h[CC * CC];
__device__ __nv_bfloat16 g_wk2h[CC * CC];
__device__ float g_bkv[2 * CC], g_bq1[CC], g_bq2[CC], g_bk2[CC];
__device__ __nv_bfloat16 g_val[(size_t)BB * CC * HW];
__device__ __nv_bfloat16 g_key[(size_t)BB * CC * HW];
__device__ __nv_bfloat16 g_qr [(size_t)BB * CC * HW];
__device__ float g_S[BB * CC * CC];
__device__ float g_Z[BB * CC];

// ---------------- helpers ----------------
__device__ __forceinline__ void st4h(__nv_bfloat16* p, float4 v) {
    __nv_bfloat162 lo = __floats2bfloat162_rn(v.x, v.y);
    __nv_bfloat162 hi = __floats2bfloat162_rn(v.z, v.w);
    uint2 u = { *(uint32_t*)&lo, *(uint32_t*)&hi };
    *(uint2*)p = u;
}
__device__ __forceinline__ void ldsm4(uint32_t* r, uint32_t a) {
    asm volatile("ldmatrix.sync.aligned.m8n8.x4.shared.b16 {%0,%1,%2,%3}, [%4];"
                 : "=r"(r[0]), "=r"(r[1]), "=r"(r[2]), "=r"(r[3]) : "r"(a));
}
__device__ __forceinline__ void ldsm4t(uint32_t* r, uint32_t a) {
    asm volatile("ldmatrix.sync.aligned.m8n8.x4.trans.shared.b16 {%0,%1,%2,%3}, [%4];"
                 : "=r"(r[0]), "=r"(r[1]), "=r"(r[2]), "=r"(r[3]) : "r"(a));
}
__device__ __forceinline__ void mma16(float* c, const uint32_t* a, const uint32_t* b) {
    asm volatile("mma.sync.aligned.m16n8k16.row.col.f32.bf16.bf16.f32 "
                 "{%0,%1,%2,%3}, {%4,%5,%6,%7}, {%8,%9}, {%0,%1,%2,%3};"
                 : "+f"(c[0]), "+f"(c[1]), "+f"(c[2]), "+f"(c[3])
                 : "r"(a[0]), "r"(a[1]), "r"(a[2]), "r"(a[3]), "r"(b[0]), "r"(b[1]));
}
__device__ __forceinline__ void cpa16(uint32_t dst, const void* src) {
    asm volatile("cp.async.cg.shared.global [%0], [%1], 16;" :: "r"(dst), "l"(src));
}
#define CPA_COMMIT() asm volatile("cp.async.commit_group;" ::: "memory")
#define CPA_WAIT0()  asm volatile("cp.async.wait_group 0;" ::: "memory")
__device__ __forceinline__ float softplus_fast(float x) {
    return fmaxf(x, 0.f) + log1pf(__expf(-fabsf(x)));
}

// ---------------- merged BN fold (weights -> bf16) ----------------
struct PrepEnt { const float *w, *g, *b, *m, *v; __nv_bfloat16* wf; float* bf; int K; };
struct PrepAll { PrepEnt e[5]; };

__global__ void fold5(PrepAll a) {
    PrepEnt p = a.e[blockIdx.y];
    int o = blockIdx.x;
    float s = p.g[o] * rsqrtf(p.v[o] + 1e-5f);
    if (threadIdx.x == 0) p.bf[o] = p.b[o] - p.m[o] * s;
    for (int c = threadIdx.x; c < p.K; c += blockDim.x)
        p.wf[o * p.K + c] = __float2bfloat16(p.w[o * p.K + c] * s);
}

__device__ __forceinline__ void zero_acc(float acc[2][8][4]) {
#pragma unroll
    for (int i = 0; i < 2; i++)
#pragma unroll
        for (int j = 0; j < 8; j++)
#pragma unroll
            for (int l = 0; l < 4; l++) acc[i][j][l] = 0.f;
}

// ---------------- phase-1 mainloop: A bf16 via cp.async, B fp32 reg-prefetch
__device__ __forceinline__ void mainloop1(float acc[2][8][4], __nv_bfloat16* hsm,
                                          uint32_t sbase, const __nv_bfloat16* Ab,
                                          const float* Xb, int tid, int wm, int wn,
                                          uint32_t aLane, uint32_t bLane) {
    __nv_bfloat16* Bs = hsm + BS_OFF;
    const int bk = tid >> 5, bn = (tid & 31) * 4;
    auto fillA = [&](int stage, int k0) {
        uint32_t dst = sbase + (AS_OFF + stage * HA_STG) * 2;
#pragma unroll
        for (int t = 0; t < 2; t++) {
            int id = tid + t * 256;
            int row = id >> 2, k8 = (id & 3) * 8;
            cpa16(dst + (row * KPAD + k8) * 2, Ab + (size_t)row * CIN + k0 + k8);
        }
    };
    // stage 0
    fillA(0, 0);
    CPA_COMMIT();
#pragma unroll
    for (int i = 0; i < 4; i++) {
        int k = bk + 8 * i;
        float4 v = *(const float4*)(Xb + (size_t)k * HW + bn);
        st4h(Bs + k * NPAD + bn, v);
    }
    CPA_WAIT0();
    __syncthreads();

    constexpr int NKB = CIN / 32;
    for (int kb = 0; kb < NKB; kb++) {
        float4 rb[4];
        if (kb + 1 < NKB) {
            fillA((kb + 1) & 1, (kb + 1) * 32);
            CPA_COMMIT();
            const int k0 = (kb + 1) * 32;
#pragma unroll
            for (int i = 0; i < 4; i++)
                rb[i] = *(const float4*)(Xb + (size_t)(k0 + bk + 8 * i) * HW + bn);
        }
        const uint32_t sA = sbase + (AS_OFF + (kb & 1) * HA_STG) * 2;
        const uint32_t sB = sbase + (BS_OFF + (kb & 1) * HB_STG) * 2;
#pragma unroll
        for (int kk = 0; kk < 2; kk++) {
            uint32_t a[2][4], bq[8][2];
#pragma unroll
            for (int mw = 0; mw < 2; mw++)
                ldsm4(a[mw], sA + ((wm * 32 + mw * 16) * KPAD) * 2 + kk * 32 + aLane);
#pragma unroll
            for (int ng = 0; ng < 4; ng++) {
                uint32_t r[4];
                ldsm4t(r, sB + (kk * 16 * NPAD + wn * 64 + ng * 16) * 2 + bLane);
                bq[2 * ng][0] = r[0]; bq[2 * ng][1] = r[1];
                bq[2 * ng + 1][0] = r[2]; bq[2 * ng + 1][1] = r[3];
            }
#pragma unroll
            for (int mw = 0; mw < 2; mw++)
#pragma unroll
                for (int nw = 0; nw < 8; nw++)
                    mma16(acc[mw][nw], a[mw], bq[nw]);
        }
        if (kb + 1 < NKB) {
            __nv_bfloat16* Bd = Bs + ((kb + 1) & 1) * HB_STG;
#pragma unroll
            for (int i = 0; i < 4; i++)
                st4h(Bd + (bk + 8 * i) * NPAD + bn, rb[i]);
            CPA_WAIT0();
        }
        __syncthreads();
    }
}

// ---------------- smem-resident K=128 mainloop ----------------
__device__ __forceinline__ void mainloop2p(float acc[2][8][4], uint32_t sbase,
                                           uint32_t a_off_b, uint32_t b_off_b,
                                           int wm, int wn, uint32_t aLane2,
                                           uint32_t bLane) {
    const uint32_t sA2 = sbase + a_off_b;
    const uint32_t sB2 = sbase + b_off_b;
#pragma unroll
    for (int kb = 0; kb < 4; kb++) {
#pragma unroll
        for (int kk = 0; kk < 2; kk++) {
            const int kofs = kb * 32 + kk * 16;
            uint32_t a[2][4], bq[8][2];
#pragma unroll
            for (int mw = 0; mw < 2; mw++)
                ldsm4(a[mw], sA2 + ((wm * 32 + mw * 16) * A2PAD + kofs) * 2 + aLane2);
#pragma unroll
            for (int ng = 0; ng < 4; ng++) {
                uint32_t r[4];
                ldsm4t(r, sB2 + ((size_t)kofs * NPAD + wn * 64 + ng * 16) * 2 + bLane);
                bq[2 * ng][0] = r[0]; bq[2 * ng][1] = r[1];
                bq[2 * ng + 1][0] = r[2]; bq[2 * ng + 1][1] = r[3];
            }
#pragma unroll
            for (int mw = 0; mw < 2; mw++)
#pragma unroll
                for (int nw = 0; nw < 8; nw++)
                    mma16(acc[mw][nw], a[mw], bq[nw]);
        }
    }
}

// ---------------- chain body ----------------
__device__ __forceinline__ void chain_body(__nv_bfloat16* hsm, uint32_t sbase,
                                           const __nv_bfloat16* W1, const float* b1,
                                           const __nv_bfloat16* W2, const float* b2,
                                           const float* Xb, __nv_bfloat16* Yout,
                                           int tid, int wm, int wn, int qid, int tq,
                                           uint32_t aLane, uint32_t bLane) {
    const int lane = tid & 31;
    const uint32_t aLane2 = ((lane & 15) * A2PAD + (lane >> 4) * 8) * 2;

    float acc[2][8][4];
    zero_acc(acc);
    mainloop1(acc, hsm, sbase, W1, Xb, tid, wm, wn, aLane, bLane);
    // AS/BS dead after final sync; alias A2 over them.

    {
        uint32_t dst = sbase + A2_OFF * 2;
#pragma unroll
        for (int t = 0; t < 8; t++) {
            int id = tid + t * 256;
            int m = id >> 4, k8 = (id & 15) * 8;
            cpa16(dst + (m * A2PAD + k8) * 2, W2 + (size_t)m * CC + k8);
        }
        CPA_COMMIT();
    }
    {
        __nv_bfloat16* B2s = hsm + B2_OFF;
#pragma unroll
        for (int mw = 0; mw < 2; mw++) {
            const int r0 = wm * 32 + mw * 16 + qid;
            float bv0 = b1[r0], bv1 = b1[r0 + 8];
#pragma unroll
            for (int nw = 0; nw < 8; nw++) {
                const int col = wn * 64 + nw * 8 + tq * 2;
                __nv_bfloat162 p0 = __floats2bfloat162_rn(
                    fmaxf(acc[mw][nw][0] + bv0, 0.f), fmaxf(acc[mw][nw][1] + bv0, 0.f));
                __nv_bfloat162 p1 = __floats2bfloat162_rn(
                    fmaxf(acc[mw][nw][2] + bv1, 0.f), fmaxf(acc[mw][nw][3] + bv1, 0.f));
                *(__nv_bfloat162*)(B2s + (size_t)r0 * NPAD + col) = p0;
                *(__nv_bfloat162*)(B2s + (size_t)(r0 + 8) * NPAD + col) = p1;
            }
        }
    }
    CPA_WAIT0();
    __syncthreads();

    zero_acc(acc);
    mainloop2p(acc, sbase, A2_OFF * 2, B2_OFF * 2, wm, wn, aLane2, bLane);

#pragma unroll
    for (int mw = 0; mw < 2; mw++) {
        const int r0 = wm * 32 + mw * 16 + qid;
        float bv0 = b2[r0], bv1 = b2[r0 + 8];
#pragma unroll
        for (int nw = 0; nw < 8; nw++) {
            const int col = wn * 64 + nw * 8 + tq * 2;
            __nv_bfloat162 p0 = __floats2bfloat162_rn(
                softplus_fast(acc[mw][nw][0] + bv0), softplus_fast(acc[mw][nw][1] + bv0));
            __nv_bfloat162 p1 = __floats2bfloat162_rn(
                softplus_fast(acc[mw][nw][2] + bv1), softplus_fast(acc[mw][nw][3] + bv1));
            *(__nv_bfloat162*)(Yout + (size_t)r0 * HW + col) = p0;
            *(__nv_bfloat162*)(Yout + (size_t)(r0 + 8) * HW + col) = p1;
        }
    }
}

// ---------------- merged conv kernel ----------------
__global__ void __launch_bounds__(256, 2)
conv_all(const __nv_bfloat16* __restrict__ Wkv, const float* __restrict__ bkv,
         const __nv_bfloat16* __restrict__ Wk2, const float* __restrict__ bk2,
         const __nv_bfloat16* __restrict__ Wq1, const float* __restrict__ bq1,
         const __nv_bfloat16* __restrict__ Wq2, const float* __restrict__ bq2,
         const float* __restrict__ Xsrc, const float* __restrict__ Xtgt,
         __nv_bfloat16* __restrict__ val, __nv_bfloat16* __restrict__ key,
         __nv_bfloat16* __restrict__ qr) {
    extern __shared__ __nv_bfloat16 hsm[];
    const int tid = threadIdx.x;
    const int b = blockIdx.y;
    const int role = blockIdx.x % 3;
    const int n0 = (blockIdx.x / 3) * 128;
    const int warp = tid >> 5, lane = tid & 31;
    const int wm = warp >> 1, wn = warp & 1;
    const int qid = lane >> 2, tq = lane & 3;
    const uint32_t sbase = (uint32_t)__cvta_generic_to_shared(hsm);
    const uint32_t aLane = ((lane & 15) * KPAD + (lane >> 4) * 8) * 2;
    const uint32_t bLane = ((lane & 15) * NPAD + (lane >> 4) * 8) * 2;

    if (role == 1) {
        const float* Xb = Xsrc + (size_t)b * CIN * HW + n0;
        float acc[2][8][4];
        zero_acc(acc);
        mainloop1(acc, hsm, sbase, Wkv + (size_t)128 * CIN, Xb, tid, wm, wn, aLane, bLane);
        __nv_bfloat16* Yb = val + (size_t)b * CC * HW + n0;
        const float* bp = bkv + 128;
#pragma unroll
        for (int mw = 0; mw < 2; mw++) {
            const int r0 = wm * 32 + mw * 16 + qid;
            float bv0 = bp[r0], bv1 = bp[r0 + 8];
#pragma unroll
            for (int nw = 0; nw < 8; nw++) {
                const int col = wn * 64 + nw * 8 + tq * 2;
                __nv_bfloat162 p0 = __floats2bfloat162_rn(
                    fmaxf(acc[mw][nw][0] + bv0, 0.f), fmaxf(acc[mw][nw][1] + bv0, 0.f));
                __nv_bfloat162 p1 = __floats2bfloat162_rn(
                    fmaxf(acc[mw][nw][2] + bv1, 0.f), fmaxf(acc[mw][nw][3] + bv1, 0.f));
                *(__nv_bfloat162*)(Yb + (size_t)r0 * HW + col) = p0;
                *(__nv_bfloat162*)(Yb + (size_t)(r0 + 8) * HW + col) = p1;
            }
        }
    } else if (role == 0) {
        chain_body(hsm, sbase, Wkv, bkv, Wk2, bk2,
                   Xsrc + (size_t)b * CIN * HW + n0,
                   key + (size_t)b * CC * HW + n0, tid, wm, wn, qid, tq, aLane, bLane);
    } else {
        chain_body(hsm, sbase, Wq1, bq1, Wq2, bq2,
                   Xtgt + (size_t)b * CIN * HW + n0,
                   qr + (size_t)b * CC * HW + n0, tid, wm, wn, qid, tq, aLane, bLane);
    }
}

// ============================================================================
// S[b,c,d] += sum_n V K^T (+ fused Z), 4-stage cp.async pipeline
// ============================================================================
__global__ void __launch_bounds__(256, 2)
s_bf(const __nv_bfloat16* __restrict__ V, const __nv_bfloat16* __restrict__ Kt,
     float* __restrict__ S, float* __restrict__ Z) {
    extern __shared__ __nv_bfloat16 hsm[];
    const int tid = threadIdx.x;
    const int b = blockIdx.y;
    const int n0 = blockIdx.x * SCHUNK;
    const int warp = tid >> 5, lane = tid & 31;
    const int wm = warp >> 1, wn = warp & 1;
    const int qid = lane >> 2, tq = lane & 3;
    const __nv_bfloat16* Vb = V + (size_t)b * CC * HW + n0;
    const __nv_bfloat16* Kb = Kt + (size_t)b * CC * HW + n0;
    constexpr int NKB = SCHUNK / 32;

    float acc[2][8][4];
    zero_acc(acc);
    float zp[2] = {0.f, 0.f};
    const uint32_t sbase = (uint32_t)__cvta_generic_to_shared(hsm);
    const uint32_t lLane = ((lane & 15) * KPAD + (lane >> 4) * 8) * 2;
    const int frow = tid >> 2;
    const int fk8 = (tid & 3) * 8;

    auto issue_fill = [&](int stage, int k0) {
        uint32_t vdst = sbase + (stage * SSTG_ELEMS) * 2;
        uint32_t kdst = vdst + HA_STG * 2;
#pragma unroll
        for (int t = 0; t < 2; t++) {
            int row = frow + 64 * t;
            cpa16(vdst + (row * KPAD + fk8) * 2, Vb + (size_t)row * HW + k0 + fk8);
            cpa16(kdst + (row * KPAD + fk8) * 2, Kb + (size_t)row * HW + k0 + fk8);
        }
        CPA_COMMIT();
    };

    issue_fill(0, 0);
    issue_fill(1, 32);
    issue_fill(2, 64);

    for (int kb = 0; kb < NKB; kb++) {
        if (kb < NKB - 2)       asm volatile("cp.async.wait_group 2;" ::: "memory");
        else if (kb == NKB - 2) asm volatile("cp.async.wait_group 1;" ::: "memory");
        else                    asm volatile("cp.async.wait_group 0;" ::: "memory");
        __syncthreads();
        if (kb + 3 < NKB) issue_fill((kb + 3) & (SSTAGES - 1), (kb + 3) * 32);

        const int st = kb & (SSTAGES - 1);
        {
            const __nv_bfloat16* Kd = hsm + st * SSTG_ELEMS + HA_STG;
#pragma unroll
            for (int t = 0; t < 2; t++) {
                int row = frow + 64 * t;
                uint4 kv4 = *(const uint4*)(Kd + row * KPAD + fk8);
                const __nv_bfloat162* h = (const __nv_bfloat162*)&kv4;
#pragma unroll
                for (int j = 0; j < 4; j++) {
                    float2 f2 = __bfloat1622float2(h[j]);
                    zp[t] += f2.x + f2.y;
                }
            }
        }
        const uint32_t sA = sbase + (st * SSTG_ELEMS) * 2;
        const uint32_t sB = sA + HA_STG * 2;
#pragma unroll
        for (int kk = 0; kk < 2; kk++) {
            uint32_t a[2][4], bq[8][2];
#pragma unroll
            for (int mw = 0; mw < 2; mw++)
                ldsm4(a[mw], sA + ((wm * 32 + mw * 16) * KPAD) * 2 + kk * 32 + lLane);
#pragma unroll
            for (int ng = 0; ng < 4; ng++) {
                uint32_t r[4];
                ldsm4(r, sB + ((wn * 64 + ng * 16) * KPAD) * 2 + kk * 32 + lLane);
                bq[2 * ng][0] = r[0]; bq[2 * ng][1] = r[2];
                bq[2 * ng + 1][0] = r[1]; bq[2 * ng + 1][1] = r[3];
            }
#pragma unroll
            for (int mw = 0; mw < 2; mw++)
#pragma unroll
                for (int nw = 0; nw < 8; nw++)
                    mma16(acc[mw][nw], a[mw], bq[nw]);
        }
        __syncthreads();
    }

#pragma unroll
    for (int o = 1; o < 4; o <<= 1) {
        zp[0] += __shfl_xor_sync(0xffffffff, zp[0], o);
        zp[1] += __shfl_xor_sync(0xffffffff, zp[1], o);
    }
    if ((lane & 3) == 0) {
        atomicAdd(&Z[b * CC + (tid >> 2)], zp[0]);
        atomicAdd(&Z[b * CC + 64 + (tid >> 2)], zp[1]);
    }

    float* Sb = S + (size_t)b * CC * CC;
#pragma unroll
    for (int mw = 0; mw < 2; mw++) {
        const int r0 = wm * 32 + mw * 16 + qid;
#pragma unroll
        for (int nw = 0; nw < 8; nw++) {
            const int col = wn * 64 + nw * 8 + tq * 2;
            atomicAdd(&Sb[(size_t)r0 * CC + col],           acc[mw][nw][0]);
            atomicAdd(&Sb[(size_t)r0 * CC + col + 1],       acc[mw][nw][1]);
            atomicAdd(&Sb[(size_t)(r0 + 8) * CC + col],     acc[mw][nw][2]);
            atomicAdd(&Sb[(size_t)(r0 + 8) * CC + col + 1], acc[mw][nw][3]);
        }
    }
}

// ============================================================================
// out GEMM (bf16 MMA, den fused, S converted in-kernel)
// ============================================================================
__global__ void __launch_bounds__(256, 2)
out_bf(const float* __restrict__ Sg, const __nv_bfloat16* __restrict__ Q,
       const float* __restrict__ Zvec, float* __restrict__ Y) {
    extern __shared__ __nv_bfloat16 hsm[];
    float* den_s = (float*)(hsm + O_ELEMS);
    float* Zs = den_s + 128;
    const int tid = threadIdx.x;
    const int b = blockIdx.y;
    const int n0 = blockIdx.x * 128;
    const int warp = tid >> 5, lane = tid & 31;
    const int wm = warp >> 1, wn = warp & 1;
    const int qid = lane >> 2, tq = lane & 3;
    const uint32_t sbase = (uint32_t)__cvta_generic_to_shared(hsm);
    const uint32_t aLane2 = ((lane & 15) * A2PAD + (lane >> 4) * 8) * 2;
    const uint32_t bLane = ((lane & 15) * NPAD + (lane >> 4) * 8) * 2;
    const float* Ab = Sg + (size_t)b * CC * CC;
    const __nv_bfloat16* Xb = Q + (size_t)b * CC * HW + n0;

    // B: q tile via cp.async (8 x 16B per thread)
    {
        uint32_t dst = sbase + OB_OFF * 2;
        const int n8 = (tid & 15) * 8;
#pragma unroll
        for (int t = 0; t < 8; t++) {
            int k = (tid >> 4) + t * 16;
            cpa16(dst + (k * NPAD + n8) * 2, Xb + (size_t)k * HW + n8);
        }
        CPA_COMMIT();
    }
    if (tid < 128) { Zs[tid] = Zvec[b * CC + tid]; den_s[tid] = 0.f; }
    // A: S fp32 -> bf16 smem (stride A2PAD)
    {
        __nv_bfloat16* A2s = hsm + OA_OFF;
#pragma unroll
        for (int t = 0; t < 16; t++) {
            int id = tid + t * 256;
            int m = id >> 5, k4 = (id & 31) * 4;
            float4 v = *(const float4*)(Ab + (size_t)m * CC + k4);
            st4h(A2s + (size_t)m * A2PAD + k4, v);
        }
    }
    CPA_WAIT0();
    __syncthreads();

    // den from smem q (bf16 == gmem values)
    {
        const __nv_bfloat16* B2s = hsm + OB_OFF;
        const int n8 = (tid & 15) * 8;
        float dreg[8] = {0.f, 0.f, 0.f, 0.f, 0.f, 0.f, 0.f, 0.f};
#pragma unroll
        for (int t = 0; t < 8; t++) {
            int k = (tid >> 4) + t * 16;
            uint4 q4 = *(const uint4*)(B2s + (size_t)k * NPAD + n8);
            float z = Zs[k];
            const __nv_bfloat162* h = (const __nv_bfloat162*)&q4;
#pragma unroll
            for (int j = 0; j < 4; j++) {
                float2 f2 = __bfloat1622float2(h[j]);
                dreg[2 * j]     = fmaf(z, f2.x, dreg[2 * j]);
                dreg[2 * j + 1] = fmaf(z, f2.y, dreg[2 * j + 1]);
            }
        }
#pragma unroll
        for (int j = 0; j < 8; j++) atomicAdd(&den_s[n8 + j], dreg[j]);
    }
    __syncthreads();

    float acc[2][8][4];
    zero_acc(acc);
    mainloop2p(acc, sbase, OA_OFF * 2, OB_OFF * 2, wm, wn, aLane2, bLane);

    float* Yb = Y + (size_t)b * CC * HW + n0;
#pragma unroll
    for (int mw = 0; mw < 2; mw++) {
        const int r0 = wm * 32 + mw * 16 + qid;
#pragma unroll
        for (int nw = 0; nw < 8; nw++) {
            const int col = wn * 64 + nw * 8 + tq * 2;
            float i0 = 1.f / fmaxf(den_s[col], 1e-12f);
            float i1 = 1.f / fmaxf(den_s[col + 1], 1e-12f);
            float2 p0 = { acc[mw][nw][0] * i0, acc[mw][nw][1] * i1 };
            float2 p1 = { acc[mw][nw][2] * i0, acc[mw][nw][3] * i1 };
            *(float2*)(Yb + (size_t)r0 * HW + col) = p0;
            *(float2*)(Yb + (size_t)(r0 + 8) * HW + col) = p1;
        }
    }
}

// ---------------- launch ----------------
extern "C" void kernel_launch(void* const* d_in, const int* in_sizes, int n_in,
                              void* d_out, int out_size) {
    const float* target = (const float*)d_in[0];
    const float* source = (const float*)d_in[1];
    const float* q_w1 = (const float*)d_in[2];
    const float* q_w2 = (const float*)d_in[3];
    const float* k_w1 = (const float*)d_in[4];
    const float* k_w2 = (const float*)d_in[5];
    const float* v_w  = (const float*)d_in[6];

    __nv_bfloat16 *wkvh, *wq1h, *wq2h, *wk2h, *val, *key, *qr;
    float *bkv, *bq1, *bq2, *bk2, *S, *Z;
    cudaGetSymbolAddress((void**)&wkvh, g_wkvh);
    cudaGetSymbolAddress((void**)&wq1h, g_wq1h);
    cudaGetSymbolAddress((void**)&wq2h, g_wq2h);
    cudaGetSymbolAddress((void**)&wk2h, g_wk2h);
    cudaGetSymbolAddress((void**)&bkv, g_bkv);
    cudaGetSymbolAddress((void**)&bq1, g_bq1);
    cudaGetSymbolAddress((void**)&bq2, g_bq2);
    cudaGetSymbolAddress((void**)&bk2, g_bk2);
    cudaGetSymbolAddress((void**)&val, g_val);
    cudaGetSymbolAddress((void**)&key, g_key);
    cudaGetSymbolAddress((void**)&qr,  g_qr);
    cudaGetSymbolAddress((void**)&S,   g_S);
    cudaGetSymbolAddress((void**)&Z,   g_Z);

    cudaFuncSetAttribute(conv_all, cudaFuncAttributeMaxDynamicSharedMemorySize, CHAIN_SM_BYTES);
    cudaFuncSetAttribute(s_bf,  cudaFuncAttributeMaxDynamicSharedMemorySize, SSM_BYTES);
    cudaFuncSetAttribute(out_bf, cudaFuncAttributeMaxDynamicSharedMemorySize, OSM_BYTES);

    PrepAll pa;
    pa.e[0] = { k_w1, (const float*)d_in[15], (const float*)d_in[16], (const float*)d_in[17], (const float*)d_in[18], wkvh, bkv, CIN };
    pa.e[1] = { v_w,  (const float*)d_in[23], (const float*)d_in[24], (const float*)d_in[25], (const float*)d_in[26], wkvh + CC * CIN, bkv + CC, CIN };
    pa.e[2] = { q_w1, (const float*)d_in[7],  (const float*)d_in[8],  (const float*)d_in[9],  (const float*)d_in[10], wq1h, bq1, CIN };
    pa.e[3] = { q_w2, (const float*)d_in[11], (const float*)d_in[12], (const float*)d_in[13], (const float*)d_in[14], wq2h, bq2, CC };
    pa.e[4] = { k_w2, (const float*)d_in[19], (const float*)d_in[20], (const float*)d_in[21], (const float*)d_in[22], wk2h, bk2, CC };
    fold5<<<dim3(CC, 5), 256>>>(pa);

    cudaMemsetAsync(S, 0, BB * CC * CC * sizeof(float));
    cudaMemsetAsync(Z, 0, BB * CC * sizeof(float));

    conv_all<<<dim3(HW / 128 * 3, BB), 256, CHAIN_SM_BYTES>>>(
        wkvh, bkv, wk2h, bk2, wq1h, bq1, wq2h, bq2, source, target, val, key, qr);
    s_bf<<<dim3(NSPLIT, BB), 256, SSM_BYTES>>>(val, key, S, Z);
    out_bf<<<dim3(HW / 128, BB), 256, OSM_BYTES>>>(S, qr, Z, (float*)d_out);
}

// round 15
// speedup vs baseline: 4.4946x; 1.0102x over previous
#include <cuda_runtime.h>
#include <cuda_bf16.h>
#include <math.h>
#include <stdint.h>

#define BB 8
#define CIN 256
#define CC 128
#define HW 16384
#define NSPLIT 32
#define SCHUNK 512

#define KPAD 40
#define NPAD 136
#define A2PAD 136
#define HA_STG (128 * KPAD)      // 5120 elems
#define HB_STG (32 * NPAD)       // 4352 elems

// chain kernel smem layout (bf16 elems); A pipeline = 4 stages
#define ASTAGES 4
#define AS_OFF 0
#define BS_OFF (AS_OFF + ASTAGES * HA_STG)    // 20480
#define P1_ELEMS (BS_OFF + 2 * HB_STG)        // 29184
#define A2_OFF 0
#define B2_OFF P1_ELEMS                        // 29184
#define CHAIN_ELEMS (B2_OFF + 128 * NPAD)      // 46592
#define CHAIN_SM_BYTES (CHAIN_ELEMS * 2)       // 93184

// s_bf: 4-stage cp.async pipeline
#define SSTAGES 4
#define SSTG_ELEMS (2 * HA_STG)
#define SSM_BYTES (SSTAGES * SSTG_ELEMS * 2)   // 81920

// out_bf v2: 2 n-tiles, double-buffered B
#define OA_OFF 0
#define OB_OFF (128 * A2PAD)                   // 17408
#define OB_STG (128 * NPAD)                    // 17408
#define O_ELEMS (OB_OFF + 2 * OB_STG)          // 52224
#define OSM_BYTES (O_ELEMS * 2 + 384 * 4)      // 105984

// ---------------- scratch ----------------
__device__ __nv_bfloat16 g_wkvh[2 * CC * CIN];
__device__ __nv_bfloat16 g_wq1h[CC * CIN];
__device__ __nv_bfloat16 g_wq2h[CC * CC];
__device__ __nv_bfloat16 g_wk2h[CC * CC];
__device__ float g_bkv[2 * CC], g_bq1[CC], g_bq2[CC], g_bk2[CC];
__device__ __nv_bfloat16 g_val[(size_t)BB * CC * HW];
__device__ __nv_bfloat16 g_key[(size_t)BB * CC * HW];
__device__ __nv_bfloat16 g_qr [(size_t)BB * CC * HW];
__device__ float g_S[BB * CC * CC];
__device__ float g_Z[BB * CC];

// ---------------- helpers ----------------
__device__ __forceinline__ void st4h(__nv_bfloat16* p, float4 v) {
    __nv_bfloat162 lo = __floats2bfloat162_rn(v.x, v.y);
    __nv_bfloat162 hi = __floats2bfloat162_rn(v.z, v.w);
    uint2 u = { *(uint32_t*)&lo, *(uint32_t*)&hi };
    *(uint2*)p = u;
}
__device__ __forceinline__ void ldsm4(uint32_t* r, uint32_t a) {
    asm volatile("ldmatrix.sync.aligned.m8n8.x4.shared.b16 {%0,%1,%2,%3}, [%4];"
                 : "=r"(r[0]), "=r"(r[1]), "=r"(r[2]), "=r"(r[3]) : "r"(a));
}
__device__ __forceinline__ void ldsm4t(uint32_t* r, uint32_t a) {
    asm volatile("ldmatrix.sync.aligned.m8n8.x4.trans.shared.b16 {%0,%1,%2,%3}, [%4];"
                 : "=r"(r[0]), "=r"(r[1]), "=r"(r[2]), "=r"(r[3]) : "r"(a));
}
__device__ __forceinline__ void mma16(float* c, const uint32_t* a, const uint32_t* b) {
    asm volatile("mma.sync.aligned.m16n8k16.row.col.f32.bf16.bf16.f32 "
                 "{%0,%1,%2,%3}, {%4,%5,%6,%7}, {%8,%9}, {%0,%1,%2,%3};"
                 : "+f"(c[0]), "+f"(c[1]), "+f"(c[2]), "+f"(c[3])
                 : "r"(a[0]), "r"(a[1]), "r"(a[2]), "r"(a[3]), "r"(b[0]), "r"(b[1]));
}
__device__ __forceinline__ void cpa16(uint32_t dst, const void* src) {
    asm volatile("cp.async.cg.shared.global [%0], [%1], 16;" :: "r"(dst), "l"(src));
}
#define CPA_COMMIT() asm volatile("cp.async.commit_group;" ::: "memory")
#define CPA_WAIT0()  asm volatile("cp.async.wait_group 0;" ::: "memory")
#define CPA_WAIT1()  asm volatile("cp.async.wait_group 1;" ::: "memory")
#define CPA_WAIT2()  asm volatile("cp.async.wait_group 2;" ::: "memory")
__device__ __forceinline__ float softplus_fast(float x) {
    return fmaxf(x, 0.f) + log1pf(__expf(-fabsf(x)));
}

// ---------------- merged BN fold (weights -> bf16) ----------------
struct PrepEnt { const float *w, *g, *b, *m, *v; __nv_bfloat16* wf; float* bf; int K; };
struct PrepAll { PrepEnt e[5]; };

__global__ void fold5(PrepAll a) {
    PrepEnt p = a.e[blockIdx.y];
    int o = blockIdx.x;
    float s = p.g[o] * rsqrtf(p.v[o] + 1e-5f);
    if (threadIdx.x == 0) p.bf[o] = p.b[o] - p.m[o] * s;
    for (int c = threadIdx.x; c < p.K; c += blockDim.x)
        p.wf[o * p.K + c] = __float2bfloat16(p.w[o * p.K + c] * s);
}

__device__ __forceinline__ void zero_acc(float acc[2][8][4]) {
#pragma unroll
    for (int i = 0; i < 2; i++)
#pragma unroll
        for (int j = 0; j < 8; j++)
#pragma unroll
            for (int l = 0; l < 4; l++) acc[i][j][l] = 0.f;
}

// ---------------- phase-1: A bf16 4-stage cp.async, B fp32 reg-prefetch ----
__device__ __forceinline__ void mainloop1(float acc[2][8][4], __nv_bfloat16* hsm,
                                          uint32_t sbase, const __nv_bfloat16* Ab,
                                          const float* Xb, int tid, int wm, int wn,
                                          uint32_t aLane, uint32_t bLane) {
    __nv_bfloat16* Bs = hsm + BS_OFF;
    const int bk = tid >> 5, bn = (tid & 31) * 4;
    auto fillA = [&](int stage, int k0) {
        uint32_t dst = sbase + (AS_OFF + stage * HA_STG) * 2;
#pragma unroll
        for (int t = 0; t < 2; t++) {
            int id = tid + t * 256;
            int row = id >> 2, k8 = (id & 3) * 8;
            cpa16(dst + (row * KPAD + k8) * 2, Ab + (size_t)row * CIN + k0 + k8);
        }
        CPA_COMMIT();
    };
    fillA(0, 0);
    fillA(1, 32);
    fillA(2, 64);
#pragma unroll
    for (int i = 0; i < 4; i++) {
        int k = bk + 8 * i;
        float4 v = *(const float4*)(Xb + (size_t)k * HW + bn);
        st4h(Bs + k * NPAD + bn, v);
    }
    CPA_WAIT2();
    __syncthreads();

    constexpr int NKB = CIN / 32;
    for (int kb = 0; kb < NKB; kb++) {
        if (kb + 3 < NKB) fillA((kb + 3) & (ASTAGES - 1), (kb + 3) * 32);
        float4 rb[4];
        if (kb + 1 < NKB) {
            const int k0 = (kb + 1) * 32;
#pragma unroll
            for (int i = 0; i < 4; i++)
                rb[i] = *(const float4*)(Xb + (size_t)(k0 + bk + 8 * i) * HW + bn);
        }
        const uint32_t sA = sbase + (AS_OFF + (kb & (ASTAGES - 1)) * HA_STG) * 2;
        const uint32_t sB = sbase + (BS_OFF + (kb & 1) * HB_STG) * 2;
#pragma unroll
        for (int kk = 0; kk < 2; kk++) {
            uint32_t a[2][4], bq[8][2];
#pragma unroll
            for (int mw = 0; mw < 2; mw++)
                ldsm4(a[mw], sA + ((wm * 32 + mw * 16) * KPAD) * 2 + kk * 32 + aLane);
#pragma unroll
            for (int ng = 0; ng < 4; ng++) {
                uint32_t r[4];
                ldsm4t(r, sB + (kk * 16 * NPAD + wn * 64 + ng * 16) * 2 + bLane);
                bq[2 * ng][0] = r[0]; bq[2 * ng][1] = r[1];
                bq[2 * ng + 1][0] = r[2]; bq[2 * ng + 1][1] = r[3];
            }
#pragma unroll
            for (int mw = 0; mw < 2; mw++)
#pragma unroll
                for (int nw = 0; nw < 8; nw++)
                    mma16(acc[mw][nw], a[mw], bq[nw]);
        }
        if (kb + 1 < NKB) {
            __nv_bfloat16* Bd = Bs + ((kb + 1) & 1) * HB_STG;
#pragma unroll
            for (int i = 0; i < 4; i++)
                st4h(Bd + (bk + 8 * i) * NPAD + bn, rb[i]);
            // wait for A(kb+1); groups issued after it: min(2, NKB-2-kb)
            const int rem = NKB - 2 - kb;
            if (rem >= 2)      CPA_WAIT2();
            else if (rem == 1) CPA_WAIT1();
            else               CPA_WAIT0();
        }
        __syncthreads();
    }
}

// ---------------- smem-resident K=128 mainloop ----------------
__device__ __forceinline__ void mainloop2p(float acc[2][8][4], uint32_t sbase,
                                           uint32_t a_off_b, uint32_t b_off_b,
                                           int wm, int wn, uint32_t aLane2,
                                           uint32_t bLane) {
    const uint32_t sA2 = sbase + a_off_b;
    const uint32_t sB2 = sbase + b_off_b;
#pragma unroll
    for (int kb = 0; kb < 4; kb++) {
#pragma unroll
        for (int kk = 0; kk < 2; kk++) {
            const int kofs = kb * 32 + kk * 16;
            uint32_t a[2][4], bq[8][2];
#pragma unroll
            for (int mw = 0; mw < 2; mw++)
                ldsm4(a[mw], sA2 + ((wm * 32 + mw * 16) * A2PAD + kofs) * 2 + aLane2);
#pragma unroll
            for (int ng = 0; ng < 4; ng++) {
                uint32_t r[4];
                ldsm4t(r, sB2 + ((size_t)kofs * NPAD + wn * 64 + ng * 16) * 2 + bLane);
                bq[2 * ng][0] = r[0]; bq[2 * ng][1] = r[1];
                bq[2 * ng + 1][0] = r[2]; bq[2 * ng + 1][1] = r[3];
            }
#pragma unroll
            for (int mw = 0; mw < 2; mw++)
#pragma unroll
                for (int nw = 0; nw < 8; nw++)
                    mma16(acc[mw][nw], a[mw], bq[nw]);
        }
    }
}

// ---------------- chain body ----------------
__device__ __forceinline__ void chain_body(__nv_bfloat16* hsm, uint32_t sbase,
                                           const __nv_bfloat16* W1, const float* b1,
                                           const __nv_bfloat16* W2, const float* b2,
                                           const float* Xb, __nv_bfloat16* Yout,
                                           int tid, int wm, int wn, int qid, int tq,
                                           uint32_t aLane, uint32_t bLane) {
    const int lane = tid & 31;
    const uint32_t aLane2 = ((lane & 15) * A2PAD + (lane >> 4) * 8) * 2;

    float acc[2][8][4];
    zero_acc(acc);
    mainloop1(acc, hsm, sbase, W1, Xb, tid, wm, wn, aLane, bLane);
    // AS/BS dead after final sync; alias A2 over them.

    {
        uint32_t dst = sbase + A2_OFF * 2;
#pragma unroll
        for (int t = 0; t < 8; t++) {
            int id = tid + t * 256;
            int m = id >> 4, k8 = (id & 15) * 8;
            cpa16(dst + (m * A2PAD + k8) * 2, W2 + (size_t)m * CC + k8);
        }
        CPA_COMMIT();
    }
    {
        __nv_bfloat16* B2s = hsm + B2_OFF;
#pragma unroll
        for (int mw = 0; mw < 2; mw++) {
            const int r0 = wm * 32 + mw * 16 + qid;
            float bv0 = b1[r0], bv1 = b1[r0 + 8];
#pragma unroll
            for (int nw = 0; nw < 8; nw++) {
                const int col = wn * 64 + nw * 8 + tq * 2;
                __nv_bfloat162 p0 = __floats2bfloat162_rn(
                    fmaxf(acc[mw][nw][0] + bv0, 0.f), fmaxf(acc[mw][nw][1] + bv0, 0.f));
                __nv_bfloat162 p1 = __floats2bfloat162_rn(
                    fmaxf(acc[mw][nw][2] + bv1, 0.f), fmaxf(acc[mw][nw][3] + bv1, 0.f));
                *(__nv_bfloat162*)(B2s + (size_t)r0 * NPAD + col) = p0;
                *(__nv_bfloat162*)(B2s + (size_t)(r0 + 8) * NPAD + col) = p1;
            }
        }
    }
    CPA_WAIT0();
    __syncthreads();

    zero_acc(acc);
    mainloop2p(acc, sbase, A2_OFF * 2, B2_OFF * 2, wm, wn, aLane2, bLane);

#pragma unroll
    for (int mw = 0; mw < 2; mw++) {
        const int r0 = wm * 32 + mw * 16 + qid;
        float bv0 = b2[r0], bv1 = b2[r0 + 8];
#pragma unroll
        for (int nw = 0; nw < 8; nw++) {
            const int col = wn * 64 + nw * 8 + tq * 2;
            __nv_bfloat162 p0 = __floats2bfloat162_rn(
                softplus_fast(acc[mw][nw][0] + bv0), softplus_fast(acc[mw][nw][1] + bv0));
            __nv_bfloat162 p1 = __floats2bfloat162_rn(
                softplus_fast(acc[mw][nw][2] + bv1), softplus_fast(acc[mw][nw][3] + bv1));
            *(__nv_bfloat162*)(Yout + (size_t)r0 * HW + col) = p0;
            *(__nv_bfloat162*)(Yout + (size_t)(r0 + 8) * HW + col) = p1;
        }
    }
}

// ---------------- merged conv kernel ----------------
__global__ void __launch_bounds__(256, 2)
conv_all(const __nv_bfloat16* __restrict__ Wkv, const float* __restrict__ bkv,
         const __nv_bfloat16* __restrict__ Wk2, const float* __restrict__ bk2,
         const __nv_bfloat16* __restrict__ Wq1, const float* __restrict__ bq1,
         const __nv_bfloat16* __restrict__ Wq2, const float* __restrict__ bq2,
         const float* __restrict__ Xsrc, const float* __restrict__ Xtgt,
         __nv_bfloat16* __restrict__ val, __nv_bfloat16* __restrict__ key,
         __nv_bfloat16* __restrict__ qr) {
    extern __shared__ __nv_bfloat16 hsm[];
    const int tid = threadIdx.x;
    const int b = blockIdx.y;
    const int role = blockIdx.x % 3;
    const int n0 = (blockIdx.x / 3) * 128;
    const int warp = tid >> 5, lane = tid & 31;
    const int wm = warp >> 1, wn = warp & 1;
    const int qid = lane >> 2, tq = lane & 3;
    const uint32_t sbase = (uint32_t)__cvta_generic_to_shared(hsm);
    const uint32_t aLane = ((lane & 15) * KPAD + (lane >> 4) * 8) * 2;
    const uint32_t bLane = ((lane & 15) * NPAD + (lane >> 4) * 8) * 2;

    if (role == 1) {
        const float* Xb = Xsrc + (size_t)b * CIN * HW + n0;
        float acc[2][8][4];
        zero_acc(acc);
        mainloop1(acc, hsm, sbase, Wkv + (size_t)128 * CIN, Xb, tid, wm, wn, aLane, bLane);
        __nv_bfloat16* Yb = val + (size_t)b * CC * HW + n0;
        const float* bp = bkv + 128;
#pragma unroll
        for (int mw = 0; mw < 2; mw++) {
            const int r0 = wm * 32 + mw * 16 + qid;
            float bv0 = bp[r0], bv1 = bp[r0 + 8];
#pragma unroll
            for (int nw = 0; nw < 8; nw++) {
                const int col = wn * 64 + nw * 8 + tq * 2;
                __nv_bfloat162 p0 = __floats2bfloat162_rn(
                    fmaxf(acc[mw][nw][0] + bv0, 0.f), fmaxf(acc[mw][nw][1] + bv0, 0.f));
                __nv_bfloat162 p1 = __floats2bfloat162_rn(
                    fmaxf(acc[mw][nw][2] + bv1, 0.f), fmaxf(acc[mw][nw][3] + bv1, 0.f));
                *(__nv_bfloat162*)(Yb + (size_t)r0 * HW + col) = p0;
                *(__nv_bfloat162*)(Yb + (size_t)(r0 + 8) * HW + col) = p1;
            }
        }
    } else if (role == 0) {
        chain_body(hsm, sbase, Wkv, bkv, Wk2, bk2,
                   Xsrc + (size_t)b * CIN * HW + n0,
                   key + (size_t)b * CC * HW + n0, tid, wm, wn, qid, tq, aLane, bLane);
    } else {
        chain_body(hsm, sbase, Wq1, bq1, Wq2, bq2,
                   Xtgt + (size_t)b * CIN * HW + n0,
                   qr + (size_t)b * CC * HW + n0, tid, wm, wn, qid, tq, aLane, bLane);
    }
}

// ============================================================================
// S[b,c,d] += sum_n V K^T (+ fused Z), 4-stage cp.async pipeline
// ============================================================================
__global__ void __launch_bounds__(256, 2)
s_bf(const __nv_bfloat16* __restrict__ V, const __nv_bfloat16* __restrict__ Kt,
     float* __restrict__ S, float* __restrict__ Z) {
    extern __shared__ __nv_bfloat16 hsm[];
    const int tid = threadIdx.x;
    const int b = blockIdx.y;
    const int n0 = blockIdx.x * SCHUNK;
    const int warp = tid >> 5, lane = tid & 31;
    const int wm = warp >> 1, wn = warp & 1;
    const int qid = lane >> 2, tq = lane & 3;
    const __nv_bfloat16* Vb = V + (size_t)b * CC * HW + n0;
    const __nv_bfloat16* Kb = Kt + (size_t)b * CC * HW + n0;
    constexpr int NKB = SCHUNK / 32;

    float acc[2][8][4];
    zero_acc(acc);
    float zp[2] = {0.f, 0.f};
    const uint32_t sbase = (uint32_t)__cvta_generic_to_shared(hsm);
    const uint32_t lLane = ((lane & 15) * KPAD + (lane >> 4) * 8) * 2;
    const int frow = tid >> 2;
    const int fk8 = (tid & 3) * 8;

    auto issue_fill = [&](int stage, int k0) {
        uint32_t vdst = sbase + (stage * SSTG_ELEMS) * 2;
        uint32_t kdst = vdst + HA_STG * 2;
#pragma unroll
        for (int t = 0; t < 2; t++) {
            int row = frow + 64 * t;
            cpa16(vdst + (row * KPAD + fk8) * 2, Vb + (size_t)row * HW + k0 + fk8);
            cpa16(kdst + (row * KPAD + fk8) * 2, Kb + (size_t)row * HW + k0 + fk8);
        }
        CPA_COMMIT();
    };

    issue_fill(0, 0);
    issue_fill(1, 32);
    issue_fill(2, 64);

    for (int kb = 0; kb < NKB; kb++) {
        if (kb < NKB - 2)       CPA_WAIT2();
        else if (kb == NKB - 2) CPA_WAIT1();
        else                    CPA_WAIT0();
        __syncthreads();
        if (kb + 3 < NKB) issue_fill((kb + 3) & (SSTAGES - 1), (kb + 3) * 32);

        const int st = kb & (SSTAGES - 1);
        {
            const __nv_bfloat16* Kd = hsm + st * SSTG_ELEMS + HA_STG;
#pragma unroll
            for (int t = 0; t < 2; t++) {
                int row = frow + 64 * t;
                uint4 kv4 = *(const uint4*)(Kd + row * KPAD + fk8);
                const __nv_bfloat162* h = (const __nv_bfloat162*)&kv4;
#pragma unroll
                for (int j = 0; j < 4; j++) {
                    float2 f2 = __bfloat1622float2(h[j]);
                    zp[t] += f2.x + f2.y;
                }
            }
        }
        const uint32_t sA = sbase + (st * SSTG_ELEMS) * 2;
        const uint32_t sB = sA + HA_STG * 2;
#pragma unroll
        for (int kk = 0; kk < 2; kk++) {
            uint32_t a[2][4], bq[8][2];
#pragma unroll
            for (int mw = 0; mw < 2; mw++)
                ldsm4(a[mw], sA + ((wm * 32 + mw * 16) * KPAD) * 2 + kk * 32 + lLane);
#pragma unroll
            for (int ng = 0; ng < 4; ng++) {
                uint32_t r[4];
                ldsm4(r, sB + ((wn * 64 + ng * 16) * KPAD) * 2 + kk * 32 + lLane);
                bq[2 * ng][0] = r[0]; bq[2 * ng][1] = r[2];
                bq[2 * ng + 1][0] = r[1]; bq[2 * ng + 1][1] = r[3];
            }
#pragma unroll
            for (int mw = 0; mw < 2; mw++)
#pragma unroll
                for (int nw = 0; nw < 8; nw++)
                    mma16(acc[mw][nw], a[mw], bq[nw]);
        }
        __syncthreads();
    }

#pragma unroll
    for (int o = 1; o < 4; o <<= 1) {
        zp[0] += __shfl_xor_sync(0xffffffff, zp[0], o);
        zp[1] += __shfl_xor_sync(0xffffffff, zp[1], o);
    }
    if ((lane & 3) == 0) {
        atomicAdd(&Z[b * CC + (tid >> 2)], zp[0]);
        atomicAdd(&Z[b * CC + 64 + (tid >> 2)], zp[1]);
    }

    float* Sb = S + (size_t)b * CC * CC;
#pragma unroll
    for (int mw = 0; mw < 2; mw++) {
        const int r0 = wm * 32 + mw * 16 + qid;
#pragma unroll
        for (int nw = 0; nw < 8; nw++) {
            const int col = wn * 64 + nw * 8 + tq * 2;
            atomicAdd(&Sb[(size_t)r0 * CC + col],           acc[mw][nw][0]);
            atomicAdd(&Sb[(size_t)r0 * CC + col + 1],       acc[mw][nw][1]);
            atomicAdd(&Sb[(size_t)(r0 + 8) * CC + col],     acc[mw][nw][2]);
            atomicAdd(&Sb[(size_t)(r0 + 8) * CC + col + 1], acc[mw][nw][3]);
        }
    }
}

// ============================================================================
// out GEMM v2: 2 n-tiles per CTA, double-buffered B, A(S) amortized
// ============================================================================
__global__ void __launch_bounds__(256, 2)
out_bf(const float* __restrict__ Sg, const __nv_bfloat16* __restrict__ Q,
       const float* __restrict__ Zvec, float* __restrict__ Y) {
    extern __shared__ __nv_bfloat16 hsm[];
    float* den_s = (float*)(hsm + O_ELEMS);     // 256 entries (2 tiles)
    float* Zs = den_s + 256;                    // 128 entries
    const int tid = threadIdx.x;
    const int b = blockIdx.y;
    const int n0 = blockIdx.x * 256;
    const int warp = tid >> 5, lane = tid & 31;
    const int wm = warp >> 1, wn = warp & 1;
    const int qid = lane >> 2, tq = lane & 3;
    const uint32_t sbase = (uint32_t)__cvta_generic_to_shared(hsm);
    const uint32_t aLane2 = ((lane & 15) * A2PAD + (lane >> 4) * 8) * 2;
    const uint32_t bLane = ((lane & 15) * NPAD + (lane >> 4) * 8) * 2;
    const float* Ab = Sg + (size_t)b * CC * CC;

    // issue both q tiles via cp.async (one commit group per tile)
    const int n8 = (tid & 15) * 8;
#pragma unroll
    for (int t2 = 0; t2 < 2; t2++) {
        const __nv_bfloat16* Xb = Q + (size_t)b * CC * HW + n0 + t2 * 128;
        uint32_t dst = sbase + (OB_OFF + t2 * OB_STG) * 2;
#pragma unroll
        for (int t = 0; t < 8; t++) {
            int k = (tid >> 4) + t * 16;
            cpa16(dst + (k * NPAD + n8) * 2, Xb + (size_t)k * HW + n8);
        }
        CPA_COMMIT();
    }
    if (tid < 128) Zs[tid] = Zvec[b * CC + tid];
    if (tid < 256) den_s[tid] = 0.f;
    // A: S fp32 -> bf16 smem (done once, overlaps with both B copies)
    {
        __nv_bfloat16* A2s = hsm + OA_OFF;
#pragma unroll
        for (int t = 0; t < 16; t++) {
            int id = tid + t * 256;
            int m = id >> 5, k4 = (id & 31) * 4;
            float4 v = *(const float4*)(Ab + (size_t)m * CC + k4);
            st4h(A2s + (size_t)m * A2PAD + k4, v);
        }
    }

    for (int t2 = 0; t2 < 2; t2++) {
        if (t2 == 0) CPA_WAIT1(); else CPA_WAIT0();
        __syncthreads();
        // den from smem q
        {
            const __nv_bfloat16* B2s = hsm + OB_OFF + t2 * OB_STG;
            float dreg[8] = {0.f, 0.f, 0.f, 0.f, 0.f, 0.f, 0.f, 0.f};
#pragma unroll
            for (int t = 0; t < 8; t++) {
                int k = (tid >> 4) + t * 16;
                uint4 q4 = *(const uint4*)(B2s + (size_t)k * NPAD + n8);
                float z = Zs[k];
                const __nv_bfloat162* h = (const __nv_bfloat162*)&q4;
#pragma unroll
                for (int j = 0; j < 4; j++) {
                    float2 f2 = __bfloat1622float2(h[j]);
                    dreg[2 * j]     = fmaf(z, f2.x, dreg[2 * j]);
                    dreg[2 * j + 1] = fmaf(z, f2.y, dreg[2 * j + 1]);
                }
            }
            float* ds = den_s + t2 * 128;
#pragma unroll
            for (int j = 0; j < 8; j++) atomicAdd(&ds[n8 + j], dreg[j]);
        }
        __syncthreads();

        float acc[2][8][4];
        zero_acc(acc);
        mainloop2p(acc, sbase, OA_OFF * 2, (OB_OFF + t2 * OB_STG) * 2,
                   wm, wn, aLane2, bLane);

        float* Yb = Y + (size_t)b * CC * HW + n0 + t2 * 128;
        const float* ds = den_s + t2 * 128;
#pragma unroll
        for (int mw = 0; mw < 2; mw++) {
            const int r0 = wm * 32 + mw * 16 + qid;
#pragma unroll
            for (int nw = 0; nw < 8; nw++) {
                const int col = wn * 64 + nw * 8 + tq * 2;
                float i0 = 1.f / fmaxf(ds[col], 1e-12f);
                float i1 = 1.f / fmaxf(ds[col + 1], 1e-12f);
                float2 p0 = { acc[mw][nw][0] * i0, acc[mw][nw][1] * i1 };
                float2 p1 = { acc[mw][nw][2] * i0, acc[mw][nw][3] * i1 };
                *(float2*)(Yb + (size_t)r0 * HW + col) = p0;
                *(float2*)(Yb + (size_t)(r0 + 8) * HW + col) = p1;
            }
        }
    }
}

// ---------------- launch ----------------
extern "C" void kernel_launch(void* const* d_in, const int* in_sizes, int n_in,
                              void* d_out, int out_size) {
    const float* target = (const float*)d_in[0];
    const float* source = (const float*)d_in[1];
    const float* q_w1 = (const float*)d_in[2];
    const float* q_w2 = (const float*)d_in[3];
    const float* k_w1 = (const float*)d_in[4];
    const float* k_w2 = (const float*)d_in[5];
    const float* v_w  = (const float*)d_in[6];

    __nv_bfloat16 *wkvh, *wq1h, *wq2h, *wk2h, *val, *key, *qr;
    float *bkv, *bq1, *bq2, *bk2, *S, *Z;
    cudaGetSymbolAddress((void**)&wkvh, g_wkvh);
    cudaGetSymbolAddress((void**)&wq1h, g_wq1h);
    cudaGetSymbolAddress((void**)&wq2h, g_wq2h);
    cudaGetSymbolAddress((void**)&wk2h, g_wk2h);
    cudaGetSymbolAddress((void**)&bkv, g_bkv);
    cudaGetSymbolAddress((void**)&bq1, g_bq1);
    cudaGetSymbolAddress((void**)&bq2, g_bq2);
    cudaGetSymbolAddress((void**)&bk2, g_bk2);
    cudaGetSymbolAddress((void**)&val, g_val);
    cudaGetSymbolAddress((void**)&key, g_key);
    cudaGetSymbolAddress((void**)&qr,  g_qr);
    cudaGetSymbolAddress((void**)&S,   g_S);
    cudaGetSymbolAddress((void**)&Z,   g_Z);

    cudaFuncSetAttribute(conv_all, cudaFuncAttributeMaxDynamicSharedMemorySize, CHAIN_SM_BYTES);
    cudaFuncSetAttribute(s_bf,  cudaFuncAttributeMaxDynamicSharedMemorySize, SSM_BYTES);
    cudaFuncSetAttribute(out_bf, cudaFuncAttributeMaxDynamicSharedMemorySize, OSM_BYTES);

    PrepAll pa;
    pa.e[0] = { k_w1, (const float*)d_in[15], (const float*)d_in[16], (const float*)d_in[17], (const float*)d_in[18], wkvh, bkv, CIN };
    pa.e[1] = { v_w,  (const float*)d_in[23], (const float*)d_in[24], (const float*)d_in[25], (const float*)d_in[26], wkvh + CC * CIN, bkv + CC, CIN };
    pa.e[2] = { q_w1, (const float*)d_in[7],  (const float*)d_in[8],  (const float*)d_in[9],  (const float*)d_in[10], wq1h, bq1, CIN };
    pa.e[3] = { q_w2, (const float*)d_in[11], (const float*)d_in[12], (const float*)d_in[13], (const float*)d_in[14], wq2h, bq2, CC };
    pa.e[4] = { k_w2, (const float*)d_in[19], (const float*)d_in[20], (const float*)d_in[21], (const float*)d_in[22], wk2h, bk2, CC };
    fold5<<<dim3(CC, 5), 256>>>(pa);

    cudaMemsetAsync(S, 0, BB * CC * CC * sizeof(float));
    cudaMemsetAsync(Z, 0, BB * CC * sizeof(float));

    conv_all<<<dim3(HW / 128 * 3, BB), 256, CHAIN_SM_BYTES>>>(
        wkvh, bkv, wk2h, bk2, wq1h, bq1, wq2h, bq2, source, target, val, key, qr);
    s_bf<<<dim3(NSPLIT, BB), 256, SSM_BYTES>>>(val, key, S, Z);
    out_bf<<<dim3(HW / 256, BB), 256, OSM_BYTES>>>(S, qr, Z, (float*)d_out);
}